// round 8
// baseline (speedup 1.0000x reference)
#include <cuda_runtime.h>
#include <math.h>
#include <stdint.h>

#define NB 32
#define NL 1024
#define NC 512
#define LH 512   // L/2

// ---------------- scratch (device globals; no allocations) ----------------
__device__ float g_res[(size_t)2*NB*NC*NL];     // [2][B][C][L]
__device__ float g_cv [(size_t)2*NB*NC*86];     // conv out interleaved, per branch
__device__ float g_x1 [(size_t)NB*NC*85];       // [B][C][m]
__device__ float g_xf [(size_t)NB*NC*169];      // [B][C][2m-1]
__device__ float g_xi [(size_t)NB*NC*85];
__device__ float g_xr [(size_t)NB*NC*85];
__device__ float g_yln[(size_t)NB*NC*85];
__device__ float g_y2 [(size_t)NB*NC*1032];     // [B][C][m*k]
__device__ float g_br [(size_t)NB*NL*2*NC];     // [B*L][2*C]
__device__ float g_mg [(size_t)NB*NL*NC];
__device__ float g_h1 [(size_t)NB*NL*4*NC];
__device__ float g_h2 [(size_t)NB*NL*NC];
__device__ float g_W2a[(size_t)NC*12*NC];
__device__ float g_W2b[(size_t)NC*24*NC];
__device__ float g_Wm [(size_t)2*NC*NC];
__device__ float g_CM0 [85*169];
__device__ float g_CM20[85*85];
__device__ float g_CM1 [43*85];
__device__ float g_CM21[43*43];
__device__ float g_part[(size_t)12*1024*1024]; // split-K partials workspace

// ---------------- series decomp ----------------
__global__ void decomp_kernel(const float* __restrict__ src, float* __restrict__ res) {
    __shared__ float s[64][33];
    int b = blockIdx.z;
    int c0 = blockIdx.y * 32;
    int l0 = blockIdx.x * 32;
    int tx = threadIdx.x, ty = threadIdx.y;
    for (int r = ty; r < 64; r += 32) {
        int l = l0 - 16 + r;
        l = l < 0 ? 0 : (l > NL - 1 ? NL - 1 : l);
        s[r][tx] = src[((size_t)b*NL + l)*NC + c0 + tx];
    }
    __syncthreads();
    int base = tx + 16;
    float s17 = 0.f;
    #pragma unroll
    for (int j = -8; j <= 8; j++) s17 += s[base + j][ty];
    float s33 = s17;
    #pragma unroll
    for (int j = 9; j <= 16; j++) s33 += s[base - j][ty] + s[base + j][ty];
    float v = s[base][ty];
    size_t o = ((size_t)(b*NC + c0 + ty))*NL + l0 + tx;
    res[o] = v - s17 / 17.0f;
    res[(size_t)NB*NC*NL + o] = v - s33 / 33.0f;
}

// ---------------- fused prep ----------------
__global__ void prep_all(const float* __restrict__ mwt, float* __restrict__ Wm,
                         const float* __restrict__ tw0, float* __restrict__ W2a,
                         const float* __restrict__ tw1, float* __restrict__ W2b,
                         float* __restrict__ CM0, float* __restrict__ CM20,
                         float* __restrict__ CM1, float* __restrict__ CM21) {
    const double TWO_PI = 6.283185307179586476925286766559;
    const int tM = NC*NC*2;
    const int tA = NC*NC*12, tB = NC*NC*24;
    const int c0 = 85*169, c1 = 85*85, c2 = 43*85, c3 = 43*43;
    int total = tM + tA + tB + c0 + c1 + c2 + c3;
    for (int idx = blockIdx.x*blockDim.x + threadIdx.x; idx < total; idx += gridDim.x*blockDim.x) {
        int i = idx;
        if (i < tM) {
            int o = i / (NC*2);
            int rem = i - o*NC*2;
            int c = rem >> 1, n = rem & 1;
            Wm[((size_t)n*NC + c)*NC + o] = mwt[i];
            continue;
        }
        i -= tM;
        if (i < tA) {
            int cin = i / (NC*12);
            int r   = i - cin*(NC*12);
            W2a[(size_t)r*NC + cin] = tw0[i];
            continue;
        }
        i -= tA;
        if (i < tB) {
            int cin = i / (NC*24);
            int r   = i - cin*(NC*24);
            W2b[(size_t)r*NC + cin] = tw1[i];
            continue;
        }
        i -= tB;
        if (i < c0) {
            int t = i / 169, f = i - t*169;
            CM0[i] = (float)cos(TWO_PI * (double)((long long)f*(t + 84)) / 169.0);
            continue;
        }
        i -= c0;
        if (i < c1) {
            int f = i / 85, t = i - f*85;
            CM20[i] = (float)(cos(TWO_PI * (double)((long long)f*t) / 85.0) / 85.0);
            continue;
        }
        i -= c1;
        if (i < c2) {
            int t = i / 85, f = i - t*85;
            CM1[i] = (float)cos(TWO_PI * (double)((long long)f*(t + 42)) / 85.0);
            continue;
        }
        i -= c2;
        {
            int f = i / 43, t = i - f*43;
            CM21[i] = (float)(cos(TWO_PI * (double)((long long)f*t) / 43.0) / 43.0);
        }
    }
}

// ---------------- x1: exp-gated interleave, drop last ----------------
__global__ void x1_kernel(const float* __restrict__ cv, float* __restrict__ x1, int m, int ne2) {
    size_t total = (size_t)NB*NC*m;
    for (size_t idx = (size_t)blockIdx.x*blockDim.x + threadIdx.x; idx < total;
         idx += (size_t)gridDim.x*blockDim.x) {
        int t = (int)(idx % m);
        size_t bc = idx / m;
        const float* c2 = cv + bc*ne2;
        x1[idx] = c2[t ^ 1] * expf(c2[t]);
    }
}

// ---------------- GEMM params ----------------
struct GemmP {
    const float* A; int lda;
    const float* Bp; int ldb; long long sBb;
    float* D; long long sDb; int ldd;
    const float* bias;
    int M, N, K;
    int npos;
    int pad, lhalf, inner;
    int kt, mklen;
    float* part;
};

__device__ __forceinline__ uint32_t f2tf32(float v) {
    uint32_t u;
    asm("cvt.rna.tf32.f32 %0, %1;" : "=r"(u) : "f"(v));
    return u;
}
__device__ __forceinline__ void mma_tf32(float c[4], const uint32_t a[4], const uint32_t b[2]) {
    asm("mma.sync.aligned.m16n8k8.row.col.f32.tf32.tf32.f32 "
        "{%0,%1,%2,%3},{%4,%5,%6,%7},{%8,%9},{%0,%1,%2,%3};"
        : "+f"(c[0]), "+f"(c[1]), "+f"(c[2]), "+f"(c[3])
        : "r"(a[0]), "r"(a[1]), "r"(a[2]), "r"(a[3]), "r"(b[0]), "r"(b[1]));
}

template<int BMODE, int KK>
__device__ __forceinline__ float ldB(const GemmP& p, const float* bbase, int sb, int gk) {
    if (gk >= p.K) return 0.f;
    if (BMODE == 0) return bbase[(long long)gk * p.ldb];
    int cin = gk / KK, t = gk - cin*KK;
    if (BMODE == 1) {
        int s = sb + t;
        return (s >= 0 && s < p.lhalf) ? bbase[(long long)cin*p.inner + 2*s] : 0.f;
    }
    return bbase[(long long)cin*p.inner + t];
}

// tf32 mma.sync GEMM: BM=128, BN=64, BK=32, fragment-major smem, double-buffered.
// BMODE: 0 dense, 1 conv-im2col(even/odd), 2 iso-im2col   (KK: conv kernel size)
// BIASM: 0 none, 1 per-row, 2 per-col(q), 3 bias[row/kt]
// ACT:   0 none, 1 tanh, 2 relu
// SMODE: 0 normal, 1 transconv scatter
// SPLITK>1: raw partials to p.part; epilogue by reduce kernel.
// Requires: M % 128 == 0.
template<int BMODE, int KK, int BIASM, int ACT, int SMODE, int SPLITK>
__global__ void __launch_bounds__(256, 2)
gemm_k(GemmP p) {
    constexpr int BM = 128, BN = 64, BK = 32;
    constexpr int WR = 4;            // warp rows
    constexpr int WC = 2;            // warp cols
    constexpr int WN = BN/WC;        // 32
    constexpr int NF = WN/8;         // 4
    constexpr int AG = BM/32;        // 4
    constexpr int BR = BN/32;        // 2
    constexpr int ASZ = BM*BK, BSZ = BK*BN;
    extern __shared__ float dyn[];
    float* As = dyn;
    float* Bs = dyn + 2*ASZ;

    const int tid = threadIdx.x, lane = tid & 31, warp = tid >> 5;
    const int wr = warp % WR, wc = warp / WR;
    const int m0 = blockIdx.y * BM, n0 = blockIdx.x * BN;

    int kbeg = 0, kend = p.K;
    if (SPLITK > 1) {
        int kc = ((p.K + SPLITK*BK - 1) / (SPLITK*BK)) * BK;
        kbeg = blockIdx.z * kc;
        kend = min(kbeg + kc, p.K);
    }

    // ---- hoisted fill bases ----
    const int am_ = tid >> 3, ak_ = (tid & 7) * 4;
    const float* arow[AG];
    #pragma unroll
    for (int g = 0; g < AG; g++)
        arow[g] = p.A + (long long)(m0 + am_ + 32*g) * p.lda;
    const int bn_ = tid & 31, bk_ = (tid >> 5) * 4;
    const float* bbase_r[BR];
    int sb_r[BR];
    bool nv_r[BR];
    #pragma unroll
    for (int rp = 0; rp < BR; rp++) {
        int gn = n0 + bn_ + 32*rp;
        nv_r[rp] = gn < p.N;
        int g = nv_r[rp] ? gn : 0;
        int b = 0, q = g;
        if (!(BMODE == 0 && p.sBb == 0)) { b = g / p.npos; q = g - b*p.npos; }
        int sb = 0;
        const float* bb;
        if (BMODE == 0) bb = p.Bp + b*p.sBb + q;
        else if (BMODE == 1) { int o = q >> 1, pb = q & 1; sb = o*KK - p.pad; bb = p.Bp + b*p.sBb + pb; }
        else bb = p.Bp + b*p.sBb + q;
        bbase_r[rp] = bb;
        sb_r[rp] = sb;
    }

    // ---- base-only smem store indices ----
    int aidx[AG];
    #pragma unroll
    for (int g = 0; g < AG; g++) {
        int m = am_ + 32*g;
        int wr_ = m >> 5, mi = (m & 31) >> 4, mr = m & 15;
        int kc = ak_ >> 3, kin = ak_ & 7;
        aidx[g] = (((kc*WR + wr_)*2 + mi)*32 + (mr & 7)*4 + (kin & 3))*4
                  + (mr >> 3) + 2*(kin >> 2);
    }
    int bidx[BR];
    #pragma unroll
    for (int rp = 0; rp < BR; rp++) {
        int n = bn_ + 32*rp;
        int kc = bk_ >> 3, kin = bk_ & 7;
        bidx[rp] = ((kc*(BN/8) + (n >> 3))*32 + (n & 7)*4 + (kin & 3))*2 + (kin >> 2);
    }

    float acc[2][NF][4];
    #pragma unroll
    for (int mi = 0; mi < 2; mi++)
        #pragma unroll
        for (int ni = 0; ni < NF; ni++)
            #pragma unroll
            for (int e = 0; e < 4; e++) acc[mi][ni][e] = 0.f;

    float ra[AG][4], rb[BR][4];
    #pragma unroll
    for (int g = 0; g < AG; g++)
        #pragma unroll
        for (int j = 0; j < 4; j++) {
            int gk = kbeg + ak_ + j;
            ra[g][j] = (gk < p.K) ? arow[g][gk] : 0.f;
        }
    #pragma unroll
    for (int rp = 0; rp < BR; rp++)
        #pragma unroll
        for (int j = 0; j < 4; j++)
            rb[rp][j] = nv_r[rp] ? ldB<BMODE, KK>(p, bbase_r[rp], sb_r[rp], kbeg + bk_ + j) : 0.f;
    #pragma unroll
    for (int g = 0; g < AG; g++)
        #pragma unroll
        for (int j = 0; j < 4; j++)
            As[aidx[g] + 4*j] = __uint_as_float(f2tf32(ra[g][j]));
    #pragma unroll
    for (int rp = 0; rp < BR; rp++)
        #pragma unroll
        for (int j = 0; j < 4; j++)
            Bs[bidx[rp] + 2*j] = __uint_as_float(f2tf32(rb[rp][j]));
    __syncthreads();

    int buf = 0;
    for (int k0 = kbeg; k0 < kend; k0 += BK) {
        int kn = k0 + BK;
        bool more = kn < kend;
        if (more) {
            #pragma unroll
            for (int g = 0; g < AG; g++)
                #pragma unroll
                for (int j = 0; j < 4; j++) {
                    int gk = kn + ak_ + j;
                    ra[g][j] = (gk < p.K) ? arow[g][gk] : 0.f;
                }
            #pragma unroll
            for (int rp = 0; rp < BR; rp++)
                #pragma unroll
                for (int j = 0; j < 4; j++)
                    rb[rp][j] = nv_r[rp] ? ldB<BMODE, KK>(p, bbase_r[rp], sb_r[rp], kn + bk_ + j) : 0.f;
        }
        const float* Ac = As + buf*ASZ;
        const float* Bc = Bs + buf*BSZ;
        #pragma unroll
        for (int kc = 0; kc < 4; kc++) {
            uint32_t af[2][4];
            #pragma unroll
            for (int mi = 0; mi < 2; mi++) {
                const float4 av = *(const float4*)&Ac[(((kc*WR + wr)*2 + mi)*32 + lane)*4];
                af[mi][0] = __float_as_uint(av.x);
                af[mi][1] = __float_as_uint(av.y);
                af[mi][2] = __float_as_uint(av.z);
                af[mi][3] = __float_as_uint(av.w);
            }
            uint32_t bf[NF][2];
            #pragma unroll
            for (int ni = 0; ni < NF; ni++) {
                const float2 bv = *(const float2*)&Bc[((kc*(BN/8) + wc*NF + ni)*32 + lane)*2];
                bf[ni][0] = __float_as_uint(bv.x);
                bf[ni][1] = __float_as_uint(bv.y);
            }
            #pragma unroll
            for (int mi = 0; mi < 2; mi++)
                #pragma unroll
                for (int ni = 0; ni < NF; ni++)
                    mma_tf32(acc[mi][ni], af[mi], bf[ni]);
        }
        if (more) {
            float* An = As + (buf^1)*ASZ;
            float* Bn = Bs + (buf^1)*BSZ;
            #pragma unroll
            for (int g = 0; g < AG; g++)
                #pragma unroll
                for (int j = 0; j < 4; j++)
                    An[aidx[g] + 4*j] = __uint_as_float(f2tf32(ra[g][j]));
            #pragma unroll
            for (int rp = 0; rp < BR; rp++)
                #pragma unroll
                for (int j = 0; j < 4; j++)
                    Bn[bidx[rp] + 2*j] = __uint_as_float(f2tf32(rb[rp][j]));
        }
        __syncthreads();
        buf ^= 1;
    }

    // ---- epilogue ----
    if (SPLITK > 1) {
        float* pd = p.part + (size_t)blockIdx.z * ((size_t)p.M * p.N);
        #pragma unroll
        for (int mi = 0; mi < 2; mi++)
            #pragma unroll
            for (int half = 0; half < 2; half++) {
                int row = m0 + wr*32 + mi*16 + (lane >> 2) + half*8;
                #pragma unroll
                for (int ni = 0; ni < NF; ni++)
                    #pragma unroll
                    for (int e = 0; e < 2; e++) {
                        int gn = n0 + wc*WN + ni*8 + (lane & 3)*2 + e;
                        if (gn < p.N)
                            pd[(size_t)row*p.N + gn] = acc[mi][ni][half*2 + e];
                    }
            }
        return;
    }
    #pragma unroll
    for (int mi = 0; mi < 2; mi++) {
        #pragma unroll
        for (int half = 0; half < 2; half++) {
            int row = m0 + wr*32 + mi*16 + (lane >> 2) + half*8;
            float brow = 0.f;
            if (BIASM == 1) brow = p.bias[row];
            else if (BIASM == 3) brow = p.bias[row / p.kt];
            int cout = 0, jj = 0;
            if (SMODE == 1) { cout = row / p.kt; jj = row - cout*p.kt; }
            #pragma unroll
            for (int ni = 0; ni < NF; ni++) {
                #pragma unroll
                for (int e = 0; e < 2; e++) {
                    int gn = n0 + wc*WN + ni*8 + (lane & 3)*2 + e;
                    if (gn >= p.N) continue;
                    int b, q;
                    if (SMODE == 0 && p.sDb == 0) { b = 0; q = gn; }
                    else { b = gn / p.npos; q = gn - b*p.npos; }
                    float v = acc[mi][ni][half*2 + e] + brow;
                    if (BIASM == 2) v += p.bias[q];
                    if (ACT == 1) v = tanhf(v);
                    else if (ACT == 2) v = fmaxf(v, 0.f);
                    long long addr;
                    if (SMODE == 0) addr = b*p.sDb + (long long)row*p.ldd + q;
                    else addr = b*p.sDb + (long long)cout*p.mklen + (long long)q*p.kt + jj;
                    p.D[addr] = v;
                }
            }
        }
    }
}

// ---------------- split-K reduce + bias + tanh + batched store ----------------
__global__ void reduce_ep_k(const float* __restrict__ part, float* __restrict__ D,
                            const float* __restrict__ bias,
                            int S, int M, int N, long long sDb, int ldd, int npos) {
    int idx = blockIdx.x*blockDim.x + threadIdx.x;
    if (idx >= M*N) return;
    int row = idx / N, gn = idx - row*N;
    size_t st = (size_t)M*N;
    float v = 0.f;
    for (int z = 0; z < S; z++) v += part[(size_t)z*st + idx];
    v = tanhf(v + bias[row]);
    int b = gn / npos, q = gn - b*npos;
    D[b*sDb + (long long)row*ldd + q] = v;
}

// ---------------- block reduce + layer norms ----------
__device__ __forceinline__ float blk_sum(float v) {
    __shared__ float sb[8];
    #pragma unroll
    for (int o = 16; o; o >>= 1) v += __shfl_xor_sync(0xffffffffu, v, o);
    if ((threadIdx.x & 31) == 0) sb[threadIdx.x >> 5] = v;
    __syncthreads();
    float t = 0.f;
    #pragma unroll
    for (int i = 0; i < 8; i++) t += sb[i];
    __syncthreads();
    return t;
}

__global__ void ln1_kernel(const float* __restrict__ xr, const float* __restrict__ x1,
                           const float* __restrict__ g, const float* __restrict__ bt,
                           float* __restrict__ out, int m) {
    int row = blockIdx.x;
    int b = row / m, t = row - b*m;
    int tid = threadIdx.x;
    size_t base = (size_t)b*NC*m + t;
    float v0 = xr[base + (size_t)tid*m]       + x1[base + (size_t)tid*m];
    float v1 = xr[base + (size_t)(tid+256)*m] + x1[base + (size_t)(tid+256)*m];
    float mu = blk_sum(v0 + v1) * (1.f/NC);
    float d0 = v0 - mu, d1 = v1 - mu;
    float var = blk_sum(d0*d0 + d1*d1) * (1.f/NC);
    float inv = rsqrtf(var + 1e-5f);
    out[base + (size_t)tid*m]       = d0*inv*g[tid]     + bt[tid];
    out[base + (size_t)(tid+256)*m] = d1*inv*g[tid+256] + bt[tid+256];
}

__global__ void branch_out_kernel(const float* __restrict__ y2, const float* __restrict__ resn,
                                  const float* __restrict__ g, const float* __restrict__ bt,
                                  float* __restrict__ br, int mk, int nbr) {
    int row = blockIdx.x;
    int b = row >> 10, l = row & 1023;
    int li = (l * mk) >> 10;
    int tid = threadIdx.x;
    size_t yb = (size_t)b*NC*mk + li;
    size_t rb = (size_t)b*NC*NL + l;
    float v0 = y2[yb + (size_t)tid*mk]       + resn[rb + (size_t)tid*NL];
    float v1 = y2[yb + (size_t)(tid+256)*mk] + resn[rb + (size_t)(tid+256)*NL];
    float mu = blk_sum(v0 + v1) * (1.f/NC);
    float d0 = v0 - mu, d1 = v1 - mu;
    float var = blk_sum(d0*d0 + d1*d1) * (1.f/NC);
    float inv = rsqrtf(var + 1e-5f);
    float* o = br + (size_t)row*(2*NC) + nbr*NC;
    o[tid]     = d0*inv*g[tid]     + bt[tid];
    o[tid+256] = d1*inv*g[tid+256] + bt[tid+256];
}

__global__ void final_ln_kernel(const float* __restrict__ mg, const float* __restrict__ h2,
                                const float* __restrict__ g, const float* __restrict__ bt,
                                float* __restrict__ out) {
    int row = blockIdx.x;
    int tid = threadIdx.x;
    size_t base = (size_t)row*NC;
    float v0 = mg[base + tid]       + h2[base + tid];
    float v1 = mg[base + tid + 256] + h2[base + tid + 256];
    float mu = blk_sum(v0 + v1) * (1.f/NC);
    float d0 = v0 - mu, d1 = v1 - mu;
    float var = blk_sum(d0*d0 + d1*d1) * (1.f/NC);
    float inv = rsqrtf(var + 1e-5f);
    out[base + tid]       = d0*inv*g[tid]     + bt[tid];
    out[base + tid + 256] = d1*inv*g[tid+256] + bt[tid+256];
}

template<int SPLITK>
static inline dim3 gg(int M, int N) { return dim3((N + 63)/64, M/128, SPLITK); }

template<int BMODE, int KK, int BIASM, int ACT, int SMODE, int SPLITK = 1>
static void launch_gemm(const GemmP& p) {
    constexpr int SMEM = 2*(128*32 + 32*64)*4;   // 49152
    cudaFuncSetAttribute((const void*)gemm_k<BMODE,KK,BIASM,ACT,SMODE,SPLITK>,
                         cudaFuncAttributeMaxDynamicSharedMemorySize, SMEM);
    gemm_k<BMODE,KK,BIASM,ACT,SMODE,SPLITK><<<gg<SPLITK>(p.M, p.N), 256, SMEM>>>(p);
}

extern "C" void kernel_launch(void* const* d_in, const int* in_sizes, int n_in,
                              void* d_out, int out_size) {
    (void)in_sizes; (void)n_in; (void)out_size;
    const float* src   = (const float*)d_in[0];
    const float* cw[2] = {(const float*)d_in[1],  (const float*)d_in[7]};
    const float* cb[2] = {(const float*)d_in[2],  (const float*)d_in[8]};
    const float* iw[2] = {(const float*)d_in[3],  (const float*)d_in[9]};
    const float* ib[2] = {(const float*)d_in[4],  (const float*)d_in[10]};
    const float* tw[2] = {(const float*)d_in[5],  (const float*)d_in[11]};
    const float* tb[2] = {(const float*)d_in[6],  (const float*)d_in[12]};
    const float* mw  = (const float*)d_in[13];
    const float* mb  = (const float*)d_in[14];
    const float* ng  = (const float*)d_in[15];
    const float* nb  = (const float*)d_in[16];
    const float* fw1 = (const float*)d_in[17];
    const float* fb1 = (const float*)d_in[18];
    const float* fw2 = (const float*)d_in[19];
    const float* fb2 = (const float*)d_in[20];
    const float* fng = (const float*)d_in[21];
    const float* fnb = (const float*)d_in[22];
    float* out = (float*)d_out;

    float *p_res,*p_cv,*p_x1,*p_xf,*p_xi,*p_xr,*p_yln,*p_y2,*p_br,*p_mg,*p_h1,*p_h2;
    float *p_W2a,*p_W2b,*p_Wm,*p_CM0,*p_CM20,*p_CM1,*p_CM21,*p_part;
    cudaGetSymbolAddress((void**)&p_res, g_res);
    cudaGetSymbolAddress((void**)&p_cv,  g_cv);
    cudaGetSymbolAddress((void**)&p_x1,  g_x1);
    cudaGetSymbolAddress((void**)&p_xf,  g_xf);
    cudaGetSymbolAddress((void**)&p_xi,  g_xi);
    cudaGetSymbolAddress((void**)&p_xr,  g_xr);
    cudaGetSymbolAddress((void**)&p_yln, g_yln);
    cudaGetSymbolAddress((void**)&p_y2,  g_y2);
    cudaGetSymbolAddress((void**)&p_br,  g_br);
    cudaGetSymbolAddress((void**)&p_mg,  g_mg);
    cudaGetSymbolAddress((void**)&p_h1,  g_h1);
    cudaGetSymbolAddress((void**)&p_h2,  g_h2);
    cudaGetSymbolAddress((void**)&p_W2a, g_W2a);
    cudaGetSymbolAddress((void**)&p_W2b, g_W2b);
    cudaGetSymbolAddress((void**)&p_Wm,  g_Wm);
    cudaGetSymbolAddress((void**)&p_CM0, g_CM0);
    cudaGetSymbolAddress((void**)&p_CM20,g_CM20);
    cudaGetSymbolAddress((void**)&p_CM1, g_CM1);
    cudaGetSymbolAddress((void**)&p_CM21,g_CM21);
    cudaGetSymbolAddress((void**)&p_part,g_part);

    const int Kk[2] = {12, 24}, PD[2] = {6, 12}, NE[2] = {43, 22},
              MM[2] = {85, 43}, N2_[2] = {169, 85}, MKl[2] = {1020, 1032};
    float* CMv[2]  = {p_CM0, p_CM1};
    float* CM2v[2] = {p_CM20, p_CM21};
    float* W2v[2]  = {p_W2a, p_W2b};
    float* cpart[2] = {p_part, p_part + (size_t)6*1024*1024};

    // launches: 0 decomp, 1 prep, 2 conv-b0 gemm, 3 conv-b1 gemm (global 5 -> ncu)
    decomp_kernel<<<dim3(NL/32, NC/32, NB), dim3(32, 32)>>>(src, p_res);
    prep_all<<<2048, 256>>>(mw, p_Wm, tw[0], p_W2a, tw[1], p_W2b,
                            p_CM0, p_CM20, p_CM1, p_CM21);

    for (int n = 0; n < 2; n++) {
        int k = Kk[n], pad = PD[n], ne = NE[n];
        int ne2 = 2*ne;
        GemmP p{};
        p.A = cw[n]; p.lda = NC*k;
        p.Bp = p_res + (size_t)n*NB*NC*NL; p.sBb = (long long)NC*NL;
        p.pad = pad; p.lhalf = LH; p.inner = NL;
        p.part = cpart[n];
        p.bias = cb[n];
        p.M = NC; p.N = NB*ne2; p.K = NC*k; p.npos = ne2;
        if (n == 0) launch_gemm<1,12,1,1,0,4>(p);
        else        launch_gemm<1,24,1,1,0,8>(p);
    }
    for (int n = 0; n < 2; n++) {
        int ne2 = 2*NE[n];
        int Nn = NB*ne2;
        reduce_ep_k<<<(NC*Nn + 255)/256, 256>>>(cpart[n], p_cv + (size_t)n*NB*NC*86, cb[n],
                                                (n == 0) ? 4 : 8, NC, Nn,
                                                (long long)NC*ne2, ne2, ne2);
    }

    for (int n = 0; n < 2; n++) {
        int k = Kk[n], m = MM[n], N2 = N2_[n], mk = MKl[n];
        int ne2 = 2*NE[n];

        x1_kernel<<<1024, 256>>>(p_cv + (size_t)n*NB*NC*86, p_x1, m, ne2);
        { // real-DFT
            GemmP p{};
            p.A = p_x1; p.lda = m;
            p.Bp = CMv[n]; p.ldb = N2; p.sBb = 0;
            p.D = p_xf; p.sDb = 0; p.ldd = N2;
            p.M = NB*NC; p.N = N2; p.K = m; p.npos = N2;
            launch_gemm<0,1,0,0,0>(p);
        }
        { // isometric conv (valid), tanh — split-K
            GemmP p{};
            p.A = iw[n]; p.lda = NC*m;
            p.Bp = p_xf; p.sBb = (long long)NC*N2; p.inner = N2;
            p.part = p_part;
            p.bias = ib[n];
            p.M = NC; p.N = NB*m; p.K = NC*m; p.npos = m;
            if (n == 0) launch_gemm<2,85,1,1,0,8>(p);
            else        launch_gemm<2,43,1,1,0,8>(p);
            reduce_ep_k<<<(NC*NB*m + 255)/256, 256>>>(p_part, p_xi, ib[n],
                                                      8, NC, NB*m,
                                                      (long long)NC*m, m, m);
        }
        { // real-IDFT
            GemmP p{};
            p.A = p_xi; p.lda = m;
            p.Bp = CM2v[n]; p.ldb = m; p.sBb = 0;
            p.D = p_xr; p.sDb = 0; p.ldd = m;
            p.M = NB*NC; p.N = m; p.K = m; p.npos = m;
            launch_gemm<0,1,0,0,0>(p);
        }
        ln1_kernel<<<NB*m, 256>>>(p_xr, p_x1, ng, nb, p_yln, m);
        { // conv-transpose (stride==kernel), tanh, scatter store
            GemmP p{};
            p.A = W2v[n]; p.lda = NC;
            p.Bp = p_yln; p.ldb = m; p.sBb = (long long)NC*m;
            p.D = p_y2; p.sDb = (long long)NC*mk; p.kt = k; p.mklen = mk;
            p.bias = tb[n];
            p.M = NC*k; p.N = NB*m; p.K = NC; p.npos = m;
            launch_gemm<0,1,3,1,1>(p);
        }
        branch_out_kernel<<<NB*NL, 256>>>(p_y2, p_res + (size_t)n*NB*NC*NL, ng, nb, p_br, mk, n);
    }
    { // merge
        GemmP p{};
        p.A = p_br; p.lda = 2*NC;
        p.Bp = p_Wm; p.ldb = NC; p.sBb = 0;
        p.D = p_mg; p.sDb = 0; p.ldd = NC;
        p.bias = mb;
        p.M = NB*NL; p.N = NC; p.K = 2*NC; p.npos = NC;
        launch_gemm<0,1,2,0,0>(p);
    }
    { // FFN layer 1 (relu)
        GemmP p{};
        p.A = p_mg; p.lda = NC;
        p.Bp = fw1; p.ldb = 4*NC; p.sBb = 0;
        p.D = p_h1; p.sDb = 0; p.ldd = 4*NC;
        p.bias = fb1;
        p.M = NB*NL; p.N = 4*NC; p.K = NC; p.npos = 4*NC;
        launch_gemm<0,1,2,2,0>(p);
    }
    { // FFN layer 2
        GemmP p{};
        p.A = p_h1; p.lda = 4*NC;
        p.Bp = fw2; p.ldb = NC; p.sBb = 0;
        p.D = p_h2; p.sDb = 0; p.ldd = NC;
        p.bias = fb2;
        p.M = NB*NL; p.N = NC; p.K = 4*NC; p.npos = NC;
        launch_gemm<0,1,2,0,0>(p);
    }
    final_ln_kernel<<<NB*NL, 256>>>(p_mg, p_h2, fng, fnb, out);
}

// round 9
// speedup vs baseline: 1.0575x; 1.0575x over previous
#include <cuda_runtime.h>
#include <math.h>
#include <stdint.h>

#define NB 32
#define NL 1024
#define NC 512
#define LH 512   // L/2

// ---------------- scratch (device globals; no allocations) ----------------
__device__ float g_res[(size_t)2*NB*NC*NL];     // [2][B][C][L]
__device__ float g_cv [(size_t)2*NB*NC*86];     // conv out interleaved, per branch
__device__ float g_x1 [(size_t)NB*NC*85];       // [B][C][m]
__device__ float g_xf [(size_t)NB*NC*169];      // [B][C][2m-1]
__device__ float g_xi [(size_t)NB*NC*85];
__device__ float g_xr [(size_t)NB*NC*85];
__device__ float g_yln[(size_t)NB*NC*85];
__device__ float g_y2 [(size_t)NB*NC*1032];     // [B][C][m*k]
__device__ float g_br [(size_t)NB*NL*2*NC];     // [B*L][2*C]
__device__ float g_mg [(size_t)NB*NL*NC];
__device__ float g_h1 [(size_t)NB*NL*4*NC];
__device__ float g_h2 [(size_t)NB*NL*NC];
__device__ float g_W2a[(size_t)NC*12*NC];
__device__ float g_W2b[(size_t)NC*24*NC];
__device__ float g_Wm [(size_t)2*NC*NC];
__device__ float g_CM0 [85*169];
__device__ float g_CM20[85*85];
__device__ float g_CM1 [43*85];
__device__ float g_CM21[43*43];
__device__ float g_part[(size_t)12*1024*1024];  // split-K partials workspace
__device__ float g_im [(size_t)18*1024*1024];   // materialized conv im2col

// ---------------- series decomp ----------------
__global__ void decomp_kernel(const float* __restrict__ src, float* __restrict__ res) {
    __shared__ float s[64][33];
    int b = blockIdx.z;
    int c0 = blockIdx.y * 32;
    int l0 = blockIdx.x * 32;
    int tx = threadIdx.x, ty = threadIdx.y;
    for (int r = ty; r < 64; r += 32) {
        int l = l0 - 16 + r;
        l = l < 0 ? 0 : (l > NL - 1 ? NL - 1 : l);
        s[r][tx] = src[((size_t)b*NL + l)*NC + c0 + tx];
    }
    __syncthreads();
    int base = tx + 16;
    float s17 = 0.f;
    #pragma unroll
    for (int j = -8; j <= 8; j++) s17 += s[base + j][ty];
    float s33 = s17;
    #pragma unroll
    for (int j = 9; j <= 16; j++) s33 += s[base - j][ty] + s[base + j][ty];
    float v = s[base][ty];
    size_t o = ((size_t)(b*NC + c0 + ty))*NL + l0 + tx;
    res[o] = v - s17 / 17.0f;
    res[(size_t)NB*NC*NL + o] = v - s33 / 33.0f;
}

// ---------------- fused prep ----------------
__global__ void prep_all(const float* __restrict__ mwt, float* __restrict__ Wm,
                         const float* __restrict__ tw0, float* __restrict__ W2a,
                         const float* __restrict__ tw1, float* __restrict__ W2b,
                         float* __restrict__ CM0, float* __restrict__ CM20,
                         float* __restrict__ CM1, float* __restrict__ CM21) {
    const double TWO_PI = 6.283185307179586476925286766559;
    const int tM = NC*NC*2;
    const int tA = NC*NC*12, tB = NC*NC*24;
    const int c0 = 85*169, c1 = 85*85, c2 = 43*85, c3 = 43*43;
    int total = tM + tA + tB + c0 + c1 + c2 + c3;
    for (int idx = blockIdx.x*blockDim.x + threadIdx.x; idx < total; idx += gridDim.x*blockDim.x) {
        int i = idx;
        if (i < tM) {
            int o = i / (NC*2);
            int rem = i - o*NC*2;
            int c = rem >> 1, n = rem & 1;
            Wm[((size_t)n*NC + c)*NC + o] = mwt[i];
            continue;
        }
        i -= tM;
        if (i < tA) {
            int cin = i / (NC*12);
            int r   = i - cin*(NC*12);
            W2a[(size_t)r*NC + cin] = tw0[i];
            continue;
        }
        i -= tA;
        if (i < tB) {
            int cin = i / (NC*24);
            int r   = i - cin*(NC*24);
            W2b[(size_t)r*NC + cin] = tw1[i];
            continue;
        }
        i -= tB;
        if (i < c0) {
            int t = i / 169, f = i - t*169;
            CM0[i] = (float)cos(TWO_PI * (double)((long long)f*(t + 84)) / 169.0);
            continue;
        }
        i -= c0;
        if (i < c1) {
            int f = i / 85, t = i - f*85;
            CM20[i] = (float)(cos(TWO_PI * (double)((long long)f*t) / 85.0) / 85.0);
            continue;
        }
        i -= c1;
        if (i < c2) {
            int t = i / 85, f = i - t*85;
            CM1[i] = (float)cos(TWO_PI * (double)((long long)f*(t + 42)) / 85.0);
            continue;
        }
        i -= c2;
        {
            int f = i / 43, t = i - f*43;
            CM21[i] = (float)(cos(TWO_PI * (double)((long long)f*t) / 43.0) / 43.0);
        }
    }
}

// ---------------- conv im2col materialization (coalesced writes) ----------------
// out[gk][gn], gk = cin*KK + t, gn = b*NE2 + q, q = 2o+pb; src s = o*KK - pad + t.
template<int KK, int NE2>
__global__ void im2col_conv_k(const float* __restrict__ res, float* __restrict__ out, int pad) {
    int gk = blockIdx.x;
    int cin = gk / KK, t = gk - cin*KK;
    const int N = NB*NE2;
    const float* rbase = res + (size_t)cin*NL;
    float* obase = out + (size_t)gk*N;
    int tb = t - pad;
    for (int gn = threadIdx.x; gn < N; gn += blockDim.x) {
        int b = gn / NE2, q = gn - b*NE2;
        int s = (q >> 1)*KK + tb;
        float v = (s >= 0 && s < LH) ? rbase[(size_t)b*NC*NL + 2*s + (q & 1)] : 0.f;
        obase[gn] = v;
    }
}

// ---------------- x1: exp-gated interleave, drop last ----------------
__global__ void x1_kernel(const float* __restrict__ cv, float* __restrict__ x1, int m, int ne2) {
    size_t total = (size_t)NB*NC*m;
    for (size_t idx = (size_t)blockIdx.x*blockDim.x + threadIdx.x; idx < total;
         idx += (size_t)gridDim.x*blockDim.x) {
        int t = (int)(idx % m);
        size_t bc = idx / m;
        const float* c2 = cv + bc*ne2;
        x1[idx] = c2[t ^ 1] * expf(c2[t]);
    }
}

// ---------------- GEMM params ----------------
struct GemmP {
    const float* A; int lda;
    const float* Bp; int ldb; long long sBb;
    float* D; long long sDb; int ldd;
    const float* bias;
    int M, N, K;
    int npos;
    int pad, lhalf, inner;
    int kt, mklen;
    float* part;
};

__device__ __forceinline__ uint32_t f2tf32(float v) {
    uint32_t u;
    asm("cvt.rna.tf32.f32 %0, %1;" : "=r"(u) : "f"(v));
    return u;
}
__device__ __forceinline__ void mma_tf32(float c[4], const uint32_t a[4], const uint32_t b[2]) {
    asm("mma.sync.aligned.m16n8k8.row.col.f32.tf32.tf32.f32 "
        "{%0,%1,%2,%3},{%4,%5,%6,%7},{%8,%9},{%0,%1,%2,%3};"
        : "+f"(c[0]), "+f"(c[1]), "+f"(c[2]), "+f"(c[3])
        : "r"(a[0]), "r"(a[1]), "r"(a[2]), "r"(a[3]), "r"(b[0]), "r"(b[1]));
}

template<int BMODE, int KK>
__device__ __forceinline__ float ldB(const GemmP& p, const float* bbase, int sb, int gk) {
    if (gk >= p.K) return 0.f;
    if (BMODE == 0) return bbase[(long long)gk * p.ldb];
    int cin = gk / KK, t = gk - cin*KK;
    if (BMODE == 1) {
        int s = sb + t;
        return (s >= 0 && s < p.lhalf) ? bbase[(long long)cin*p.inner + 2*s] : 0.f;
    }
    return bbase[(long long)cin*p.inner + t];
}

// tf32 mma.sync GEMM: BM=128, BN in {64,128}, BK=32, fragment-major smem, double-buffered.
// BMODE: 0 dense, 1 conv-im2col(even/odd), 2 iso-im2col   (KK: conv kernel size)
// BIASM: 0 none, 1 per-row, 2 per-col(q), 3 bias[row/kt]
// ACT:   0 none, 1 tanh, 2 relu
// SMODE: 0 normal, 1 transconv scatter
// SPLITK>1: raw partials to p.part; epilogue by reduce kernel.
// Requires: M % 128 == 0.
template<int BN, int BMODE, int KK, int BIASM, int ACT, int SMODE, int SPLITK>
__global__ void __launch_bounds__(256, (BN == 64) ? 2 : 1)
gemm_k(GemmP p) {
    constexpr int BM = 128, BK = 32;
    constexpr int WR = 4;            // warp rows
    constexpr int WC = 2;            // warp cols
    constexpr int WN = BN/WC;
    constexpr int NF = WN/8;
    constexpr int AG = BM/32;        // 4
    constexpr int BR = BN/32;
    constexpr int ASZ = BM*BK, BSZ = BK*BN;
    extern __shared__ float dyn[];
    float* As = dyn;
    float* Bs = dyn + 2*ASZ;

    const int tid = threadIdx.x, lane = tid & 31, warp = tid >> 5;
    const int wr = warp % WR, wc = warp / WR;
    const int m0 = blockIdx.y * BM, n0 = blockIdx.x * BN;

    int kbeg = 0, kend = p.K;
    if (SPLITK > 1) {
        int kc = ((p.K + SPLITK*BK - 1) / (SPLITK*BK)) * BK;
        kbeg = blockIdx.z * kc;
        kend = min(kbeg + kc, p.K);
    }

    // ---- hoisted fill bases ----
    const int am_ = tid >> 3, ak_ = (tid & 7) * 4;
    const float* arow[AG];
    #pragma unroll
    for (int g = 0; g < AG; g++)
        arow[g] = p.A + (long long)(m0 + am_ + 32*g) * p.lda;
    const int bn_ = tid & 31, bk_ = (tid >> 5) * 4;
    const float* bbase_r[BR];
    int sb_r[BR];
    bool nv_r[BR];
    #pragma unroll
    for (int rp = 0; rp < BR; rp++) {
        int gn = n0 + bn_ + 32*rp;
        nv_r[rp] = gn < p.N;
        int g = nv_r[rp] ? gn : 0;
        int b = 0, q = g;
        if (!(BMODE == 0 && p.sBb == 0)) { b = g / p.npos; q = g - b*p.npos; }
        int sb = 0;
        const float* bb;
        if (BMODE == 0) bb = p.Bp + b*p.sBb + q;
        else if (BMODE == 1) { int o = q >> 1, pb = q & 1; sb = o*KK - p.pad; bb = p.Bp + b*p.sBb + pb; }
        else bb = p.Bp + b*p.sBb + q;
        bbase_r[rp] = bb;
        sb_r[rp] = sb;
    }

    // ---- base-only smem store indices ----
    int aidx[AG];
    #pragma unroll
    for (int g = 0; g < AG; g++) {
        int m = am_ + 32*g;
        int wr_ = m >> 5, mi = (m & 31) >> 4, mr = m & 15;
        int kc = ak_ >> 3, kin = ak_ & 7;
        aidx[g] = (((kc*WR + wr_)*2 + mi)*32 + (mr & 7)*4 + (kin & 3))*4
                  + (mr >> 3) + 2*(kin >> 2);
    }
    int bidx[BR];
    #pragma unroll
    for (int rp = 0; rp < BR; rp++) {
        int n = bn_ + 32*rp;
        int kc = bk_ >> 3, kin = bk_ & 7;
        bidx[rp] = ((kc*(BN/8) + (n >> 3))*32 + (n & 7)*4 + (kin & 3))*2 + (kin >> 2);
    }

    float acc[2][NF][4];
    #pragma unroll
    for (int mi = 0; mi < 2; mi++)
        #pragma unroll
        for (int ni = 0; ni < NF; ni++)
            #pragma unroll
            for (int e = 0; e < 4; e++) acc[mi][ni][e] = 0.f;

    float ra[AG][4], rb[BR][4];
    #pragma unroll
    for (int g = 0; g < AG; g++)
        #pragma unroll
        for (int j = 0; j < 4; j++) {
            int gk = kbeg + ak_ + j;
            ra[g][j] = (gk < p.K) ? arow[g][gk] : 0.f;
        }
    #pragma unroll
    for (int rp = 0; rp < BR; rp++)
        #pragma unroll
        for (int j = 0; j < 4; j++)
            rb[rp][j] = nv_r[rp] ? ldB<BMODE, KK>(p, bbase_r[rp], sb_r[rp], kbeg + bk_ + j) : 0.f;
    #pragma unroll
    for (int g = 0; g < AG; g++)
        #pragma unroll
        for (int j = 0; j < 4; j++)
            As[aidx[g] + 4*j] = __uint_as_float(f2tf32(ra[g][j]));
    #pragma unroll
    for (int rp = 0; rp < BR; rp++)
        #pragma unroll
        for (int j = 0; j < 4; j++)
            Bs[bidx[rp] + 2*j] = __uint_as_float(f2tf32(rb[rp][j]));
    __syncthreads();

    int buf = 0;
    for (int k0 = kbeg; k0 < kend; k0 += BK) {
        int kn = k0 + BK;
        bool more = kn < kend;
        if (more) {
            #pragma unroll
            for (int g = 0; g < AG; g++)
                #pragma unroll
                for (int j = 0; j < 4; j++) {
                    int gk = kn + ak_ + j;
                    ra[g][j] = (gk < p.K) ? arow[g][gk] : 0.f;
                }
            #pragma unroll
            for (int rp = 0; rp < BR; rp++)
                #pragma unroll
                for (int j = 0; j < 4; j++)
                    rb[rp][j] = nv_r[rp] ? ldB<BMODE, KK>(p, bbase_r[rp], sb_r[rp], kn + bk_ + j) : 0.f;
        }
        const float* Ac = As + buf*ASZ;
        const float* Bc = Bs + buf*BSZ;
        #pragma unroll
        for (int kc = 0; kc < 4; kc++) {
            uint32_t af[2][4];
            #pragma unroll
            for (int mi = 0; mi < 2; mi++) {
                const float4 av = *(const float4*)&Ac[(((kc*WR + wr)*2 + mi)*32 + lane)*4];
                af[mi][0] = __float_as_uint(av.x);
                af[mi][1] = __float_as_uint(av.y);
                af[mi][2] = __float_as_uint(av.z);
                af[mi][3] = __float_as_uint(av.w);
            }
            uint32_t bf[NF][2];
            #pragma unroll
            for (int ni = 0; ni < NF; ni++) {
                const float2 bv = *(const float2*)&Bc[((kc*(BN/8) + wc*NF + ni)*32 + lane)*2];
                bf[ni][0] = __float_as_uint(bv.x);
                bf[ni][1] = __float_as_uint(bv.y);
            }
            #pragma unroll
            for (int mi = 0; mi < 2; mi++)
                #pragma unroll
                for (int ni = 0; ni < NF; ni++)
                    mma_tf32(acc[mi][ni], af[mi], bf[ni]);
        }
        if (more) {
            float* An = As + (buf^1)*ASZ;
            float* Bn = Bs + (buf^1)*BSZ;
            #pragma unroll
            for (int g = 0; g < AG; g++)
                #pragma unroll
                for (int j = 0; j < 4; j++)
                    An[aidx[g] + 4*j] = __uint_as_float(f2tf32(ra[g][j]));
            #pragma unroll
            for (int rp = 0; rp < BR; rp++)
                #pragma unroll
                for (int j = 0; j < 4; j++)
                    Bn[bidx[rp] + 2*j] = __uint_as_float(f2tf32(rb[rp][j]));
        }
        __syncthreads();
        buf ^= 1;
    }

    // ---- epilogue ----
    if (SPLITK > 1) {
        float* pd = p.part + (size_t)blockIdx.z * ((size_t)p.M * p.N);
        #pragma unroll
        for (int mi = 0; mi < 2; mi++)
            #pragma unroll
            for (int half = 0; half < 2; half++) {
                int row = m0 + wr*32 + mi*16 + (lane >> 2) + half*8;
                #pragma unroll
                for (int ni = 0; ni < NF; ni++)
                    #pragma unroll
                    for (int e = 0; e < 2; e++) {
                        int gn = n0 + wc*WN + ni*8 + (lane & 3)*2 + e;
                        if (gn < p.N)
                            pd[(size_t)row*p.N + gn] = acc[mi][ni][half*2 + e];
                    }
            }
        return;
    }
    #pragma unroll
    for (int mi = 0; mi < 2; mi++) {
        #pragma unroll
        for (int half = 0; half < 2; half++) {
            int row = m0 + wr*32 + mi*16 + (lane >> 2) + half*8;
            float brow = 0.f;
            if (BIASM == 1) brow = p.bias[row];
            else if (BIASM == 3) brow = p.bias[row / p.kt];
            int cout = 0, jj = 0;
            if (SMODE == 1) { cout = row / p.kt; jj = row - cout*p.kt; }
            #pragma unroll
            for (int ni = 0; ni < NF; ni++) {
                #pragma unroll
                for (int e = 0; e < 2; e++) {
                    int gn = n0 + wc*WN + ni*8 + (lane & 3)*2 + e;
                    if (gn >= p.N) continue;
                    int b, q;
                    if (SMODE == 0 && p.sDb == 0) { b = 0; q = gn; }
                    else { b = gn / p.npos; q = gn - b*p.npos; }
                    float v = acc[mi][ni][half*2 + e] + brow;
                    if (BIASM == 2) v += p.bias[q];
                    if (ACT == 1) v = tanhf(v);
                    else if (ACT == 2) v = fmaxf(v, 0.f);
                    long long addr;
                    if (SMODE == 0) addr = b*p.sDb + (long long)row*p.ldd + q;
                    else addr = b*p.sDb + (long long)cout*p.mklen + (long long)q*p.kt + jj;
                    p.D[addr] = v;
                }
            }
        }
    }
}

// ---------------- split-K reduce + bias + tanh + batched store ----------------
__global__ void reduce_ep_k(const float* __restrict__ part, float* __restrict__ D,
                            const float* __restrict__ bias,
                            int S, int M, int N, long long sDb, int ldd, int npos) {
    int idx = blockIdx.x*blockDim.x + threadIdx.x;
    if (idx >= M*N) return;
    int row = idx / N, gn = idx - row*N;
    size_t st = (size_t)M*N;
    float v = 0.f;
    for (int z = 0; z < S; z++) v += part[(size_t)z*st + idx];
    v = tanhf(v + bias[row]);
    int b = gn / npos, q = gn - b*npos;
    D[b*sDb + (long long)row*ldd + q] = v;
}

// ---------------- block reduce + layer norms ----------
__device__ __forceinline__ float blk_sum(float v) {
    __shared__ float sb[8];
    #pragma unroll
    for (int o = 16; o; o >>= 1) v += __shfl_xor_sync(0xffffffffu, v, o);
    if ((threadIdx.x & 31) == 0) sb[threadIdx.x >> 5] = v;
    __syncthreads();
    float t = 0.f;
    #pragma unroll
    for (int i = 0; i < 8; i++) t += sb[i];
    __syncthreads();
    return t;
}

__global__ void ln1_kernel(const float* __restrict__ xr, const float* __restrict__ x1,
                           const float* __restrict__ g, const float* __restrict__ bt,
                           float* __restrict__ out, int m) {
    int row = blockIdx.x;
    int b = row / m, t = row - b*m;
    int tid = threadIdx.x;
    size_t base = (size_t)b*NC*m + t;
    float v0 = xr[base + (size_t)tid*m]       + x1[base + (size_t)tid*m];
    float v1 = xr[base + (size_t)(tid+256)*m] + x1[base + (size_t)(tid+256)*m];
    float mu = blk_sum(v0 + v1) * (1.f/NC);
    float d0 = v0 - mu, d1 = v1 - mu;
    float var = blk_sum(d0*d0 + d1*d1) * (1.f/NC);
    float inv = rsqrtf(var + 1e-5f);
    out[base + (size_t)tid*m]       = d0*inv*g[tid]     + bt[tid];
    out[base + (size_t)(tid+256)*m] = d1*inv*g[tid+256] + bt[tid+256];
}

__global__ void branch_out_kernel(const float* __restrict__ y2, const float* __restrict__ resn,
                                  const float* __restrict__ g, const float* __restrict__ bt,
                                  float* __restrict__ br, int mk, int nbr) {
    int row = blockIdx.x;
    int b = row >> 10, l = row & 1023;
    int li = (l * mk) >> 10;
    int tid = threadIdx.x;
    size_t yb = (size_t)b*NC*mk + li;
    size_t rb = (size_t)b*NC*NL + l;
    float v0 = y2[yb + (size_t)tid*mk]       + resn[rb + (size_t)tid*NL];
    float v1 = y2[yb + (size_t)(tid+256)*mk] + resn[rb + (size_t)(tid+256)*NL];
    float mu = blk_sum(v0 + v1) * (1.f/NC);
    float d0 = v0 - mu, d1 = v1 - mu;
    float var = blk_sum(d0*d0 + d1*d1) * (1.f/NC);
    float inv = rsqrtf(var + 1e-5f);
    float* o = br + (size_t)row*(2*NC) + nbr*NC;
    o[tid]     = d0*inv*g[tid]     + bt[tid];
    o[tid+256] = d1*inv*g[tid+256] + bt[tid+256];
}

__global__ void final_ln_kernel(const float* __restrict__ mg, const float* __restrict__ h2,
                                const float* __restrict__ g, const float* __restrict__ bt,
                                float* __restrict__ out) {
    int row = blockIdx.x;
    int tid = threadIdx.x;
    size_t base = (size_t)row*NC;
    float v0 = mg[base + tid]       + h2[base + tid];
    float v1 = mg[base + tid + 256] + h2[base + tid + 256];
    float mu = blk_sum(v0 + v1) * (1.f/NC);
    float d0 = v0 - mu, d1 = v1 - mu;
    float var = blk_sum(d0*d0 + d1*d1) * (1.f/NC);
    float inv = rsqrtf(var + 1e-5f);
    out[base + tid]       = d0*inv*g[tid]     + bt[tid];
    out[base + tid + 256] = d1*inv*g[tid+256] + bt[tid+256];
}

template<int BN, int SPLITK>
static inline dim3 gg(int M, int N) { return dim3((N + BN - 1)/BN, M/128, SPLITK); }

template<int BN, int BMODE, int KK, int BIASM, int ACT, int SMODE, int SPLITK = 1>
static void launch_gemm(const GemmP& p) {
    constexpr int SMEM = 2*(128*32 + 32*BN)*4;
    cudaFuncSetAttribute((const void*)gemm_k<BN,BMODE,KK,BIASM,ACT,SMODE,SPLITK>,
                         cudaFuncAttributeMaxDynamicSharedMemorySize, SMEM);
    gemm_k<BN,BMODE,KK,BIASM,ACT,SMODE,SPLITK><<<gg<BN,SPLITK>(p.M, p.N), 256, SMEM>>>(p);
}

extern "C" void kernel_launch(void* const* d_in, const int* in_sizes, int n_in,
                              void* d_out, int out_size) {
    (void)in_sizes; (void)n_in; (void)out_size;
    const float* src   = (const float*)d_in[0];
    const float* cw[2] = {(const float*)d_in[1],  (const float*)d_in[7]};
    const float* cb[2] = {(const float*)d_in[2],  (const float*)d_in[8]};
    const float* iw[2] = {(const float*)d_in[3],  (const float*)d_in[9]};
    const float* ib[2] = {(const float*)d_in[4],  (const float*)d_in[10]};
    const float* tw[2] = {(const float*)d_in[5],  (const float*)d_in[11]};
    const float* tb[2] = {(const float*)d_in[6],  (const float*)d_in[12]};
    const float* mw  = (const float*)d_in[13];
    const float* mb  = (const float*)d_in[14];
    const float* ng  = (const float*)d_in[15];
    const float* nb  = (const float*)d_in[16];
    const float* fw1 = (const float*)d_in[17];
    const float* fb1 = (const float*)d_in[18];
    const float* fw2 = (const float*)d_in[19];
    const float* fb2 = (const float*)d_in[20];
    const float* fng = (const float*)d_in[21];
    const float* fnb = (const float*)d_in[22];
    float* out = (float*)d_out;

    float *p_res,*p_cv,*p_x1,*p_xf,*p_xi,*p_xr,*p_yln,*p_y2,*p_br,*p_mg,*p_h1,*p_h2;
    float *p_W2a,*p_W2b,*p_Wm,*p_CM0,*p_CM20,*p_CM1,*p_CM21,*p_part,*p_im;
    cudaGetSymbolAddress((void**)&p_res, g_res);
    cudaGetSymbolAddress((void**)&p_cv,  g_cv);
    cudaGetSymbolAddress((void**)&p_x1,  g_x1);
    cudaGetSymbolAddress((void**)&p_xf,  g_xf);
    cudaGetSymbolAddress((void**)&p_xi,  g_xi);
    cudaGetSymbolAddress((void**)&p_xr,  g_xr);
    cudaGetSymbolAddress((void**)&p_yln, g_yln);
    cudaGetSymbolAddress((void**)&p_y2,  g_y2);
    cudaGetSymbolAddress((void**)&p_br,  g_br);
    cudaGetSymbolAddress((void**)&p_mg,  g_mg);
    cudaGetSymbolAddress((void**)&p_h1,  g_h1);
    cudaGetSymbolAddress((void**)&p_h2,  g_h2);
    cudaGetSymbolAddress((void**)&p_W2a, g_W2a);
    cudaGetSymbolAddress((void**)&p_W2b, g_W2b);
    cudaGetSymbolAddress((void**)&p_Wm,  g_Wm);
    cudaGetSymbolAddress((void**)&p_CM0, g_CM0);
    cudaGetSymbolAddress((void**)&p_CM20,g_CM20);
    cudaGetSymbolAddress((void**)&p_CM1, g_CM1);
    cudaGetSymbolAddress((void**)&p_CM21,g_CM21);
    cudaGetSymbolAddress((void**)&p_part,g_part);
    cudaGetSymbolAddress((void**)&p_im,  g_im);

    const int Kk[2] = {12, 24}, NE[2] = {43, 22},
              MM[2] = {85, 43}, N2_[2] = {169, 85}, MKl[2] = {1020, 1032};
    float* CMv[2]  = {p_CM0, p_CM1};
    float* CM2v[2] = {p_CM20, p_CM21};
    float* W2v[2]  = {p_W2a, p_W2b};
    float* cpart[2] = {p_part, p_part + (size_t)6*1024*1024};

    decomp_kernel<<<dim3(NL/32, NC/32, NB), dim3(32, 32)>>>(src, p_res);
    prep_all<<<2048, 256>>>(mw, p_Wm, tw[0], p_W2a, tw[1], p_W2b,
                            p_CM0, p_CM20, p_CM1, p_CM21);

    // conv via materialized im2col + dense split-K GEMM
    for (int n = 0; n < 2; n++) {
        int k = Kk[n], ne2 = 2*NE[n];
        int Nn = NB*ne2;
        if (n == 0) im2col_conv_k<12,86><<<NC*12, 256>>>(p_res, p_im, 6);
        else        im2col_conv_k<24,44><<<NC*24, 256>>>(p_res + (size_t)NB*NC*NL, p_im, 12);
        GemmP p{};
        p.A = cw[n]; p.lda = NC*k;
        p.Bp = p_im; p.ldb = Nn; p.sBb = 0;
        p.part = cpart[n];
        p.bias = cb[n];
        p.M = NC; p.N = Nn; p.K = NC*k; p.npos = ne2;
        if (n == 0) launch_gemm<64,0,1,1,1,0,4>(p);
        else        launch_gemm<64,0,1,1,1,0,8>(p);
        reduce_ep_k<<<(NC*Nn + 255)/256, 256>>>(cpart[n], p_cv + (size_t)n*NB*NC*86, cb[n],
                                                (n == 0) ? 4 : 8, NC, Nn,
                                                (long long)NC*ne2, ne2, ne2);
    }

    for (int n = 0; n < 2; n++) {
        int k = Kk[n], m = MM[n], N2 = N2_[n], mk = MKl[n];
        int ne2 = 2*NE[n];

        x1_kernel<<<1024, 256>>>(p_cv + (size_t)n*NB*NC*86, p_x1, m, ne2);
        { // real-DFT
            GemmP p{};
            p.A = p_x1; p.lda = m;
            p.Bp = CMv[n]; p.ldb = N2; p.sBb = 0;
            p.D = p_xf; p.sDb = 0; p.ldd = N2;
            p.M = NB*NC; p.N = N2; p.K = m; p.npos = N2;
            launch_gemm<64,0,1,0,0,0>(p);
        }
        { // isometric conv (valid), tanh — split-K
            GemmP p{};
            p.A = iw[n]; p.lda = NC*m;
            p.Bp = p_xf; p.sBb = (long long)NC*N2; p.inner = N2;
            p.part = p_part;
            p.bias = ib[n];
            p.M = NC; p.N = NB*m; p.K = NC*m; p.npos = m;
            if (n == 0) launch_gemm<64,2,85,1,1,0,8>(p);
            else        launch_gemm<64,2,43,1,1,0,8>(p);
            reduce_ep_k<<<(NC*NB*m + 255)/256, 256>>>(p_part, p_xi, ib[n],
                                                      8, NC, NB*m,
                                                      (long long)NC*m, m, m);
        }
        { // real-IDFT
            GemmP p{};
            p.A = p_xi; p.lda = m;
            p.Bp = CM2v[n]; p.ldb = m; p.sBb = 0;
            p.D = p_xr; p.sDb = 0; p.ldd = m;
            p.M = NB*NC; p.N = m; p.K = m; p.npos = m;
            launch_gemm<64,0,1,0,0,0>(p);
        }
        ln1_kernel<<<NB*m, 256>>>(p_xr, p_x1, ng, nb, p_yln, m);
        { // conv-transpose (stride==kernel), tanh, scatter store
            GemmP p{};
            p.A = W2v[n]; p.lda = NC;
            p.Bp = p_yln; p.ldb = m; p.sBb = (long long)NC*m;
            p.D = p_y2; p.sDb = (long long)NC*mk; p.kt = k; p.mklen = mk;
            p.bias = tb[n];
            p.M = NC*k; p.N = NB*m; p.K = NC; p.npos = m;
            launch_gemm<128,0,1,3,1,1>(p);
        }
        branch_out_kernel<<<NB*NL, 256>>>(p_y2, p_res + (size_t)n*NB*NC*NL, ng, nb, p_br, mk, n);
    }
    { // merge
        GemmP p{};
        p.A = p_br; p.lda = 2*NC;
        p.Bp = p_Wm; p.ldb = NC; p.sBb = 0;
        p.D = p_mg; p.sDb = 0; p.ldd = NC;
        p.bias = mb;
        p.M = NB*NL; p.N = NC; p.K = 2*NC; p.npos = NC;
        launch_gemm<128,0,1,2,0,0>(p);
    }
    { // FFN layer 1 (relu)
        GemmP p{};
        p.A = p_mg; p.lda = NC;
        p.Bp = fw1; p.ldb = 4*NC; p.sBb = 0;
        p.D = p_h1; p.sDb = 0; p.ldd = 4*NC;
        p.bias = fb1;
        p.M = NB*NL; p.N = 4*NC; p.K = NC; p.npos = 4*NC;
        launch_gemm<128,0,1,2,2,0>(p);
    }
    { // FFN layer 2
        GemmP p{};
        p.A = p_h1; p.lda = 4*NC;
        p.Bp = fw2; p.ldb = NC; p.sBb = 0;
        p.D = p_h2; p.sDb = 0; p.ldd = NC;
        p.bias = fb2;
        p.M = NB*NL; p.N = NC; p.K = 4*NC; p.npos = NC;
        launch_gemm<128,0,1,2,0,0>(p);
    }
    final_ln_kernel<<<NB*NL, 256>>>(p_mg, p_h2, fng, fnb, out);
}

// round 10
// speedup vs baseline: 1.1687x; 1.1051x over previous
#include <cuda_runtime.h>
#include <math.h>
#include <stdint.h>

#define NB 32
#define NL 1024
#define NC 512
#define LH 512   // L/2

// ---------------- scratch (device globals; no allocations) ----------------
__device__ float g_res[(size_t)2*NB*NC*NL];     // [2][B][C][L]
__device__ float g_cv [(size_t)2*NB*NC*86];     // conv out interleaved, per branch
__device__ float g_x1 [(size_t)NB*NC*85];       // [B][C][m]
__device__ float g_xf [(size_t)NB*NC*169];      // [B][C][2m-1]
__device__ float g_xi [(size_t)NB*NC*85];
__device__ float g_xr [(size_t)NB*NC*85];
__device__ float g_yln[(size_t)NB*NC*85];
__device__ float g_y2 [(size_t)NB*NC*1032];     // [B][C][m*k]
__device__ float g_br [(size_t)NB*NL*2*NC];     // [B*L][2*C]
__device__ float g_mg [(size_t)NB*NL*NC];
__device__ float g_h1 [(size_t)NB*NL*4*NC];
__device__ float g_h2 [(size_t)NB*NL*NC];
__device__ float g_W2a[(size_t)NC*12*NC];
__device__ float g_W2b[(size_t)NC*24*NC];
__device__ float g_Wm [(size_t)2*NC*NC];
__device__ float g_CM0 [85*169];
__device__ float g_CM20[85*85];
__device__ float g_CM1 [43*85];
__device__ float g_CM21[43*43];
__device__ float g_part[(size_t)12*1024*1024];  // split-K partials workspace
__device__ float g_im [(size_t)18*1024*1024];   // materialized conv im2col

// ---------------- series decomp ----------------
__global__ void decomp_kernel(const float* __restrict__ src, float* __restrict__ res) {
    __shared__ float s[64][33];
    int b = blockIdx.z;
    int c0 = blockIdx.y * 32;
    int l0 = blockIdx.x * 32;
    int tx = threadIdx.x, ty = threadIdx.y;
    for (int r = ty; r < 64; r += 32) {
        int l = l0 - 16 + r;
        l = l < 0 ? 0 : (l > NL - 1 ? NL - 1 : l);
        s[r][tx] = src[((size_t)b*NL + l)*NC + c0 + tx];
    }
    __syncthreads();
    int base = tx + 16;
    float s17 = 0.f;
    #pragma unroll
    for (int j = -8; j <= 8; j++) s17 += s[base + j][ty];
    float s33 = s17;
    #pragma unroll
    for (int j = 9; j <= 16; j++) s33 += s[base - j][ty] + s[base + j][ty];
    float v = s[base][ty];
    size_t o = ((size_t)(b*NC + c0 + ty))*NL + l0 + tx;
    res[o] = v - s17 / 17.0f;
    res[(size_t)NB*NC*NL + o] = v - s33 / 33.0f;
}

// ---------------- fused prep ----------------
__global__ void prep_all(const float* __restrict__ mwt, float* __restrict__ Wm,
                         const float* __restrict__ tw0, float* __restrict__ W2a,
                         const float* __restrict__ tw1, float* __restrict__ W2b,
                         float* __restrict__ CM0, float* __restrict__ CM20,
                         float* __restrict__ CM1, float* __restrict__ CM21) {
    const double TWO_PI = 6.283185307179586476925286766559;
    const int tM = NC*NC*2;
    const int tA = NC*NC*12, tB = NC*NC*24;
    const int c0 = 85*169, c1 = 85*85, c2 = 43*85, c3 = 43*43;
    int total = tM + tA + tB + c0 + c1 + c2 + c3;
    for (int idx = blockIdx.x*blockDim.x + threadIdx.x; idx < total; idx += gridDim.x*blockDim.x) {
        int i = idx;
        if (i < tM) {
            int o = i / (NC*2);
            int rem = i - o*NC*2;
            int c = rem >> 1, n = rem & 1;
            Wm[((size_t)n*NC + c)*NC + o] = mwt[i];
            continue;
        }
        i -= tM;
        if (i < tA) {
            int cin = i / (NC*12);
            int r   = i - cin*(NC*12);
            W2a[(size_t)r*NC + cin] = tw0[i];
            continue;
        }
        i -= tA;
        if (i < tB) {
            int cin = i / (NC*24);
            int r   = i - cin*(NC*24);
            W2b[(size_t)r*NC + cin] = tw1[i];
            continue;
        }
        i -= tB;
        if (i < c0) {
            int t = i / 169, f = i - t*169;
            CM0[i] = (float)cos(TWO_PI * (double)((long long)f*(t + 84)) / 169.0);
            continue;
        }
        i -= c0;
        if (i < c1) {
            int f = i / 85, t = i - f*85;
            CM20[i] = (float)(cos(TWO_PI * (double)((long long)f*t) / 85.0) / 85.0);
            continue;
        }
        i -= c1;
        if (i < c2) {
            int t = i / 85, f = i - t*85;
            CM1[i] = (float)cos(TWO_PI * (double)((long long)f*(t + 42)) / 85.0);
            continue;
        }
        i -= c2;
        {
            int f = i / 43, t = i - f*43;
            CM21[i] = (float)(cos(TWO_PI * (double)((long long)f*t) / 43.0) / 43.0);
        }
    }
}

// ---------------- conv im2col materialization (coalesced writes) ----------------
template<int KK, int NE2>
__global__ void im2col_conv_k(const float* __restrict__ res, float* __restrict__ out, int pad) {
    int gk = blockIdx.x;
    int cin = gk / KK, t = gk - cin*KK;
    const int N = NB*NE2;
    const float* rbase = res + (size_t)cin*NL;
    float* obase = out + (size_t)gk*N;
    int tb = t - pad;
    for (int gn = threadIdx.x; gn < N; gn += blockDim.x) {
        int b = gn / NE2, q = gn - b*NE2;
        int s = (q >> 1)*KK + tb;
        float v = (s >= 0 && s < LH) ? rbase[(size_t)b*NC*NL + 2*s + (q & 1)] : 0.f;
        obase[gn] = v;
    }
}

// ---------------- x1: exp-gated interleave, drop last ----------------
__global__ void x1_kernel(const float* __restrict__ cv, float* __restrict__ x1, int m, int ne2) {
    size_t total = (size_t)NB*NC*m;
    for (size_t idx = (size_t)blockIdx.x*blockDim.x + threadIdx.x; idx < total;
         idx += (size_t)gridDim.x*blockDim.x) {
        int t = (int)(idx % m);
        size_t bc = idx / m;
        const float* c2 = cv + bc*ne2;
        x1[idx] = c2[t ^ 1] * expf(c2[t]);
    }
}

// ---------------- GEMM params ----------------
struct GemmP {
    const float* A; int lda;
    const float* Bp; int ldb; long long sBb;
    float* D; long long sDb; int ldd;
    const float* bias;
    int M, N, K;
    int npos;
    int pad, lhalf, inner;
    int kt, mklen;
    float* part;
};

__device__ __forceinline__ uint32_t f2tf32(float v) {
    uint32_t u;
    asm("cvt.rna.tf32.f32 %0, %1;" : "=r"(u) : "f"(v));
    return u;
}
__device__ __forceinline__ void mma_tf32(float c[4], const uint32_t a[4], const uint32_t b[2]) {
    asm("mma.sync.aligned.m16n8k8.row.col.f32.tf32.tf32.f32 "
        "{%0,%1,%2,%3},{%4,%5,%6,%7},{%8,%9},{%0,%1,%2,%3};"
        : "+f"(c[0]), "+f"(c[1]), "+f"(c[2]), "+f"(c[3])
        : "r"(a[0]), "r"(a[1]), "r"(a[2]), "r"(a[3]), "r"(b[0]), "r"(b[1]));
}

template<int BMODE, int KK>
__device__ __forceinline__ float ldB(const GemmP& p, const float* bbase, int sb, int gk) {
    if (gk >= p.K) return 0.f;
    if (BMODE == 0) return bbase[(long long)gk * p.ldb];
    int cin = gk / KK, t = gk - cin*KK;
    if (BMODE == 1) {
        int s = sb + t;
        return (s >= 0 && s < p.lhalf) ? bbase[(long long)cin*p.inner + 2*s] : 0.f;
    }
    return bbase[(long long)cin*p.inner + t];
}

// tf32 mma.sync GEMM: BM=128, BN in {64,128}, BK=32, fragment-major smem with
// XOR bank-swizzled A layout (kills fill STS conflicts), double-buffered.
// KALIGN=1: K multiple of 32 and A rows 16B-aligned -> unguarded float4 A fills.
// BMODE: 0 dense, 2 iso-im2col   (KK: conv kernel size)
// BIASM: 0 none, 1 per-row, 2 per-col(q), 3 bias[row/kt]
// ACT:   0 none, 1 tanh, 2 relu
// SMODE: 0 normal, 1 transconv scatter
// SPLITK>1: raw partials to p.part; epilogue by reduce kernel.
// Requires: M % 128 == 0.
template<int BN, int BMODE, int KK, int KALIGN, int BIASM, int ACT, int SMODE, int SPLITK>
__global__ void __launch_bounds__(256, (BN == 64) ? 2 : 1)
gemm_k(GemmP p) {
    constexpr int BM = 128, BK = 32;
    constexpr int WR = 4;            // warp rows
    constexpr int WC = 2;            // warp cols
    constexpr int WN = BN/WC;
    constexpr int NF = WN/8;
    constexpr int AG = BM/32;        // 4
    constexpr int BR = BN/32;
    constexpr int ASZ = BM*BK, BSZ = BK*BN;
    extern __shared__ float dyn[];
    float* As = dyn;
    float* Bs = dyn + 2*ASZ;

    const int tid = threadIdx.x, lane = tid & 31, warp = tid >> 5;
    const int wr = warp % WR, wc = warp / WR;
    const int m0 = blockIdx.y * BM, n0 = blockIdx.x * BN;

    int kbeg = 0, kend = p.K;
    if (SPLITK > 1) {
        int kc = ((p.K + SPLITK*BK - 1) / (SPLITK*BK)) * BK;
        kbeg = blockIdx.z * kc;
        kend = min(kbeg + kc, p.K);
    }

    // ---- hoisted fill bases ----
    const int am_ = tid >> 3, ak_ = (tid & 7) * 4;
    const float* arow[AG];
    #pragma unroll
    for (int g = 0; g < AG; g++)
        arow[g] = p.A + (long long)(m0 + am_ + 32*g) * p.lda;
    const int bn_ = tid & 31, bk_ = (tid >> 5) * 4;
    const float* bbase_r[BR];
    int sb_r[BR];
    bool nv_r[BR];
    #pragma unroll
    for (int rp = 0; rp < BR; rp++) {
        int gn = n0 + bn_ + 32*rp;
        nv_r[rp] = gn < p.N;
        int g = nv_r[rp] ? gn : 0;
        int b = 0, q = g;
        if (!(BMODE == 0 && p.sBb == 0)) { b = g / p.npos; q = g - b*p.npos; }
        const float* bb;
        if (BMODE == 0) bb = p.Bp + b*p.sBb + q;
        else bb = p.Bp + b*p.sBb + q;
        bbase_r[rp] = bb;
        sb_r[rp] = 0;
    }

    // ---- A smem store indices: fragment-major + XOR bank swizzle ----
    int aidx[AG];
    #pragma unroll
    for (int g = 0; g < AG; g++) {
        int m = am_ + 32*g;
        int kc = ak_ >> 3, kin = ak_ & 7;
        int frag = (kc*WR + (m >> 5))*2 + ((m >> 4) & 1);
        int lcomp = ((m & 7)*4) ^ ((frag & 7) << 2);
        aidx[g] = (frag*32 + lcomp)*4 + ((m >> 3) & 1) + 2*(kin >> 2);
    }
    int bidx[BR];
    #pragma unroll
    for (int rp = 0; rp < BR; rp++) {
        int n = bn_ + 32*rp;
        int kc = bk_ >> 3, kin = bk_ & 7;
        bidx[rp] = ((kc*(BN/8) + (n >> 3))*32 + (n & 7)*4 + (kin & 3))*2 + (kin >> 2);
    }

    float acc[2][NF][4];
    #pragma unroll
    for (int mi = 0; mi < 2; mi++)
        #pragma unroll
        for (int ni = 0; ni < NF; ni++)
            #pragma unroll
            for (int e = 0; e < 4; e++) acc[mi][ni][e] = 0.f;

    float ra[AG][4], rb[BR][4];
    // ---- prologue fill (tile kbeg) ----
    if (KALIGN) {
        #pragma unroll
        for (int g = 0; g < AG; g++) {
            float4 v = *(const float4*)&arow[g][kbeg + ak_];
            ra[g][0] = v.x; ra[g][1] = v.y; ra[g][2] = v.z; ra[g][3] = v.w;
        }
    } else {
        #pragma unroll
        for (int g = 0; g < AG; g++)
            #pragma unroll
            for (int j = 0; j < 4; j++) {
                int gk = kbeg + ak_ + j;
                ra[g][j] = (gk < p.K) ? arow[g][gk] : 0.f;
            }
    }
    #pragma unroll
    for (int rp = 0; rp < BR; rp++)
        #pragma unroll
        for (int j = 0; j < 4; j++)
            rb[rp][j] = nv_r[rp] ? ldB<BMODE, KK>(p, bbase_r[rp], sb_r[rp], kbeg + bk_ + j) : 0.f;
    #pragma unroll
    for (int g = 0; g < AG; g++)
        #pragma unroll
        for (int j = 0; j < 4; j++)
            As[aidx[g] + 4*j] = __uint_as_float(f2tf32(ra[g][j]));
    #pragma unroll
    for (int rp = 0; rp < BR; rp++)
        #pragma unroll
        for (int j = 0; j < 4; j++)
            Bs[bidx[rp] + 2*j] = __uint_as_float(f2tf32(rb[rp][j]));
    __syncthreads();

    int buf = 0;
    for (int k0 = kbeg; k0 < kend; k0 += BK) {
        int kn = k0 + BK;
        bool more = kn < kend;
        if (more) {
            if (KALIGN) {
                #pragma unroll
                for (int g = 0; g < AG; g++) {
                    float4 v = *(const float4*)&arow[g][kn + ak_];
                    ra[g][0] = v.x; ra[g][1] = v.y; ra[g][2] = v.z; ra[g][3] = v.w;
                }
            } else {
                #pragma unroll
                for (int g = 0; g < AG; g++)
                    #pragma unroll
                    for (int j = 0; j < 4; j++) {
                        int gk = kn + ak_ + j;
                        ra[g][j] = (gk < p.K) ? arow[g][gk] : 0.f;
                    }
            }
            #pragma unroll
            for (int rp = 0; rp < BR; rp++)
                #pragma unroll
                for (int j = 0; j < 4; j++)
                    rb[rp][j] = nv_r[rp] ? ldB<BMODE, KK>(p, bbase_r[rp], sb_r[rp], kn + bk_ + j) : 0.f;
        }
        const float* Ac = As + buf*ASZ;
        const float* Bc = Bs + buf*BSZ;
        #pragma unroll
        for (int kc = 0; kc < 4; kc++) {
            uint32_t af[2][4];
            #pragma unroll
            for (int mi = 0; mi < 2; mi++) {
                int frag = (kc*WR + wr)*2 + mi;
                const float4 av = *(const float4*)&Ac[(frag*32 + (lane ^ ((frag & 7) << 2)))*4];
                af[mi][0] = __float_as_uint(av.x);
                af[mi][1] = __float_as_uint(av.y);
                af[mi][2] = __float_as_uint(av.z);
                af[mi][3] = __float_as_uint(av.w);
            }
            uint32_t bf[NF][2];
            #pragma unroll
            for (int ni = 0; ni < NF; ni++) {
                const float2 bv = *(const float2*)&Bc[((kc*(BN/8) + wc*NF + ni)*32 + lane)*2];
                bf[ni][0] = __float_as_uint(bv.x);
                bf[ni][1] = __float_as_uint(bv.y);
            }
            #pragma unroll
            for (int mi = 0; mi < 2; mi++)
                #pragma unroll
                for (int ni = 0; ni < NF; ni++)
                    mma_tf32(acc[mi][ni], af[mi], bf[ni]);
        }
        if (more) {
            float* An = As + (buf^1)*ASZ;
            float* Bn = Bs + (buf^1)*BSZ;
            #pragma unroll
            for (int g = 0; g < AG; g++)
                #pragma unroll
                for (int j = 0; j < 4; j++)
                    An[aidx[g] + 4*j] = __uint_as_float(f2tf32(ra[g][j]));
            #pragma unroll
            for (int rp = 0; rp < BR; rp++)
                #pragma unroll
                for (int j = 0; j < 4; j++)
                    Bn[bidx[rp] + 2*j] = __uint_as_float(f2tf32(rb[rp][j]));
        }
        __syncthreads();
        buf ^= 1;
    }

    // ---- epilogue ----
    if (SPLITK > 1) {
        float* pd = p.part + (size_t)blockIdx.z * ((size_t)p.M * p.N);
        #pragma unroll
        for (int mi = 0; mi < 2; mi++)
            #pragma unroll
            for (int half = 0; half < 2; half++) {
                int row = m0 + wr*32 + mi*16 + (lane >> 2) + half*8;
                #pragma unroll
                for (int ni = 0; ni < NF; ni++)
                    #pragma unroll
                    for (int e = 0; e < 2; e++) {
                        int gn = n0 + wc*WN + ni*8 + (lane & 3)*2 + e;
                        if (gn < p.N)
                            pd[(size_t)row*p.N + gn] = acc[mi][ni][half*2 + e];
                    }
            }
        return;
    }
    #pragma unroll
    for (int mi = 0; mi < 2; mi++) {
        #pragma unroll
        for (int half = 0; half < 2; half++) {
            int row = m0 + wr*32 + mi*16 + (lane >> 2) + half*8;
            float brow = 0.f;
            if (BIASM == 1) brow = p.bias[row];
            else if (BIASM == 3) brow = p.bias[row / p.kt];
            int cout = 0, jj = 0;
            if (SMODE == 1) { cout = row / p.kt; jj = row - cout*p.kt; }
            #pragma unroll
            for (int ni = 0; ni < NF; ni++) {
                #pragma unroll
                for (int e = 0; e < 2; e++) {
                    int gn = n0 + wc*WN + ni*8 + (lane & 3)*2 + e;
                    if (gn >= p.N) continue;
                    int b, q;
                    if (SMODE == 0 && p.sDb == 0) { b = 0; q = gn; }
                    else { b = gn / p.npos; q = gn - b*p.npos; }
                    float v = acc[mi][ni][half*2 + e] + brow;
                    if (BIASM == 2) v += p.bias[q];
                    if (ACT == 1) v = tanhf(v);
                    else if (ACT == 2) v = fmaxf(v, 0.f);
                    long long addr;
                    if (SMODE == 0) addr = b*p.sDb + (long long)row*p.ldd + q;
                    else addr = b*p.sDb + (long long)cout*p.mklen + (long long)q*p.kt + jj;
                    p.D[addr] = v;
                }
            }
        }
    }
}

// ---------------- split-K reduce + bias + tanh + batched store ----------------
__global__ void reduce_ep_k(const float* __restrict__ part, float* __restrict__ D,
                            const float* __restrict__ bias,
                            int S, int M, int N, long long sDb, int ldd, int npos) {
    int idx = blockIdx.x*blockDim.x + threadIdx.x;
    if (idx >= M*N) return;
    int row = idx / N, gn = idx - row*N;
    size_t st = (size_t)M*N;
    float v = 0.f;
    for (int z = 0; z < S; z++) v += part[(size_t)z*st + idx];
    v = tanhf(v + bias[row]);
    int b = gn / npos, q = gn - b*npos;
    D[b*sDb + (long long)row*ldd + q] = v;
}

// ---------------- block reduce + layer norms ----------
__device__ __forceinline__ float blk_sum(float v) {
    __shared__ float sb[8];
    #pragma unroll
    for (int o = 16; o; o >>= 1) v += __shfl_xor_sync(0xffffffffu, v, o);
    if ((threadIdx.x & 31) == 0) sb[threadIdx.x >> 5] = v;
    __syncthreads();
    float t = 0.f;
    #pragma unroll
    for (int i = 0; i < 8; i++) t += sb[i];
    __syncthreads();
    return t;
}

__global__ void ln1_kernel(const float* __restrict__ xr, const float* __restrict__ x1,
                           const float* __restrict__ g, const float* __restrict__ bt,
                           float* __restrict__ out, int m) {
    int row = blockIdx.x;
    int b = row / m, t = row - b*m;
    int tid = threadIdx.x;
    size_t base = (size_t)b*NC*m + t;
    float v0 = xr[base + (size_t)tid*m]       + x1[base + (size_t)tid*m];
    float v1 = xr[base + (size_t)(tid+256)*m] + x1[base + (size_t)(tid+256)*m];
    float mu = blk_sum(v0 + v1) * (1.f/NC);
    float d0 = v0 - mu, d1 = v1 - mu;
    float var = blk_sum(d0*d0 + d1*d1) * (1.f/NC);
    float inv = rsqrtf(var + 1e-5f);
    out[base + (size_t)tid*m]       = d0*inv*g[tid]     + bt[tid];
    out[base + (size_t)(tid+256)*m] = d1*inv*g[tid+256] + bt[tid+256];
}

__global__ void branch_out_kernel(const float* __restrict__ y2, const float* __restrict__ resn,
                                  const float* __restrict__ g, const float* __restrict__ bt,
                                  float* __restrict__ br, int mk, int nbr) {
    int row = blockIdx.x;
    int b = row >> 10, l = row & 1023;
    int li = (l * mk) >> 10;
    int tid = threadIdx.x;
    size_t yb = (size_t)b*NC*mk + li;
    size_t rb = (size_t)b*NC*NL + l;
    float v0 = y2[yb + (size_t)tid*mk]       + resn[rb + (size_t)tid*NL];
    float v1 = y2[yb + (size_t)(tid+256)*mk] + resn[rb + (size_t)(tid+256)*NL];
    float mu = blk_sum(v0 + v1) * (1.f/NC);
    float d0 = v0 - mu, d1 = v1 - mu;
    float var = blk_sum(d0*d0 + d1*d1) * (1.f/NC);
    float inv = rsqrtf(var + 1e-5f);
    float* o = br + (size_t)row*(2*NC) + nbr*NC;
    o[tid]     = d0*inv*g[tid]     + bt[tid];
    o[tid+256] = d1*inv*g[tid+256] + bt[tid+256];
}

__global__ void final_ln_kernel(const float* __restrict__ mg, const float* __restrict__ h2,
                                const float* __restrict__ g, const float* __restrict__ bt,
                                float* __restrict__ out) {
    int row = blockIdx.x;
    int tid = threadIdx.x;
    size_t base = (size_t)row*NC;
    float v0 = mg[base + tid]       + h2[base + tid];
    float v1 = mg[base + tid + 256] + h2[base + tid + 256];
    float mu = blk_sum(v0 + v1) * (1.f/NC);
    float d0 = v0 - mu, d1 = v1 - mu;
    float var = blk_sum(d0*d0 + d1*d1) * (1.f/NC);
    float inv = rsqrtf(var + 1e-5f);
    out[base + tid]       = d0*inv*g[tid]     + bt[tid];
    out[base + tid + 256] = d1*inv*g[tid+256] + bt[tid+256];
}

template<int BN, int SPLITK>
static inline dim3 gg(int M, int N) { return dim3((N + BN - 1)/BN, M/128, SPLITK); }

template<int BN, int BMODE, int KK, int KALIGN, int BIASM, int ACT, int SMODE, int SPLITK = 1>
static void launch_gemm(const GemmP& p) {
    constexpr int SMEM = 2*(128*32 + 32*BN)*4;
    cudaFuncSetAttribute((const void*)gemm_k<BN,BMODE,KK,KALIGN,BIASM,ACT,SMODE,SPLITK>,
                         cudaFuncAttributeMaxDynamicSharedMemorySize, SMEM);
    gemm_k<BN,BMODE,KK,KALIGN,BIASM,ACT,SMODE,SPLITK><<<gg<BN,SPLITK>(p.M, p.N), 256, SMEM>>>(p);
}

extern "C" void kernel_launch(void* const* d_in, const int* in_sizes, int n_in,
                              void* d_out, int out_size) {
    (void)in_sizes; (void)n_in; (void)out_size;
    const float* src   = (const float*)d_in[0];
    const float* cw[2] = {(const float*)d_in[1],  (const float*)d_in[7]};
    const float* cb[2] = {(const float*)d_in[2],  (const float*)d_in[8]};
    const float* iw[2] = {(const float*)d_in[3],  (const float*)d_in[9]};
    const float* ib[2] = {(const float*)d_in[4],  (const float*)d_in[10]};
    const float* tw[2] = {(const float*)d_in[5],  (const float*)d_in[11]};
    const float* tb[2] = {(const float*)d_in[6],  (const float*)d_in[12]};
    const float* mw  = (const float*)d_in[13];
    const float* mb  = (const float*)d_in[14];
    const float* ng  = (const float*)d_in[15];
    const float* nb  = (const float*)d_in[16];
    const float* fw1 = (const float*)d_in[17];
    const float* fb1 = (const float*)d_in[18];
    const float* fw2 = (const float*)d_in[19];
    const float* fb2 = (const float*)d_in[20];
    const float* fng = (const float*)d_in[21];
    const float* fnb = (const float*)d_in[22];
    float* out = (float*)d_out;

    float *p_res,*p_cv,*p_x1,*p_xf,*p_xi,*p_xr,*p_yln,*p_y2,*p_br,*p_mg,*p_h1,*p_h2;
    float *p_W2a,*p_W2b,*p_Wm,*p_CM0,*p_CM20,*p_CM1,*p_CM21,*p_part,*p_im;
    cudaGetSymbolAddress((void**)&p_res, g_res);
    cudaGetSymbolAddress((void**)&p_cv,  g_cv);
    cudaGetSymbolAddress((void**)&p_x1,  g_x1);
    cudaGetSymbolAddress((void**)&p_xf,  g_xf);
    cudaGetSymbolAddress((void**)&p_xi,  g_xi);
    cudaGetSymbolAddress((void**)&p_xr,  g_xr);
    cudaGetSymbolAddress((void**)&p_yln, g_yln);
    cudaGetSymbolAddress((void**)&p_y2,  g_y2);
    cudaGetSymbolAddress((void**)&p_br,  g_br);
    cudaGetSymbolAddress((void**)&p_mg,  g_mg);
    cudaGetSymbolAddress((void**)&p_h1,  g_h1);
    cudaGetSymbolAddress((void**)&p_h2,  g_h2);
    cudaGetSymbolAddress((void**)&p_W2a, g_W2a);
    cudaGetSymbolAddress((void**)&p_W2b, g_W2b);
    cudaGetSymbolAddress((void**)&p_Wm,  g_Wm);
    cudaGetSymbolAddress((void**)&p_CM0, g_CM0);
    cudaGetSymbolAddress((void**)&p_CM20,g_CM20);
    cudaGetSymbolAddress((void**)&p_CM1, g_CM1);
    cudaGetSymbolAddress((void**)&p_CM21,g_CM21);
    cudaGetSymbolAddress((void**)&p_part,g_part);
    cudaGetSymbolAddress((void**)&p_im,  g_im);

    const int Kk[2] = {12, 24}, NE[2] = {43, 22},
              MM[2] = {85, 43}, N2_[2] = {169, 85}, MKl[2] = {1020, 1032};
    float* CMv[2]  = {p_CM0, p_CM1};
    float* CM2v[2] = {p_CM20, p_CM21};
    float* W2v[2]  = {p_W2a, p_W2b};
    float* cpart[2] = {p_part, p_part + (size_t)6*1024*1024};

    decomp_kernel<<<dim3(NL/32, NC/32, NB), dim3(32, 32)>>>(src, p_res);
    prep_all<<<2048, 256>>>(mw, p_Wm, tw[0], p_W2a, tw[1], p_W2b,
                            p_CM0, p_CM20, p_CM1, p_CM21);

    // conv via materialized im2col + dense split-K GEMM
    for (int n = 0; n < 2; n++) {
        int k = Kk[n], ne2 = 2*NE[n];
        int Nn = NB*ne2;
        if (n == 0) im2col_conv_k<12,86><<<NC*12, 256>>>(p_res, p_im, 6);
        else        im2col_conv_k<24,44><<<NC*24, 256>>>(p_res + (size_t)NB*NC*NL, p_im, 12);
        GemmP p{};
        p.A = cw[n]; p.lda = NC*k;
        p.Bp = p_im; p.ldb = Nn; p.sBb = 0;
        p.part = cpart[n];
        p.bias = cb[n];
        p.M = NC; p.N = Nn; p.K = NC*k; p.npos = ne2;
        if (n == 0) launch_gemm<64,0,1,1,1,1,0,4>(p);
        else        launch_gemm<64,0,1,1,1,1,0,8>(p);
        reduce_ep_k<<<(NC*Nn + 255)/256, 256>>>(cpart[n], p_cv + (size_t)n*NB*NC*86, cb[n],
                                                (n == 0) ? 4 : 8, NC, Nn,
                                                (long long)NC*ne2, ne2, ne2);
    }

    for (int n = 0; n < 2; n++) {
        int k = Kk[n], m = MM[n], N2 = N2_[n], mk = MKl[n];
        int ne2 = 2*NE[n];

        x1_kernel<<<1024, 256>>>(p_cv + (size_t)n*NB*NC*86, p_x1, m, ne2);
        { // real-DFT (K=85/43 ragged -> guarded A fills)
            GemmP p{};
            p.A = p_x1; p.lda = m;
            p.Bp = CMv[n]; p.ldb = N2; p.sBb = 0;
            p.D = p_xf; p.sDb = 0; p.ldd = N2;
            p.M = NB*NC; p.N = N2; p.K = m; p.npos = N2;
            launch_gemm<64,0,1,0,0,0,0>(p);
        }
        { // isometric conv (valid), tanh — split-K
            GemmP p{};
            p.A = iw[n]; p.lda = NC*m;
            p.Bp = p_xf; p.sBb = (long long)NC*N2; p.inner = N2;
            p.part = p_part;
            p.bias = ib[n];
            p.M = NC; p.N = NB*m; p.K = NC*m; p.npos = m;
            if (n == 0) launch_gemm<64,2,85,1,1,1,0,8>(p);
            else        launch_gemm<64,2,43,1,1,1,0,8>(p);
            reduce_ep_k<<<(NC*NB*m + 255)/256, 256>>>(p_part, p_xi, ib[n],
                                                      8, NC, NB*m,
                                                      (long long)NC*m, m, m);
        }
        { // real-IDFT (ragged K)
            GemmP p{};
            p.A = p_xi; p.lda = m;
            p.Bp = CM2v[n]; p.ldb = m; p.sBb = 0;
            p.D = p_xr; p.sDb = 0; p.ldd = m;
            p.M = NB*NC; p.N = m; p.K = m; p.npos = m;
            launch_gemm<64,0,1,0,0,0,0>(p);
        }
        ln1_kernel<<<NB*m, 256>>>(p_xr, p_x1, ng, nb, p_yln, m);
        { // conv-transpose (stride==kernel), tanh, scatter store
            GemmP p{};
            p.A = W2v[n]; p.lda = NC;
            p.Bp = p_yln; p.ldb = m; p.sBb = (long long)NC*m;
            p.D = p_y2; p.sDb = (long long)NC*mk; p.kt = k; p.mklen = mk;
            p.bias = tb[n];
            p.M = NC*k; p.N = NB*m; p.K = NC; p.npos = m;
            launch_gemm<128,0,1,1,3,1,1>(p);
        }
        branch_out_kernel<<<NB*NL, 256>>>(p_y2, p_res + (size_t)n*NB*NC*NL, ng, nb, p_br, mk, n);
    }
    { // merge
        GemmP p{};
        p.A = p_br; p.lda = 2*NC;
        p.Bp = p_Wm; p.ldb = NC; p.sBb = 0;
        p.D = p_mg; p.sDb = 0; p.ldd = NC;
        p.bias = mb;
        p.M = NB*NL; p.N = NC; p.K = 2*NC; p.npos = NC;
        launch_gemm<128,0,1,1,2,0,0>(p);
    }
    { // FFN layer 1 (relu)
        GemmP p{};
        p.A = p_mg; p.lda = NC;
        p.Bp = fw1; p.ldb = 4*NC; p.sBb = 0;
        p.D = p_h1; p.sDb = 0; p.ldd = 4*NC;
        p.bias = fb1;
        p.M = NB*NL; p.N = 4*NC; p.K = NC; p.npos = 4*NC;
        launch_gemm<128,0,1,1,2,2,0>(p);
    }
    { // FFN layer 2
        GemmP p{};
        p.A = p_h1; p.lda = 4*NC;
        p.Bp = fw2; p.ldb = NC; p.sBb = 0;
        p.D = p_h2; p.sDb = 0; p.ldd = NC;
        p.bias = fb2;
        p.M = NB*NL; p.N = NC; p.K = 4*NC; p.npos = NC;
        launch_gemm<128,0,1,1,2,0,0>(p);
    }
    final_ln_kernel<<<NB*NL, 256>>>(p_mg, p_h2, fng, fnb, out);
}

// round 11
// speedup vs baseline: 1.4491x; 1.2399x over previous
#include <cuda_runtime.h>
#include <math.h>
#include <stdint.h>

#define NB 32
#define NL 1024
#define NC 512
#define LH 512   // L/2

// ---------------- scratch (device globals; no allocations) ----------------
__device__ float g_res[(size_t)2*NB*NC*NL];     // [2][B][C][L]
__device__ float g_cv [(size_t)2*NB*NC*86];     // conv out interleaved, per branch
__device__ float g_x1 [(size_t)NB*NC*85];       // [B][C][m]
__device__ float g_xf [(size_t)NB*NC*169];      // [B][C][2m-1]
__device__ float g_xi [(size_t)NB*NC*85];
__device__ float g_xr [(size_t)NB*NC*85];
__device__ float g_yln[(size_t)NB*NC*85];
__device__ float g_y2 [(size_t)NB*NC*1032];     // [B][C][m*k]
__device__ float g_br [(size_t)NB*NL*2*NC];     // [B*L][2*C]
__device__ float g_mg [(size_t)NB*NL*NC];
__device__ float g_h1 [(size_t)NB*NL*4*NC];
__device__ float g_h2 [(size_t)NB*NL*NC];
__device__ float g_W2a[(size_t)NC*12*NC];
__device__ float g_W2b[(size_t)NC*24*NC];
__device__ float g_Wm [(size_t)2*NC*NC];
__device__ float g_CM0 [85*169];
__device__ float g_CM20[85*85];
__device__ float g_CM1 [43*85];
__device__ float g_CM21[43*43];
__device__ float g_part[(size_t)12*1024*1024];  // split-K partials workspace
__device__ float g_im [(size_t)18*1024*1024];   // materialized conv im2col

// ---------------- series decomp ----------------
__global__ void decomp_kernel(const float* __restrict__ src, float* __restrict__ res) {
    __shared__ float s[64][33];
    int b = blockIdx.z;
    int c0 = blockIdx.y * 32;
    int l0 = blockIdx.x * 32;
    int tx = threadIdx.x, ty = threadIdx.y;
    for (int r = ty; r < 64; r += 32) {
        int l = l0 - 16 + r;
        l = l < 0 ? 0 : (l > NL - 1 ? NL - 1 : l);
        s[r][tx] = src[((size_t)b*NL + l)*NC + c0 + tx];
    }
    __syncthreads();
    int base = tx + 16;
    float s17 = 0.f;
    #pragma unroll
    for (int j = -8; j <= 8; j++) s17 += s[base + j][ty];
    float s33 = s17;
    #pragma unroll
    for (int j = 9; j <= 16; j++) s33 += s[base - j][ty] + s[base + j][ty];
    float v = s[base][ty];
    size_t o = ((size_t)(b*NC + c0 + ty))*NL + l0 + tx;
    res[o] = v - s17 / 17.0f;
    res[(size_t)NB*NC*NL + o] = v - s33 / 33.0f;
}

// ---------------- fused prep ----------------
__global__ void prep_all(const float* __restrict__ mwt, float* __restrict__ Wm,
                         const float* __restrict__ tw0, float* __restrict__ W2a,
                         const float* __restrict__ tw1, float* __restrict__ W2b,
                         float* __restrict__ CM0, float* __restrict__ CM20,
                         float* __restrict__ CM1, float* __restrict__ CM21) {
    const double TWO_PI = 6.283185307179586476925286766559;
    const int tM = NC*NC*2;
    const int tA = NC*NC*12, tB = NC*NC*24;
    const int c0 = 85*169, c1 = 85*85, c2 = 43*85, c3 = 43*43;
    int total = tM + tA + tB + c0 + c1 + c2 + c3;
    for (int idx = blockIdx.x*blockDim.x + threadIdx.x; idx < total; idx += gridDim.x*blockDim.x) {
        int i = idx;
        if (i < tM) {
            int o = i / (NC*2);
            int rem = i - o*NC*2;
            int c = rem >> 1, n = rem & 1;
            Wm[((size_t)n*NC + c)*NC + o] = mwt[i];
            continue;
        }
        i -= tM;
        if (i < tA) {
            int cin = i / (NC*12);
            int r   = i - cin*(NC*12);
            W2a[(size_t)r*NC + cin] = tw0[i];
            continue;
        }
        i -= tA;
        if (i < tB) {
            int cin = i / (NC*24);
            int r   = i - cin*(NC*24);
            W2b[(size_t)r*NC + cin] = tw1[i];
            continue;
        }
        i -= tB;
        if (i < c0) {
            int t = i / 169, f = i - t*169;
            CM0[i] = (float)cos(TWO_PI * (double)((long long)f*(t + 84)) / 169.0);
            continue;
        }
        i -= c0;
        if (i < c1) {
            int f = i / 85, t = i - f*85;
            CM20[i] = (float)(cos(TWO_PI * (double)((long long)f*t) / 85.0) / 85.0);
            continue;
        }
        i -= c1;
        if (i < c2) {
            int t = i / 85, f = i - t*85;
            CM1[i] = (float)cos(TWO_PI * (double)((long long)f*(t + 42)) / 85.0);
            continue;
        }
        i -= c2;
        {
            int f = i / 43, t = i - f*43;
            CM21[i] = (float)(cos(TWO_PI * (double)((long long)f*t) / 43.0) / 43.0);
        }
    }
}

// ---------------- conv im2col materialization (coalesced writes) ----------------
template<int KK, int NE2>
__global__ void im2col_conv_k(const float* __restrict__ res, float* __restrict__ out, int pad) {
    int gk = blockIdx.x;
    int cin = gk / KK, t = gk - cin*KK;
    const int N = NB*NE2;
    const float* rbase = res + (size_t)cin*NL;
    float* obase = out + (size_t)gk*N;
    int tb = t - pad;
    for (int gn = threadIdx.x; gn < N; gn += blockDim.x) {
        int b = gn / NE2, q = gn - b*NE2;
        int s = (q >> 1)*KK + tb;
        float v = (s >= 0 && s < LH) ? rbase[(size_t)b*NC*NL + 2*s + (q & 1)] : 0.f;
        obase[gn] = v;
    }
}

// ---------------- x1: exp-gated interleave, drop last ----------------
__global__ void x1_kernel(const float* __restrict__ cv, float* __restrict__ x1, int m, int ne2) {
    size_t total = (size_t)NB*NC*m;
    for (size_t idx = (size_t)blockIdx.x*blockDim.x + threadIdx.x; idx < total;
         idx += (size_t)gridDim.x*blockDim.x) {
        int t = (int)(idx % m);
        size_t bc = idx / m;
        const float* c2 = cv + bc*ne2;
        x1[idx] = c2[t ^ 1] * expf(c2[t]);
    }
}

// ---------------- GEMM params ----------------
struct GemmP {
    const float* A; int lda;
    const float* Bp; int ldb; long long sBb;
    float* D; long long sDb; int ldd;
    const float* bias;
    int M, N, K;
    int npos;
    int pad, lhalf, inner;
    int kt, mklen;
    float* part;
};

__device__ __forceinline__ uint32_t f2tf32(float v) {
    uint32_t u;
    asm("cvt.rna.tf32.f32 %0, %1;" : "=r"(u) : "f"(v));
    return u;
}
__device__ __forceinline__ void mma_tf32(float c[4], const uint32_t a[4], const uint32_t b[2]) {
    asm("mma.sync.aligned.m16n8k8.row.col.f32.tf32.tf32.f32 "
        "{%0,%1,%2,%3},{%4,%5,%6,%7},{%8,%9},{%0,%1,%2,%3};"
        : "+f"(c[0]), "+f"(c[1]), "+f"(c[2]), "+f"(c[3])
        : "r"(a[0]), "r"(a[1]), "r"(a[2]), "r"(a[3]), "r"(b[0]), "r"(b[1]));
}

template<int BMODE, int KK>
__device__ __forceinline__ float ldB(const GemmP& p, const float* bbase, int gk) {
    if (gk >= p.K) return 0.f;
    if (BMODE == 0) return bbase[(long long)gk * p.ldb];
    int cin = gk / KK, t = gk - cin*KK;
    return bbase[(long long)cin*p.inner + t];
}

// tf32 mma.sync GEMM: BM=128, BN in {64,128}, BK=32.
// Gather-style fills: one STS.128 per thread-rep, conflict-free layouts.
// KALIGN=1: K multiple of 32 -> unguarded A gathers.
// BMODE: 0 dense, 2 iso-im2col (KK: conv kernel size)
// BIASM: 0 none, 1 per-row, 2 per-col(q), 3 bias[row/kt]
// ACT: 0 none, 1 tanh, 2 relu.  SMODE: 0 normal, 1 transconv scatter.
// SPLITK>1: raw partials to p.part; epilogue by reduce kernel.  M % 128 == 0.
template<int BN, int BMODE, int KK, int KALIGN, int BIASM, int ACT, int SMODE, int SPLITK>
__global__ void __launch_bounds__(256, (BN == 64) ? 2 : 1)
gemm_k(GemmP p) {
    constexpr int BM = 128, BK = 32;
    constexpr int WR = 4, WC = 2;
    constexpr int WN = BN/WC, NF = WN/8;
    constexpr int BRP = BN/32;           // B fill reps
    constexpr int ASZ = BM*BK, BSZ = BK*BN;
    extern __shared__ float dyn[];
    float* As = dyn;
    float* Bs = dyn + 2*ASZ;

    const int tid = threadIdx.x, lane = tid & 31, warp = tid >> 5;
    const int wr = warp % WR, wc = warp / WR;
    const int m0 = blockIdx.y * BM, n0 = blockIdx.x * BN;

    int kbeg = 0, kend = p.K;
    if (SPLITK > 1) {
        int kc = ((p.K + SPLITK*BK - 1) / (SPLITK*BK)) * BK;
        kbeg = blockIdx.z * kc;
        kend = min(kbeg + kc, p.K);
    }

    // ---- A gather-fill setup: rep g -> fragment warp+8g, slot=lane ----
    const float* a0p[4];
    long long a8;                         // +8 rows offset
    int akc[4], astore[4];
    a8 = 8LL * p.lda;
    #pragma unroll
    for (int g = 0; g < 4; g++) {
        int fragid = warp + 8*g;
        int kc = fragid >> 3, sub = fragid & 7;
        int wr_ = sub >> 1, mi = sub & 1;
        int mrow = m0 + wr_*32 + mi*16 + (lane >> 2);
        a0p[g] = p.A + (long long)mrow * p.lda;
        akc[g] = kc*8 + (lane & 3);
        astore[g] = fragid*128 + lane*4;
    }
    // ---- B gather-fill setup: warp -> (kc, cbase); lane+32rp -> n ----
    const int bkl0 = (warp >> 1)*8 + (warp & 1)*2;   // kc*8 + cbase
    const float* bb_r[BRP];
    int bstore[BRP];
    bool nv_r[BRP];
    #pragma unroll
    for (int rp = 0; rp < BRP; rp++) {
        int ln = lane + 32*rp;            // n within tile
        int gn = n0 + ln;
        nv_r[rp] = gn < p.N;
        int g = nv_r[rp] ? gn : 0;
        int b = 0, q = g;
        if (!(BMODE == 0 && p.sBb == 0)) { b = g / p.npos; q = g - b*p.npos; }
        bb_r[rp] = p.Bp + b*p.sBb + q;
        int fb = (warp >> 1)*(BN/8) + (ln >> 3);
        int X = (ln & 7)*4 + (warp & 1)*2;
        X ^= ((X >> 4) & 1) << 1;
        bstore[rp] = fb*64 + X*2;
    }
    const int physl = lane ^ (((lane >> 4) & 1) << 1);   // B compute lane swizzle

    float acc[2][NF][4];
    #pragma unroll
    for (int mi = 0; mi < 2; mi++)
        #pragma unroll
        for (int ni = 0; ni < NF; ni++)
            #pragma unroll
            for (int e = 0; e < 4; e++) acc[mi][ni][e] = 0.f;

    float ra[4][4], rb[BRP][4];
    // ---- prologue: gather tile kbeg ----
    #pragma unroll
    for (int g = 0; g < 4; g++) {
        int ka = kbeg + akc[g];
        if (KALIGN) {
            ra[g][0] = a0p[g][ka];      ra[g][1] = a0p[g][a8 + ka];
            ra[g][2] = a0p[g][ka + 4];  ra[g][3] = a0p[g][a8 + ka + 4];
        } else {
            bool v0 = ka < p.K, v1 = ka + 4 < p.K;
            ra[g][0] = v0 ? a0p[g][ka] : 0.f;
            ra[g][1] = v0 ? a0p[g][a8 + ka] : 0.f;
            ra[g][2] = v1 ? a0p[g][ka + 4] : 0.f;
            ra[g][3] = v1 ? a0p[g][a8 + ka + 4] : 0.f;
        }
    }
    #pragma unroll
    for (int rp = 0; rp < BRP; rp++) {
        rb[rp][0] = nv_r[rp] ? ldB<BMODE,KK>(p, bb_r[rp], kbeg + bkl0)     : 0.f;
        rb[rp][1] = nv_r[rp] ? ldB<BMODE,KK>(p, bb_r[rp], kbeg + bkl0 + 4) : 0.f;
        rb[rp][2] = nv_r[rp] ? ldB<BMODE,KK>(p, bb_r[rp], kbeg + bkl0 + 1) : 0.f;
        rb[rp][3] = nv_r[rp] ? ldB<BMODE,KK>(p, bb_r[rp], kbeg + bkl0 + 5) : 0.f;
    }
    #pragma unroll
    for (int g = 0; g < 4; g++) {
        float4 v;
        v.x = __uint_as_float(f2tf32(ra[g][0]));
        v.y = __uint_as_float(f2tf32(ra[g][1]));
        v.z = __uint_as_float(f2tf32(ra[g][2]));
        v.w = __uint_as_float(f2tf32(ra[g][3]));
        *(float4*)&As[astore[g]] = v;
    }
    #pragma unroll
    for (int rp = 0; rp < BRP; rp++) {
        float4 v;
        v.x = __uint_as_float(f2tf32(rb[rp][0]));
        v.y = __uint_as_float(f2tf32(rb[rp][1]));
        v.z = __uint_as_float(f2tf32(rb[rp][2]));
        v.w = __uint_as_float(f2tf32(rb[rp][3]));
        *(float4*)&Bs[bstore[rp]] = v;
    }
    __syncthreads();

    int buf = 0;
    for (int k0 = kbeg; k0 < kend; k0 += BK) {
        int kn = k0 + BK;
        bool more = kn < kend;
        if (more) {
            #pragma unroll
            for (int g = 0; g < 4; g++) {
                int ka = kn + akc[g];
                if (KALIGN) {
                    ra[g][0] = a0p[g][ka];      ra[g][1] = a0p[g][a8 + ka];
                    ra[g][2] = a0p[g][ka + 4];  ra[g][3] = a0p[g][a8 + ka + 4];
                } else {
                    bool v0 = ka < p.K, v1 = ka + 4 < p.K;
                    ra[g][0] = v0 ? a0p[g][ka] : 0.f;
                    ra[g][1] = v0 ? a0p[g][a8 + ka] : 0.f;
                    ra[g][2] = v1 ? a0p[g][ka + 4] : 0.f;
                    ra[g][3] = v1 ? a0p[g][a8 + ka + 4] : 0.f;
                }
            }
            #pragma unroll
            for (int rp = 0; rp < BRP; rp++) {
                rb[rp][0] = nv_r[rp] ? ldB<BMODE,KK>(p, bb_r[rp], kn + bkl0)     : 0.f;
                rb[rp][1] = nv_r[rp] ? ldB<BMODE,KK>(p, bb_r[rp], kn + bkl0 + 4) : 0.f;
                rb[rp][2] = nv_r[rp] ? ldB<BMODE,KK>(p, bb_r[rp], kn + bkl0 + 1) : 0.f;
                rb[rp][3] = nv_r[rp] ? ldB<BMODE,KK>(p, bb_r[rp], kn + bkl0 + 5) : 0.f;
            }
        }
        const float* Ac = As + buf*ASZ;
        const float* Bc = Bs + buf*BSZ;
        #pragma unroll
        for (int kc = 0; kc < 4; kc++) {
            uint32_t af[2][4];
            #pragma unroll
            for (int mi = 0; mi < 2; mi++) {
                int frag = (kc*4 + wr)*2 + mi;
                const float4 av = *(const float4*)&Ac[frag*128 + lane*4];
                af[mi][0] = __float_as_uint(av.x);
                af[mi][1] = __float_as_uint(av.y);
                af[mi][2] = __float_as_uint(av.z);
                af[mi][3] = __float_as_uint(av.w);
            }
            uint32_t bf[NF][2];
            #pragma unroll
            for (int ni = 0; ni < NF; ni++) {
                const float2 bv = *(const float2*)&Bc[(kc*(BN/8) + wc*NF + ni)*64 + physl*2];
                bf[ni][0] = __float_as_uint(bv.x);
                bf[ni][1] = __float_as_uint(bv.y);
            }
            #pragma unroll
            for (int mi = 0; mi < 2; mi++)
                #pragma unroll
                for (int ni = 0; ni < NF; ni++)
                    mma_tf32(acc[mi][ni], af[mi], bf[ni]);
        }
        if (more) {
            float* An = As + (buf^1)*ASZ;
            float* Bn = Bs + (buf^1)*BSZ;
            #pragma unroll
            for (int g = 0; g < 4; g++) {
                float4 v;
                v.x = __uint_as_float(f2tf32(ra[g][0]));
                v.y = __uint_as_float(f2tf32(ra[g][1]));
                v.z = __uint_as_float(f2tf32(ra[g][2]));
                v.w = __uint_as_float(f2tf32(ra[g][3]));
                *(float4*)&An[astore[g]] = v;
            }
            #pragma unroll
            for (int rp = 0; rp < BRP; rp++) {
                float4 v;
                v.x = __uint_as_float(f2tf32(rb[rp][0]));
                v.y = __uint_as_float(f2tf32(rb[rp][1]));
                v.z = __uint_as_float(f2tf32(rb[rp][2]));
                v.w = __uint_as_float(f2tf32(rb[rp][3]));
                *(float4*)&Bn[bstore[rp]] = v;
            }
        }
        __syncthreads();
        buf ^= 1;
    }

    // ---- epilogue ----
    if (SPLITK > 1) {
        float* pd = p.part + (size_t)blockIdx.z * ((size_t)p.M * p.N);
        #pragma unroll
        for (int mi = 0; mi < 2; mi++)
            #pragma unroll
            for (int half = 0; half < 2; half++) {
                int row = m0 + wr*32 + mi*16 + (lane >> 2) + half*8;
                #pragma unroll
                for (int ni = 0; ni < NF; ni++)
                    #pragma unroll
                    for (int e = 0; e < 2; e++) {
                        int gn = n0 + wc*WN + ni*8 + (lane & 3)*2 + e;
                        if (gn < p.N)
                            pd[(size_t)row*p.N + gn] = acc[mi][ni][half*2 + e];
                    }
            }
        return;
    }
    #pragma unroll
    for (int mi = 0; mi < 2; mi++) {
        #pragma unroll
        for (int half = 0; half < 2; half++) {
            int row = m0 + wr*32 + mi*16 + (lane >> 2) + half*8;
            float brow = 0.f;
            if (BIASM == 1) brow = p.bias[row];
            else if (BIASM == 3) brow = p.bias[row / p.kt];
            int cout = 0, jj = 0;
            if (SMODE == 1) { cout = row / p.kt; jj = row - cout*p.kt; }
            #pragma unroll
            for (int ni = 0; ni < NF; ni++) {
                #pragma unroll
                for (int e = 0; e < 2; e++) {
                    int gn = n0 + wc*WN + ni*8 + (lane & 3)*2 + e;
                    if (gn >= p.N) continue;
                    int b, q;
                    if (SMODE == 0 && p.sDb == 0) { b = 0; q = gn; }
                    else { b = gn / p.npos; q = gn - b*p.npos; }
                    float v = acc[mi][ni][half*2 + e] + brow;
                    if (BIASM == 2) v += p.bias[q];
                    if (ACT == 1) v = tanhf(v);
                    else if (ACT == 2) v = fmaxf(v, 0.f);
                    long long addr;
                    if (SMODE == 0) addr = b*p.sDb + (long long)row*p.ldd + q;
                    else addr = b*p.sDb + (long long)cout*p.mklen + (long long)q*p.kt + jj;
                    p.D[addr] = v;
                }
            }
        }
    }
}

// ---------------- split-K reduce + bias + tanh + batched store ----------------
__global__ void reduce_ep_k(const float* __restrict__ part, float* __restrict__ D,
                            const float* __restrict__ bias,
                            int S, int M, int N, long long sDb, int ldd, int npos) {
    int idx = blockIdx.x*blockDim.x + threadIdx.x;
    if (idx >= M*N) return;
    int row = idx / N, gn = idx - row*N;
    size_t st = (size_t)M*N;
    float v = 0.f;
    for (int z = 0; z < S; z++) v += part[(size_t)z*st + idx];
    v = tanhf(v + bias[row]);
    int b = gn / npos, q = gn - b*npos;
    D[b*sDb + (long long)row*ldd + q] = v;
}

// ---------------- block reduce + layer norms ----------
__device__ __forceinline__ float blk_sum(float v) {
    __shared__ float sb[8];
    #pragma unroll
    for (int o = 16; o; o >>= 1) v += __shfl_xor_sync(0xffffffffu, v, o);
    if ((threadIdx.x & 31) == 0) sb[threadIdx.x >> 5] = v;
    __syncthreads();
    float t = 0.f;
    #pragma unroll
    for (int i = 0; i < 8; i++) t += sb[i];
    __syncthreads();
    return t;
}

__global__ void ln1_kernel(const float* __restrict__ xr, const float* __restrict__ x1,
                           const float* __restrict__ g, const float* __restrict__ bt,
                           float* __restrict__ out, int m) {
    int row = blockIdx.x;
    int b = row / m, t = row - b*m;
    int tid = threadIdx.x;
    size_t base = (size_t)b*NC*m + t;
    float v0 = xr[base + (size_t)tid*m]       + x1[base + (size_t)tid*m];
    float v1 = xr[base + (size_t)(tid+256)*m] + x1[base + (size_t)(tid+256)*m];
    float mu = blk_sum(v0 + v1) * (1.f/NC);
    float d0 = v0 - mu, d1 = v1 - mu;
    float var = blk_sum(d0*d0 + d1*d1) * (1.f/NC);
    float inv = rsqrtf(var + 1e-5f);
    out[base + (size_t)tid*m]       = d0*inv*g[tid]     + bt[tid];
    out[base + (size_t)(tid+256)*m] = d1*inv*g[tid+256] + bt[tid+256];
}

__global__ void branch_out_kernel(const float* __restrict__ y2, const float* __restrict__ resn,
                                  const float* __restrict__ g, const float* __restrict__ bt,
                                  float* __restrict__ br, int mk, int nbr) {
    int row = blockIdx.x;
    int b = row >> 10, l = row & 1023;
    int li = (l * mk) >> 10;
    int tid = threadIdx.x;
    size_t yb = (size_t)b*NC*mk + li;
    size_t rb = (size_t)b*NC*NL + l;
    float v0 = y2[yb + (size_t)tid*mk]       + resn[rb + (size_t)tid*NL];
    float v1 = y2[yb + (size_t)(tid+256)*mk] + resn[rb + (size_t)(tid+256)*NL];
    float mu = blk_sum(v0 + v1) * (1.f/NC);
    float d0 = v0 - mu, d1 = v1 - mu;
    float var = blk_sum(d0*d0 + d1*d1) * (1.f/NC);
    float inv = rsqrtf(var + 1e-5f);
    float* o = br + (size_t)row*(2*NC) + nbr*NC;
    o[tid]     = d0*inv*g[tid]     + bt[tid];
    o[tid+256] = d1*inv*g[tid+256] + bt[tid+256];
}

__global__ void final_ln_kernel(const float* __restrict__ mg, const float* __restrict__ h2,
                                const float* __restrict__ g, const float* __restrict__ bt,
                                float* __restrict__ out) {
    int row = blockIdx.x;
    int tid = threadIdx.x;
    size_t base = (size_t)row*NC;
    float v0 = mg[base + tid]       + h2[base + tid];
    float v1 = mg[base + tid + 256] + h2[base + tid + 256];
    float mu = blk_sum(v0 + v1) * (1.f/NC);
    float d0 = v0 - mu, d1 = v1 - mu;
    float var = blk_sum(d0*d0 + d1*d1) * (1.f/NC);
    float inv = rsqrtf(var + 1e-5f);
    out[base + tid]       = d0*inv*g[tid]     + bt[tid];
    out[base + tid + 256] = d1*inv*g[tid+256] + bt[tid+256];
}

template<int BN, int SPLITK>
static inline dim3 gg(int M, int N) { return dim3((N + BN - 1)/BN, M/128, SPLITK); }

template<int BN, int BMODE, int KK, int KALIGN, int BIASM, int ACT, int SMODE, int SPLITK = 1>
static void launch_gemm(const GemmP& p) {
    constexpr int SMEM = 2*(128*32 + 32*BN)*4;
    cudaFuncSetAttribute((const void*)gemm_k<BN,BMODE,KK,KALIGN,BIASM,ACT,SMODE,SPLITK>,
                         cudaFuncAttributeMaxDynamicSharedMemorySize, SMEM);
    gemm_k<BN,BMODE,KK,KALIGN,BIASM,ACT,SMODE,SPLITK><<<gg<BN,SPLITK>(p.M, p.N), 256, SMEM>>>(p);
}

extern "C" void kernel_launch(void* const* d_in, const int* in_sizes, int n_in,
                              void* d_out, int out_size) {
    (void)in_sizes; (void)n_in; (void)out_size;
    const float* src   = (const float*)d_in[0];
    const float* cw[2] = {(const float*)d_in[1],  (const float*)d_in[7]};
    const float* cb[2] = {(const float*)d_in[2],  (const float*)d_in[8]};
    const float* iw[2] = {(const float*)d_in[3],  (const float*)d_in[9]};
    const float* ib[2] = {(const float*)d_in[4],  (const float*)d_in[10]};
    const float* tw[2] = {(const float*)d_in[5],  (const float*)d_in[11]};
    const float* tb[2] = {(const float*)d_in[6],  (const float*)d_in[12]};
    const float* mw  = (const float*)d_in[13];
    const float* mb  = (const float*)d_in[14];
    const float* ng  = (const float*)d_in[15];
    const float* nb  = (const float*)d_in[16];
    const float* fw1 = (const float*)d_in[17];
    const float* fb1 = (const float*)d_in[18];
    const float* fw2 = (const float*)d_in[19];
    const float* fb2 = (const float*)d_in[20];
    const float* fng = (const float*)d_in[21];
    const float* fnb = (const float*)d_in[22];
    float* out = (float*)d_out;

    float *p_res,*p_cv,*p_x1,*p_xf,*p_xi,*p_xr,*p_yln,*p_y2,*p_br,*p_mg,*p_h1,*p_h2;
    float *p_W2a,*p_W2b,*p_Wm,*p_CM0,*p_CM20,*p_CM1,*p_CM21,*p_part,*p_im;
    cudaGetSymbolAddress((void**)&p_res, g_res);
    cudaGetSymbolAddress((void**)&p_cv,  g_cv);
    cudaGetSymbolAddress((void**)&p_x1,  g_x1);
    cudaGetSymbolAddress((void**)&p_xf,  g_xf);
    cudaGetSymbolAddress((void**)&p_xi,  g_xi);
    cudaGetSymbolAddress((void**)&p_xr,  g_xr);
    cudaGetSymbolAddress((void**)&p_yln, g_yln);
    cudaGetSymbolAddress((void**)&p_y2,  g_y2);
    cudaGetSymbolAddress((void**)&p_br,  g_br);
    cudaGetSymbolAddress((void**)&p_mg,  g_mg);
    cudaGetSymbolAddress((void**)&p_h1,  g_h1);
    cudaGetSymbolAddress((void**)&p_h2,  g_h2);
    cudaGetSymbolAddress((void**)&p_W2a, g_W2a);
    cudaGetSymbolAddress((void**)&p_W2b, g_W2b);
    cudaGetSymbolAddress((void**)&p_Wm,  g_Wm);
    cudaGetSymbolAddress((void**)&p_CM0, g_CM0);
    cudaGetSymbolAddress((void**)&p_CM20,g_CM20);
    cudaGetSymbolAddress((void**)&p_CM1, g_CM1);
    cudaGetSymbolAddress((void**)&p_CM21,g_CM21);
    cudaGetSymbolAddress((void**)&p_part,g_part);
    cudaGetSymbolAddress((void**)&p_im,  g_im);

    const int Kk[2] = {12, 24}, NE[2] = {43, 22},
              MM[2] = {85, 43}, N2_[2] = {169, 85}, MKl[2] = {1020, 1032};
    float* CMv[2]  = {p_CM0, p_CM1};
    float* CM2v[2] = {p_CM20, p_CM21};
    float* W2v[2]  = {p_W2a, p_W2b};
    float* cpart[2] = {p_part, p_part + (size_t)6*1024*1024};

    decomp_kernel<<<dim3(NL/32, NC/32, NB), dim3(32, 32)>>>(src, p_res);
    prep_all<<<2048, 256>>>(mw, p_Wm, tw[0], p_W2a, tw[1], p_W2b,
                            p_CM0, p_CM20, p_CM1, p_CM21);

    // conv via materialized im2col + dense split-K GEMM
    for (int n = 0; n < 2; n++) {
        int k = Kk[n], ne2 = 2*NE[n];
        int Nn = NB*ne2;
        if (n == 0) im2col_conv_k<12,86><<<NC*12, 256>>>(p_res, p_im, 6);
        else        im2col_conv_k<24,44><<<NC*24, 256>>>(p_res + (size_t)NB*NC*NL, p_im, 12);
        GemmP p{};
        p.A = cw[n]; p.lda = NC*k;
        p.Bp = p_im; p.ldb = Nn; p.sBb = 0;
        p.part = cpart[n];
        p.bias = cb[n];
        p.M = NC; p.N = Nn; p.K = NC*k; p.npos = ne2;
        if (n == 0) launch_gemm<64,0,1,1,1,1,0,4>(p);
        else        launch_gemm<64,0,1,1,1,1,0,8>(p);
        reduce_ep_k<<<(NC*Nn + 255)/256, 256>>>(cpart[n], p_cv + (size_t)n*NB*NC*86, cb[n],
                                                (n == 0) ? 4 : 8, NC, Nn,
                                                (long long)NC*ne2, ne2, ne2);
    }

    for (int n = 0; n < 2; n++) {
        int k = Kk[n], m = MM[n], N2 = N2_[n], mk = MKl[n];
        int ne2 = 2*NE[n];

        x1_kernel<<<1024, 256>>>(p_cv + (size_t)n*NB*NC*86, p_x1, m, ne2);
        { // real-DFT (ragged K -> guarded A gathers)
            GemmP p{};
            p.A = p_x1; p.lda = m;
            p.Bp = CMv[n]; p.ldb = N2; p.sBb = 0;
            p.D = p_xf; p.sDb = 0; p.ldd = N2;
            p.M = NB*NC; p.N = N2; p.K = m; p.npos = N2;
            launch_gemm<64,0,1,0,0,0,0>(p);
        }
        { // isometric conv (valid), tanh — split-K
            GemmP p{};
            p.A = iw[n]; p.lda = NC*m;
            p.Bp = p_xf; p.sBb = (long long)NC*N2; p.inner = N2;
            p.part = p_part;
            p.bias = ib[n];
            p.M = NC; p.N = NB*m; p.K = NC*m; p.npos = m;
            if (n == 0) launch_gemm<64,2,85,1,1,1,0,8>(p);
            else        launch_gemm<64,2,43,1,1,1,0,8>(p);
            reduce_ep_k<<<(NC*NB*m + 255)/256, 256>>>(p_part, p_xi, ib[n],
                                                      8, NC, NB*m,
                                                      (long long)NC*m, m, m);
        }
        { // real-IDFT (ragged K)
            GemmP p{};
            p.A = p_xi; p.lda = m;
            p.Bp = CM2v[n]; p.ldb = m; p.sBb = 0;
            p.D = p_xr; p.sDb = 0; p.ldd = m;
            p.M = NB*NC; p.N = m; p.K = m; p.npos = m;
            launch_gemm<64,0,1,0,0,0,0>(p);
        }
        ln1_kernel<<<NB*m, 256>>>(p_xr, p_x1, ng, nb, p_yln, m);
        { // conv-transpose (stride==kernel), tanh, scatter store
            GemmP p{};
            p.A = W2v[n]; p.lda = NC;
            p.Bp = p_yln; p.ldb = m; p.sBb = (long long)NC*m;
            p.D = p_y2; p.sDb = (long long)NC*mk; p.kt = k; p.mklen = mk;
            p.bias = tb[n];
            p.M = NC*k; p.N = NB*m; p.K = NC; p.npos = m;
            launch_gemm<128,0,1,1,3,1,1>(p);
        }
        branch_out_kernel<<<NB*NL, 256>>>(p_y2, p_res + (size_t)n*NB*NC*NL, ng, nb, p_br, mk, n);
    }
    { // merge
        GemmP p{};
        p.A = p_br; p.lda = 2*NC;
        p.Bp = p_Wm; p.ldb = NC; p.sBb = 0;
        p.D = p_mg; p.sDb = 0; p.ldd = NC;
        p.bias = mb;
        p.M = NB*NL; p.N = NC; p.K = 2*NC; p.npos = NC;
        launch_gemm<128,0,1,1,2,0,0>(p);
    }
    { // FFN layer 1 (relu)
        GemmP p{};
        p.A = p_mg; p.lda = NC;
        p.Bp = fw1; p.ldb = 4*NC; p.sBb = 0;
        p.D = p_h1; p.sDb = 0; p.ldd = 4*NC;
        p.bias = fb1;
        p.M = NB*NL; p.N = 4*NC; p.K = NC; p.npos = 4*NC;
        launch_gemm<128,0,1,1,2,2,0>(p);
    }
    { // FFN layer 2
        GemmP p{};
        p.A = p_h1; p.lda = 4*NC;
        p.Bp = fw2; p.ldb = NC; p.sBb = 0;
        p.D = p_h2; p.sDb = 0; p.ldd = NC;
        p.bias = fb2;
        p.M = NB*NL; p.N = NC; p.K = 4*NC; p.npos = NC;
        launch_gemm<128,0,1,1,2,0,0>(p);
    }
    final_ln_kernel<<<NB*NL, 256>>>(p_mg, p_h2, fng, fnb, out);
}

// round 12
// speedup vs baseline: 1.9370x; 1.3367x over previous
#include <cuda_runtime.h>
#include <math.h>
#include <stdint.h>

#define NB 32
#define NL 1024
#define NC 512
#define LH 512   // L/2

// ---------------- scratch (device globals; no allocations) ----------------
__device__ float g_res[(size_t)2*NB*NC*NL];     // [2][B][C][L]
__device__ float g_cv [(size_t)2*NB*NC*86];     // conv out interleaved, per branch
__device__ float g_x1 [(size_t)NB*NC*85];       // [B][C][m]
__device__ float g_xf [(size_t)NB*NC*169];      // [B][C][2m-1]
__device__ float g_xi [(size_t)NB*NC*85];
__device__ float g_xr [(size_t)NB*NC*85];
__device__ float g_yln[(size_t)NB*NC*85];
__device__ float g_y2 [(size_t)NB*NC*1032];     // [B][C][m*k]
__device__ float g_br [(size_t)NB*NL*2*NC];     // [B*L][2*C]
__device__ float g_mg [(size_t)NB*NL*NC];
__device__ float g_h1 [(size_t)NB*NL*4*NC];
__device__ float g_h2 [(size_t)NB*NL*NC];
__device__ float g_W2a[(size_t)NC*12*NC];
__device__ float g_W2b[(size_t)NC*24*NC];
__device__ float g_Wm [(size_t)2*NC*NC];
__device__ float g_CM0 [85*169];
__device__ float g_CM20[85*85];
__device__ float g_CM1 [43*85];
__device__ float g_CM21[43*43];
__device__ float g_part[(size_t)12*1024*1024];  // split-K partials workspace
__device__ float g_im [(size_t)18*1024*1024];   // materialized conv im2col

// ---------------- series decomp ----------------
__global__ void decomp_kernel(const float* __restrict__ src, float* __restrict__ res) {
    __shared__ float s[64][33];
    int b = blockIdx.z;
    int c0 = blockIdx.y * 32;
    int l0 = blockIdx.x * 32;
    int tx = threadIdx.x, ty = threadIdx.y;
    for (int r = ty; r < 64; r += 32) {
        int l = l0 - 16 + r;
        l = l < 0 ? 0 : (l > NL - 1 ? NL - 1 : l);
        s[r][tx] = src[((size_t)b*NL + l)*NC + c0 + tx];
    }
    __syncthreads();
    int base = tx + 16;
    float s17 = 0.f;
    #pragma unroll
    for (int j = -8; j <= 8; j++) s17 += s[base + j][ty];
    float s33 = s17;
    #pragma unroll
    for (int j = 9; j <= 16; j++) s33 += s[base - j][ty] + s[base + j][ty];
    float v = s[base][ty];
    size_t o = ((size_t)(b*NC + c0 + ty))*NL + l0 + tx;
    res[o] = v - s17 / 17.0f;
    res[(size_t)NB*NC*NL + o] = v - s33 / 33.0f;
}

// ---------------- fused prep ----------------
__global__ void prep_all(const float* __restrict__ mwt, float* __restrict__ Wm,
                         const float* __restrict__ tw0, float* __restrict__ W2a,
                         const float* __restrict__ tw1, float* __restrict__ W2b,
                         float* __restrict__ CM0, float* __restrict__ CM20,
                         float* __restrict__ CM1, float* __restrict__ CM21) {
    const double TWO_PI = 6.283185307179586476925286766559;
    const int tM = NC*NC*2;
    const int tA = NC*NC*12, tB = NC*NC*24;
    const int c0 = 85*169, c1 = 85*85, c2 = 43*85, c3 = 43*43;
    int total = tM + tA + tB + c0 + c1 + c2 + c3;
    for (int idx = blockIdx.x*blockDim.x + threadIdx.x; idx < total; idx += gridDim.x*blockDim.x) {
        int i = idx;
        if (i < tM) {
            int o = i / (NC*2);
            int rem = i - o*NC*2;
            int c = rem >> 1, n = rem & 1;
            Wm[((size_t)n*NC + c)*NC + o] = mwt[i];
            continue;
        }
        i -= tM;
        if (i < tA) {
            int cin = i / (NC*12);
            int r   = i - cin*(NC*12);
            W2a[(size_t)r*NC + cin] = tw0[i];
            continue;
        }
        i -= tA;
        if (i < tB) {
            int cin = i / (NC*24);
            int r   = i - cin*(NC*24);
            W2b[(size_t)r*NC + cin] = tw1[i];
            continue;
        }
        i -= tB;
        if (i < c0) {
            int t = i / 169, f = i - t*169;
            CM0[i] = (float)cos(TWO_PI * (double)((long long)f*(t + 84)) / 169.0);
            continue;
        }
        i -= c0;
        if (i < c1) {
            int f = i / 85, t = i - f*85;
            CM20[i] = (float)(cos(TWO_PI * (double)((long long)f*t) / 85.0) / 85.0);
            continue;
        }
        i -= c1;
        if (i < c2) {
            int t = i / 85, f = i - t*85;
            CM1[i] = (float)cos(TWO_PI * (double)((long long)f*(t + 42)) / 85.0);
            continue;
        }
        i -= c2;
        {
            int f = i / 43, t = i - f*43;
            CM21[i] = (float)(cos(TWO_PI * (double)((long long)f*t) / 43.0) / 43.0);
        }
    }
}

// ---------------- conv im2col materialization (coalesced writes) ----------------
template<int KK, int NE2>
__global__ void im2col_conv_k(const float* __restrict__ res, float* __restrict__ out, int pad) {
    int gk = blockIdx.x;
    int cin = gk / KK, t = gk - cin*KK;
    const int N = NB*NE2;
    const float* rbase = res + (size_t)cin*NL;
    float* obase = out + (size_t)gk*N;
    int tb = t - pad;
    for (int gn = threadIdx.x; gn < N; gn += blockDim.x) {
        int b = gn / NE2, q = gn - b*NE2;
        int s = (q >> 1)*KK + tb;
        float v = (s >= 0 && s < LH) ? rbase[(size_t)b*NC*NL + 2*s + (q & 1)] : 0.f;
        obase[gn] = v;
    }
}

// ---------------- x1: exp-gated interleave, drop last ----------------
__global__ void x1_kernel(const float* __restrict__ cv, float* __restrict__ x1, int m, int ne2) {
    size_t total = (size_t)NB*NC*m;
    for (size_t idx = (size_t)blockIdx.x*blockDim.x + threadIdx.x; idx < total;
         idx += (size_t)gridDim.x*blockDim.x) {
        int t = (int)(idx % m);
        size_t bc = idx / m;
        const float* c2 = cv + bc*ne2;
        x1[idx] = c2[t ^ 1] * expf(c2[t]);
    }
}

// ---------------- GEMM params ----------------
struct GemmP {
    const float* A; int lda;
    const float* Bp; int ldb; long long sBb;
    float* D; long long sDb; int ldd;
    const float* bias;
    int M, N, K;
    int npos;
    int pad, lhalf, inner;
    int kt, mklen;
    float* part;
};

__device__ __forceinline__ uint32_t f2tf32(float v) {
    uint32_t u;
    asm("cvt.rna.tf32.f32 %0, %1;" : "=r"(u) : "f"(v));
    return u;
}
__device__ __forceinline__ void mma_tf32(float c[4], const uint32_t a[4], const uint32_t b[2]) {
    asm("mma.sync.aligned.m16n8k8.row.col.f32.tf32.tf32.f32 "
        "{%0,%1,%2,%3},{%4,%5,%6,%7},{%8,%9},{%0,%1,%2,%3};"
        : "+f"(c[0]), "+f"(c[1]), "+f"(c[2]), "+f"(c[3])
        : "r"(a[0]), "r"(a[1]), "r"(a[2]), "r"(a[3]), "r"(b[0]), "r"(b[1]));
}

template<int BMODE, int KK>
__device__ __forceinline__ float ldB(const GemmP& p, const float* bbase, int gk) {
    if (gk >= p.K) return 0.f;
    if (BMODE == 0) return bbase[(long long)gk * p.ldb];
    int cin = gk / KK, t = gk - cin*KK;
    return bbase[(long long)cin*p.inner + t];
}

// tf32 mma.sync GEMM: BM=128, BN in {64,128}, BK=32.
// A: row-major padded smem [128][36] — coalesced float4 fill, conflict-free
//    STS.128 (each 8-lane phase = one row) and conflict-free LDS.32 fragment
//    gather (bank = 4r+c, all lanes distinct).
// B: fragment-major gather fills (R10 layout, conflict-free).
// KALIGN=1: K multiple of 32 and 16B-aligned A rows -> unguarded float4 fills.
// BMODE: 0 dense, 2 iso-im2col (KK: conv kernel size)
// BIASM: 0 none, 1 per-row, 2 per-col(q), 3 bias[row/kt]
// ACT: 0 none, 1 tanh, 2 relu.  SMODE: 0 normal, 1 transconv scatter.
// SPLITK>1: raw partials to p.part; epilogue by reduce kernel.  M % 128 == 0.
template<int BN, int BMODE, int KK, int KALIGN, int BIASM, int ACT, int SMODE, int SPLITK>
__global__ void __launch_bounds__(256, (BN == 64) ? 2 : 1)
gemm_k(GemmP p) {
    constexpr int BM = 128, BK = 32;
    constexpr int LDA_S = 36;            // padded row stride (floats)
    constexpr int WR = 4, WC = 2;
    constexpr int WN = BN/WC, NF = WN/8;
    constexpr int BRP = BN/32;
    constexpr int ASZ = BM*LDA_S, BSZ = BK*BN;
    extern __shared__ float dyn[];
    float* As = dyn;
    float* Bs = dyn + 2*ASZ;

    const int tid = threadIdx.x, lane = tid & 31, warp = tid >> 5;
    const int wr = warp % WR, wc = warp / WR;
    const int m0 = blockIdx.y * BM, n0 = blockIdx.x * BN;

    int kbeg = 0, kend = p.K;
    if (SPLITK > 1) {
        int kc = ((p.K + SPLITK*BK - 1) / (SPLITK*BK)) * BK;
        kbeg = blockIdx.z * kc;
        kend = min(kbeg + kc, p.K);
    }

    // ---- A row-major fill setup: thread t -> row (t>>3)+32g, k4 (t&7)*4 ----
    const int ar_ = tid >> 3, ak4 = (tid & 7) * 4;
    const float* arow[4];
    int astore[4];
    #pragma unroll
    for (int g = 0; g < 4; g++) {
        arow[g]   = p.A + (long long)(m0 + ar_ + 32*g) * p.lda;
        astore[g] = (ar_ + 32*g)*LDA_S + ak4;
    }
    // ---- B gather-fill setup: warp -> (kc, cbase); lane+32rp -> n ----
    const int bkl0 = (warp >> 1)*8 + (warp & 1)*2;
    const float* bb_r[BRP];
    int bstore[BRP];
    bool nv_r[BRP];
    #pragma unroll
    for (int rp = 0; rp < BRP; rp++) {
        int ln = lane + 32*rp;
        int gn = n0 + ln;
        nv_r[rp] = gn < p.N;
        int g = nv_r[rp] ? gn : 0;
        int b = 0, q = g;
        if (!(BMODE == 0 && p.sBb == 0)) { b = g / p.npos; q = g - b*p.npos; }
        bb_r[rp] = p.Bp + b*p.sBb + q;
        int fb = (warp >> 1)*(BN/8) + (ln >> 3);
        int X = (ln & 7)*4 + (warp & 1)*2;
        X ^= ((X >> 4) & 1) << 1;
        bstore[rp] = fb*64 + X*2;
    }
    const int physl = lane ^ (((lane >> 4) & 1) << 1);

    // A compute-load bases (row-major): row = wr*32 + mi*16 + (lane>>2), col kc*8 + (lane&3)
    const int arow_c = wr*32 + (lane >> 2);
    const int acol_c = lane & 3;

    float acc[2][NF][4];
    #pragma unroll
    for (int mi = 0; mi < 2; mi++)
        #pragma unroll
        for (int ni = 0; ni < NF; ni++)
            #pragma unroll
            for (int e = 0; e < 4; e++) acc[mi][ni][e] = 0.f;

    float ra[4][4], rb[BRP][4];
    // ---- prologue: fill tile kbeg ----
    #pragma unroll
    for (int g = 0; g < 4; g++) {
        if (KALIGN) {
            float4 v = *(const float4*)&arow[g][kbeg + ak4];
            ra[g][0] = v.x; ra[g][1] = v.y; ra[g][2] = v.z; ra[g][3] = v.w;
        } else {
            #pragma unroll
            for (int j = 0; j < 4; j++) {
                int gk = kbeg + ak4 + j;
                ra[g][j] = (gk < p.K) ? arow[g][gk] : 0.f;
            }
        }
    }
    #pragma unroll
    for (int rp = 0; rp < BRP; rp++) {
        rb[rp][0] = nv_r[rp] ? ldB<BMODE,KK>(p, bb_r[rp], kbeg + bkl0)     : 0.f;
        rb[rp][1] = nv_r[rp] ? ldB<BMODE,KK>(p, bb_r[rp], kbeg + bkl0 + 4) : 0.f;
        rb[rp][2] = nv_r[rp] ? ldB<BMODE,KK>(p, bb_r[rp], kbeg + bkl0 + 1) : 0.f;
        rb[rp][3] = nv_r[rp] ? ldB<BMODE,KK>(p, bb_r[rp], kbeg + bkl0 + 5) : 0.f;
    }
    #pragma unroll
    for (int g = 0; g < 4; g++) {
        float4 v;
        v.x = __uint_as_float(f2tf32(ra[g][0]));
        v.y = __uint_as_float(f2tf32(ra[g][1]));
        v.z = __uint_as_float(f2tf32(ra[g][2]));
        v.w = __uint_as_float(f2tf32(ra[g][3]));
        *(float4*)&As[astore[g]] = v;
    }
    #pragma unroll
    for (int rp = 0; rp < BRP; rp++) {
        float4 v;
        v.x = __uint_as_float(f2tf32(rb[rp][0]));
        v.y = __uint_as_float(f2tf32(rb[rp][1]));
        v.z = __uint_as_float(f2tf32(rb[rp][2]));
        v.w = __uint_as_float(f2tf32(rb[rp][3]));
        *(float4*)&Bs[bstore[rp]] = v;
    }
    __syncthreads();

    int buf = 0;
    for (int k0 = kbeg; k0 < kend; k0 += BK) {
        int kn = k0 + BK;
        bool more = kn < kend;
        if (more) {
            #pragma unroll
            for (int g = 0; g < 4; g++) {
                if (KALIGN) {
                    float4 v = *(const float4*)&arow[g][kn + ak4];
                    ra[g][0] = v.x; ra[g][1] = v.y; ra[g][2] = v.z; ra[g][3] = v.w;
                } else {
                    #pragma unroll
                    for (int j = 0; j < 4; j++) {
                        int gk = kn + ak4 + j;
                        ra[g][j] = (gk < p.K) ? arow[g][gk] : 0.f;
                    }
                }
            }
            #pragma unroll
            for (int rp = 0; rp < BRP; rp++) {
                rb[rp][0] = nv_r[rp] ? ldB<BMODE,KK>(p, bb_r[rp], kn + bkl0)     : 0.f;
                rb[rp][1] = nv_r[rp] ? ldB<BMODE,KK>(p, bb_r[rp], kn + bkl0 + 4) : 0.f;
                rb[rp][2] = nv_r[rp] ? ldB<BMODE,KK>(p, bb_r[rp], kn + bkl0 + 1) : 0.f;
                rb[rp][3] = nv_r[rp] ? ldB<BMODE,KK>(p, bb_r[rp], kn + bkl0 + 5) : 0.f;
            }
        }
        const float* Ac = As + buf*ASZ;
        const float* Bc = Bs + buf*BSZ;
        #pragma unroll
        for (int kc = 0; kc < 4; kc++) {
            uint32_t af[2][4];
            #pragma unroll
            for (int mi = 0; mi < 2; mi++) {
                int rb_ = (arow_c + mi*16)*LDA_S + kc*8 + acol_c;
                af[mi][0] = __float_as_uint(Ac[rb_]);
                af[mi][1] = __float_as_uint(Ac[rb_ + 8*LDA_S]);
                af[mi][2] = __float_as_uint(Ac[rb_ + 4]);
                af[mi][3] = __float_as_uint(Ac[rb_ + 8*LDA_S + 4]);
            }
            uint32_t bf[NF][2];
            #pragma unroll
            for (int ni = 0; ni < NF; ni++) {
                const float2 bv = *(const float2*)&Bc[(kc*(BN/8) + wc*NF + ni)*64 + physl*2];
                bf[ni][0] = __float_as_uint(bv.x);
                bf[ni][1] = __float_as_uint(bv.y);
            }
            #pragma unroll
            for (int mi = 0; mi < 2; mi++)
                #pragma unroll
                for (int ni = 0; ni < NF; ni++)
                    mma_tf32(acc[mi][ni], af[mi], bf[ni]);
        }
        if (more) {
            float* An = As + (buf^1)*ASZ;
            float* Bn = Bs + (buf^1)*BSZ;
            #pragma unroll
            for (int g = 0; g < 4; g++) {
                float4 v;
                v.x = __uint_as_float(f2tf32(ra[g][0]));
                v.y = __uint_as_float(f2tf32(ra[g][1]));
                v.z = __uint_as_float(f2tf32(ra[g][2]));
                v.w = __uint_as_float(f2tf32(ra[g][3]));
                *(float4*)&An[astore[g]] = v;
            }
            #pragma unroll
            for (int rp = 0; rp < BRP; rp++) {
                float4 v;
                v.x = __uint_as_float(f2tf32(rb[rp][0]));
                v.y = __uint_as_float(f2tf32(rb[rp][1]));
                v.z = __uint_as_float(f2tf32(rb[rp][2]));
                v.w = __uint_as_float(f2tf32(rb[rp][3]));
                *(float4*)&Bn[bstore[rp]] = v;
            }
        }
        __syncthreads();
        buf ^= 1;
    }

    // ---- epilogue ----
    if (SPLITK > 1) {
        float* pd = p.part + (size_t)blockIdx.z * ((size_t)p.M * p.N);
        #pragma unroll
        for (int mi = 0; mi < 2; mi++)
            #pragma unroll
            for (int half = 0; half < 2; half++) {
                int row = m0 + wr*32 + mi*16 + (lane >> 2) + half*8;
                #pragma unroll
                for (int ni = 0; ni < NF; ni++)
                    #pragma unroll
                    for (int e = 0; e < 2; e++) {
                        int gn = n0 + wc*WN + ni*8 + (lane & 3)*2 + e;
                        if (gn < p.N)
                            pd[(size_t)row*p.N + gn] = acc[mi][ni][half*2 + e];
                    }
            }
        return;
    }
    #pragma unroll
    for (int mi = 0; mi < 2; mi++) {
        #pragma unroll
        for (int half = 0; half < 2; half++) {
            int row = m0 + wr*32 + mi*16 + (lane >> 2) + half*8;
            float brow = 0.f;
            if (BIASM == 1) brow = p.bias[row];
            else if (BIASM == 3) brow = p.bias[row / p.kt];
            int cout = 0, jj = 0;
            if (SMODE == 1) { cout = row / p.kt; jj = row - cout*p.kt; }
            #pragma unroll
            for (int ni = 0; ni < NF; ni++) {
                #pragma unroll
                for (int e = 0; e < 2; e++) {
                    int gn = n0 + wc*WN + ni*8 + (lane & 3)*2 + e;
                    if (gn >= p.N) continue;
                    int b, q;
                    if (SMODE == 0 && p.sDb == 0) { b = 0; q = gn; }
                    else { b = gn / p.npos; q = gn - b*p.npos; }
                    float v = acc[mi][ni][half*2 + e] + brow;
                    if (BIASM == 2) v += p.bias[q];
                    if (ACT == 1) v = tanhf(v);
                    else if (ACT == 2) v = fmaxf(v, 0.f);
                    long long addr;
                    if (SMODE == 0) addr = b*p.sDb + (long long)row*p.ldd + q;
                    else addr = b*p.sDb + (long long)cout*p.mklen + (long long)q*p.kt + jj;
                    p.D[addr] = v;
                }
            }
        }
    }
}

// ---------------- split-K reduce + bias + tanh + batched store ----------------
__global__ void reduce_ep_k(const float* __restrict__ part, float* __restrict__ D,
                            const float* __restrict__ bias,
                            int S, int M, int N, long long sDb, int ldd, int npos) {
    int idx = blockIdx.x*blockDim.x + threadIdx.x;
    if (idx >= M*N) return;
    int row = idx / N, gn = idx - row*N;
    size_t st = (size_t)M*N;
    float v = 0.f;
    for (int z = 0; z < S; z++) v += part[(size_t)z*st + idx];
    v = tanhf(v + bias[row]);
    int b = gn / npos, q = gn - b*npos;
    D[b*sDb + (long long)row*ldd + q] = v;
}

// ---------------- block reduce + layer norms ----------
__device__ __forceinline__ float blk_sum(float v) {
    __shared__ float sb[8];
    #pragma unroll
    for (int o = 16; o; o >>= 1) v += __shfl_xor_sync(0xffffffffu, v, o);
    if ((threadIdx.x & 31) == 0) sb[threadIdx.x >> 5] = v;
    __syncthreads();
    float t = 0.f;
    #pragma unroll
    for (int i = 0; i < 8; i++) t += sb[i];
    __syncthreads();
    return t;
}

__global__ void ln1_kernel(const float* __restrict__ xr, const float* __restrict__ x1,
                           const float* __restrict__ g, const float* __restrict__ bt,
                           float* __restrict__ out, int m) {
    int row = blockIdx.x;
    int b = row / m, t = row - b*m;
    int tid = threadIdx.x;
    size_t base = (size_t)b*NC*m + t;
    float v0 = xr[base + (size_t)tid*m]       + x1[base + (size_t)tid*m];
    float v1 = xr[base + (size_t)(tid+256)*m] + x1[base + (size_t)(tid+256)*m];
    float mu = blk_sum(v0 + v1) * (1.f/NC);
    float d0 = v0 - mu, d1 = v1 - mu;
    float var = blk_sum(d0*d0 + d1*d1) * (1.f/NC);
    float inv = rsqrtf(var + 1e-5f);
    out[base + (size_t)tid*m]       = d0*inv*g[tid]     + bt[tid];
    out[base + (size_t)(tid+256)*m] = d1*inv*g[tid+256] + bt[tid+256];
}

__global__ void branch_out_kernel(const float* __restrict__ y2, const float* __restrict__ resn,
                                  const float* __restrict__ g, const float* __restrict__ bt,
                                  float* __restrict__ br, int mk, int nbr) {
    int row = blockIdx.x;
    int b = row >> 10, l = row & 1023;
    int li = (l * mk) >> 10;
    int tid = threadIdx.x;
    size_t yb = (size_t)b*NC*mk + li;
    size_t rb = (size_t)b*NC*NL + l;
    float v0 = y2[yb + (size_t)tid*mk]       + resn[rb + (size_t)tid*NL];
    float v1 = y2[yb + (size_t)(tid+256)*mk] + resn[rb + (size_t)(tid+256)*NL];
    float mu = blk_sum(v0 + v1) * (1.f/NC);
    float d0 = v0 - mu, d1 = v1 - mu;
    float var = blk_sum(d0*d0 + d1*d1) * (1.f/NC);
    float inv = rsqrtf(var + 1e-5f);
    float* o = br + (size_t)row*(2*NC) + nbr*NC;
    o[tid]     = d0*inv*g[tid]     + bt[tid];
    o[tid+256] = d1*inv*g[tid+256] + bt[tid+256];
}

__global__ void final_ln_kernel(const float* __restrict__ mg, const float* __restrict__ h2,
                                const float* __restrict__ g, const float* __restrict__ bt,
                                float* __restrict__ out) {
    int row = blockIdx.x;
    int tid = threadIdx.x;
    size_t base = (size_t)row*NC;
    float v0 = mg[base + tid]       + h2[base + tid];
    float v1 = mg[base + tid + 256] + h2[base + tid + 256];
    float mu = blk_sum(v0 + v1) * (1.f/NC);
    float d0 = v0 - mu, d1 = v1 - mu;
    float var = blk_sum(d0*d0 + d1*d1) * (1.f/NC);
    float inv = rsqrtf(var + 1e-5f);
    out[base + tid]       = d0*inv*g[tid]     + bt[tid];
    out[base + tid + 256] = d1*inv*g[tid+256] + bt[tid+256];
}

template<int BN, int SPLITK>
static inline dim3 gg(int M, int N) { return dim3((N + BN - 1)/BN, M/128, SPLITK); }

template<int BN, int BMODE, int KK, int KALIGN, int BIASM, int ACT, int SMODE, int SPLITK = 1>
static void launch_gemm(const GemmP& p) {
    constexpr int SMEM = 2*(128*36 + 32*BN)*4;
    cudaFuncSetAttribute((const void*)gemm_k<BN,BMODE,KK,KALIGN,BIASM,ACT,SMODE,SPLITK>,
                         cudaFuncAttributeMaxDynamicSharedMemorySize, SMEM);
    gemm_k<BN,BMODE,KK,KALIGN,BIASM,ACT,SMODE,SPLITK><<<gg<BN,SPLITK>(p.M, p.N), 256, SMEM>>>(p);
}

extern "C" void kernel_launch(void* const* d_in, const int* in_sizes, int n_in,
                              void* d_out, int out_size) {
    (void)in_sizes; (void)n_in; (void)out_size;
    const float* src   = (const float*)d_in[0];
    const float* cw[2] = {(const float*)d_in[1],  (const float*)d_in[7]};
    const float* cb[2] = {(const float*)d_in[2],  (const float*)d_in[8]};
    const float* iw[2] = {(const float*)d_in[3],  (const float*)d_in[9]};
    const float* ib[2] = {(const float*)d_in[4],  (const float*)d_in[10]};
    const float* tw[2] = {(const float*)d_in[5],  (const float*)d_in[11]};
    const float* tb[2] = {(const float*)d_in[6],  (const float*)d_in[12]};
    const float* mw  = (const float*)d_in[13];
    const float* mb  = (const float*)d_in[14];
    const float* ng  = (const float*)d_in[15];
    const float* nb  = (const float*)d_in[16];
    const float* fw1 = (const float*)d_in[17];
    const float* fb1 = (const float*)d_in[18];
    const float* fw2 = (const float*)d_in[19];
    const float* fb2 = (const float*)d_in[20];
    const float* fng = (const float*)d_in[21];
    const float* fnb = (const float*)d_in[22];
    float* out = (float*)d_out;

    float *p_res,*p_cv,*p_x1,*p_xf,*p_xi,*p_xr,*p_yln,*p_y2,*p_br,*p_mg,*p_h1,*p_h2;
    float *p_W2a,*p_W2b,*p_Wm,*p_CM0,*p_CM20,*p_CM1,*p_CM21,*p_part,*p_im;
    cudaGetSymbolAddress((void**)&p_res, g_res);
    cudaGetSymbolAddress((void**)&p_cv,  g_cv);
    cudaGetSymbolAddress((void**)&p_x1,  g_x1);
    cudaGetSymbolAddress((void**)&p_xf,  g_xf);
    cudaGetSymbolAddress((void**)&p_xi,  g_xi);
    cudaGetSymbolAddress((void**)&p_xr,  g_xr);
    cudaGetSymbolAddress((void**)&p_yln, g_yln);
    cudaGetSymbolAddress((void**)&p_y2,  g_y2);
    cudaGetSymbolAddress((void**)&p_br,  g_br);
    cudaGetSymbolAddress((void**)&p_mg,  g_mg);
    cudaGetSymbolAddress((void**)&p_h1,  g_h1);
    cudaGetSymbolAddress((void**)&p_h2,  g_h2);
    cudaGetSymbolAddress((void**)&p_W2a, g_W2a);
    cudaGetSymbolAddress((void**)&p_W2b, g_W2b);
    cudaGetSymbolAddress((void**)&p_Wm,  g_Wm);
    cudaGetSymbolAddress((void**)&p_CM0, g_CM0);
    cudaGetSymbolAddress((void**)&p_CM20,g_CM20);
    cudaGetSymbolAddress((void**)&p_CM1, g_CM1);
    cudaGetSymbolAddress((void**)&p_CM21,g_CM21);
    cudaGetSymbolAddress((void**)&p_part,g_part);
    cudaGetSymbolAddress((void**)&p_im,  g_im);

    const int Kk[2] = {12, 24}, NE[2] = {43, 22},
              MM[2] = {85, 43}, N2_[2] = {169, 85}, MKl[2] = {1020, 1032};
    float* CMv[2]  = {p_CM0, p_CM1};
    float* CM2v[2] = {p_CM20, p_CM21};
    float* W2v[2]  = {p_W2a, p_W2b};
    float* cpart[2] = {p_part, p_part + (size_t)6*1024*1024};

    decomp_kernel<<<dim3(NL/32, NC/32, NB), dim3(32, 32)>>>(src, p_res);
    prep_all<<<2048, 256>>>(mw, p_Wm, tw[0], p_W2a, tw[1], p_W2b,
                            p_CM0, p_CM20, p_CM1, p_CM21);

    // conv via materialized im2col + dense split-K GEMM
    for (int n = 0; n < 2; n++) {
        int k = Kk[n], ne2 = 2*NE[n];
        int Nn = NB*ne2;
        if (n == 0) im2col_conv_k<12,86><<<NC*12, 256>>>(p_res, p_im, 6);
        else        im2col_conv_k<24,44><<<NC*24, 256>>>(p_res + (size_t)NB*NC*NL, p_im, 12);
        GemmP p{};
        p.A = cw[n]; p.lda = NC*k;
        p.Bp = p_im; p.ldb = Nn; p.sBb = 0;
        p.part = cpart[n];
        p.bias = cb[n];
        p.M = NC; p.N = Nn; p.K = NC*k; p.npos = ne2;
        if (n == 0) launch_gemm<64,0,1,1,1,1,0,4>(p);
        else        launch_gemm<64,0,1,1,1,1,0,8>(p);
        reduce_ep_k<<<(NC*Nn + 255)/256, 256>>>(cpart[n], p_cv + (size_t)n*NB*NC*86, cb[n],
                                                (n == 0) ? 4 : 8, NC, Nn,
                                                (long long)NC*ne2, ne2, ne2);
    }

    for (int n = 0; n < 2; n++) {
        int k = Kk[n], m = MM[n], N2 = N2_[n], mk = MKl[n];
        int ne2 = 2*NE[n];

        x1_kernel<<<1024, 256>>>(p_cv + (size_t)n*NB*NC*86, p_x1, m, ne2);
        { // real-DFT (ragged K -> guarded scalar A fills)
            GemmP p{};
            p.A = p_x1; p.lda = m;
            p.Bp = CMv[n]; p.ldb = N2; p.sBb = 0;
            p.D = p_xf; p.sDb = 0; p.ldd = N2;
            p.M = NB*NC; p.N = N2; p.K = m; p.npos = N2;
            launch_gemm<64,0,1,0,0,0,0>(p);
        }
        { // isometric conv (valid), tanh — split-K
            GemmP p{};
            p.A = iw[n]; p.lda = NC*m;
            p.Bp = p_xf; p.sBb = (long long)NC*N2; p.inner = N2;
            p.part = p_part;
            p.bias = ib[n];
            p.M = NC; p.N = NB*m; p.K = NC*m; p.npos = m;
            if (n == 0) launch_gemm<64,2,85,1,1,1,0,8>(p);
            else        launch_gemm<64,2,43,1,1,1,0,8>(p);
            reduce_ep_k<<<(NC*NB*m + 255)/256, 256>>>(p_part, p_xi, ib[n],
                                                      8, NC, NB*m,
                                                      (long long)NC*m, m, m);
        }
        { // real-IDFT (ragged K)
            GemmP p{};
            p.A = p_xi; p.lda = m;
            p.Bp = CM2v[n]; p.ldb = m; p.sBb = 0;
            p.D = p_xr; p.sDb = 0; p.ldd = m;
            p.M = NB*NC; p.N = m; p.K = m; p.npos = m;
            launch_gemm<64,0,1,0,0,0,0>(p);
        }
        ln1_kernel<<<NB*m, 256>>>(p_xr, p_x1, ng, nb, p_yln, m);
        { // conv-transpose (stride==kernel), tanh, scatter store
            GemmP p{};
            p.A = W2v[n]; p.lda = NC;
            p.Bp = p_yln; p.ldb = m; p.sBb = (long long)NC*m;
            p.D = p_y2; p.sDb = (long long)NC*mk; p.kt = k; p.mklen = mk;
            p.bias = tb[n];
            p.M = NC*k; p.N = NB*m; p.K = NC; p.npos = m;
            launch_gemm<128,0,1,1,3,1,1>(p);
        }
        branch_out_kernel<<<NB*NL, 256>>>(p_y2, p_res + (size_t)n*NB*NC*NL, ng, nb, p_br, mk, n);
    }
    { // merge
        GemmP p{};
        p.A = p_br; p.lda = 2*NC;
        p.Bp = p_Wm; p.ldb = NC; p.sBb = 0;
        p.D = p_mg; p.sDb = 0; p.ldd = NC;
        p.bias = mb;
        p.M = NB*NL; p.N = NC; p.K = 2*NC; p.npos = NC;
        launch_gemm<128,0,1,1,2,0,0>(p);
    }
    { // FFN layer 1 (relu)
        GemmP p{};
        p.A = p_mg; p.lda = NC;
        p.Bp = fw1; p.ldb = 4*NC; p.sBb = 0;
        p.D = p_h1; p.sDb = 0; p.ldd = 4*NC;
        p.bias = fb1;
        p.M = NB*NL; p.N = 4*NC; p.K = NC; p.npos = 4*NC;
        launch_gemm<128,0,1,1,2,2,0>(p);
    }
    { // FFN layer 2
        GemmP p{};
        p.A = p_h1; p.lda = 4*NC;
        p.Bp = fw2; p.ldb = NC; p.sBb = 0;
        p.D = p_h2; p.sDb = 0; p.ldd = NC;
        p.bias = fb2;
        p.M = NB*NL; p.N = NC; p.K = 4*NC; p.npos = NC;
        launch_gemm<128,0,1,1,2,0,0>(p);
    }
    final_ln_kernel<<<NB*NL, 256>>>(p_mg, p_h2, fng, fnb, out);
}

// round 13
// speedup vs baseline: 2.1198x; 1.0943x over previous
#include <cuda_runtime.h>
#include <math.h>
#include <stdint.h>

#define NB 32
#define NL 1024
#define NC 512
#define LH 512   // L/2

// ---------------- scratch (device globals; no allocations) ----------------
__device__ float g_res[(size_t)2*NB*NC*NL];
__device__ float g_cv [(size_t)2*NB*NC*86];
__device__ float g_x1 [(size_t)NB*NC*85];
__device__ float g_xf [(size_t)NB*NC*169];
__device__ float g_xi [(size_t)NB*NC*85];
__device__ float g_xr [(size_t)NB*NC*85];
__device__ float g_yln[(size_t)NB*NC*85];
__device__ float g_y2 [(size_t)NB*NC*1032];
__device__ float g_br [(size_t)NB*NL*2*NC];
__device__ float g_mg [(size_t)NB*NL*NC];
__device__ float g_h1 [(size_t)NB*NL*4*NC];
__device__ float g_h2 [(size_t)NB*NL*NC];
__device__ float g_W2a[(size_t)NC*12*NC];
__device__ float g_W2b[(size_t)NC*24*NC];
__device__ float g_Wm [(size_t)2*NC*NC];
__device__ float g_CM0 [85*169];
__device__ float g_CM20[85*85];
__device__ float g_CM1 [43*85];
__device__ float g_CM21[43*43];
__device__ float g_part[(size_t)12*1024*1024];
__device__ float g_im [(size_t)18*1024*1024];

// ---------------- series decomp ----------------
__global__ void decomp_kernel(const float* __restrict__ src, float* __restrict__ res) {
    __shared__ float s[64][33];
    int b = blockIdx.z;
    int c0 = blockIdx.y * 32;
    int l0 = blockIdx.x * 32;
    int tx = threadIdx.x, ty = threadIdx.y;
    for (int r = ty; r < 64; r += 32) {
        int l = l0 - 16 + r;
        l = l < 0 ? 0 : (l > NL - 1 ? NL - 1 : l);
        s[r][tx] = src[((size_t)b*NL + l)*NC + c0 + tx];
    }
    __syncthreads();
    int base = tx + 16;
    float s17 = 0.f;
    #pragma unroll
    for (int j = -8; j <= 8; j++) s17 += s[base + j][ty];
    float s33 = s17;
    #pragma unroll
    for (int j = 9; j <= 16; j++) s33 += s[base - j][ty] + s[base + j][ty];
    float v = s[base][ty];
    size_t o = ((size_t)(b*NC + c0 + ty))*NL + l0 + tx;
    res[o] = v - s17 / 17.0f;
    res[(size_t)NB*NC*NL + o] = v - s33 / 33.0f;
}

// ---------------- fused prep ----------------
__global__ void prep_all(const float* __restrict__ mwt, float* __restrict__ Wm,
                         const float* __restrict__ tw0, float* __restrict__ W2a,
                         const float* __restrict__ tw1, float* __restrict__ W2b,
                         float* __restrict__ CM0, float* __restrict__ CM20,
                         float* __restrict__ CM1, float* __restrict__ CM21) {
    const double TWO_PI = 6.283185307179586476925286766559;
    const int tM = NC*NC*2;
    const int tA = NC*NC*12, tB = NC*NC*24;
    const int c0 = 85*169, c1 = 85*85, c2 = 43*85, c3 = 43*43;
    int total = tM + tA + tB + c0 + c1 + c2 + c3;
    for (int idx = blockIdx.x*blockDim.x + threadIdx.x; idx < total; idx += gridDim.x*blockDim.x) {
        int i = idx;
        if (i < tM) {
            int o = i / (NC*2);
            int rem = i - o*NC*2;
            int c = rem >> 1, n = rem & 1;
            Wm[((size_t)n*NC + c)*NC + o] = mwt[i];
            continue;
        }
        i -= tM;
        if (i < tA) {
            int cin = i / (NC*12);
            int r   = i - cin*(NC*12);
            W2a[(size_t)r*NC + cin] = tw0[i];
            continue;
        }
        i -= tA;
        if (i < tB) {
            int cin = i / (NC*24);
            int r   = i - cin*(NC*24);
            W2b[(size_t)r*NC + cin] = tw1[i];
            continue;
        }
        i -= tB;
        if (i < c0) {
            int t = i / 169, f = i - t*169;
            CM0[i] = (float)cos(TWO_PI * (double)((long long)f*(t + 84)) / 169.0);
            continue;
        }
        i -= c0;
        if (i < c1) {
            int f = i / 85, t = i - f*85;
            CM20[i] = (float)(cos(TWO_PI * (double)((long long)f*t) / 85.0) / 85.0);
            continue;
        }
        i -= c1;
        if (i < c2) {
            int t = i / 85, f = i - t*85;
            CM1[i] = (float)cos(TWO_PI * (double)((long long)f*(t + 42)) / 85.0);
            continue;
        }
        i -= c2;
        {
            int f = i / 43, t = i - f*43;
            CM21[i] = (float)(cos(TWO_PI * (double)((long long)f*t) / 43.0) / 43.0);
        }
    }
}

// ---------------- conv im2col materialization ----------------
template<int KK, int NE2>
__global__ void im2col_conv_k(const float* __restrict__ res, float* __restrict__ out, int pad) {
    int gk = blockIdx.x;
    int cin = gk / KK, t = gk - cin*KK;
    const int N = NB*NE2;
    const float* rbase = res + (size_t)cin*NL;
    float* obase = out + (size_t)gk*N;
    int tb = t - pad;
    for (int gn = threadIdx.x; gn < N; gn += blockDim.x) {
        int b = gn / NE2, q = gn - b*NE2;
        int s = (q >> 1)*KK + tb;
        float v = (s >= 0 && s < LH) ? rbase[(size_t)b*NC*NL + 2*s + (q & 1)] : 0.f;
        obase[gn] = v;
    }
}

// ---------------- x1: exp-gated interleave ----------------
__global__ void x1_kernel(const float* __restrict__ cv, float* __restrict__ x1, int m, int ne2) {
    size_t total = (size_t)NB*NC*m;
    for (size_t idx = (size_t)blockIdx.x*blockDim.x + threadIdx.x; idx < total;
         idx += (size_t)gridDim.x*blockDim.x) {
        int t = (int)(idx % m);
        size_t bc = idx / m;
        const float* c2 = cv + bc*ne2;
        x1[idx] = c2[t ^ 1] * expf(c2[t]);
    }
}

// ---------------- GEMM params ----------------
struct GemmP {
    const float* A; int lda;
    const float* Bp; int ldb; long long sBb;
    float* D; long long sDb; int ldd;
    const float* bias;
    int M, N, K;
    int npos;
    int pad, lhalf, inner;
    int kt, mklen;
    float* part;
};

__device__ __forceinline__ uint32_t f2tf32(float v) {
    uint32_t u;
    asm("cvt.rna.tf32.f32 %0, %1;" : "=r"(u) : "f"(v));
    return u;
}
__device__ __forceinline__ void mma_tf32(float c[4], const uint32_t a[4], const uint32_t b[2]) {
    asm("mma.sync.aligned.m16n8k8.row.col.f32.tf32.tf32.f32 "
        "{%0,%1,%2,%3},{%4,%5,%6,%7},{%8,%9},{%0,%1,%2,%3};"
        : "+f"(c[0]), "+f"(c[1]), "+f"(c[2]), "+f"(c[3])
        : "r"(a[0]), "r"(a[1]), "r"(a[2]), "r"(a[3]), "r"(b[0]), "r"(b[1]));
}

template<int BMODE, int KK>
__device__ __forceinline__ float ldB(const GemmP& p, const float* bbase, int gk) {
    if (gk >= p.K) return 0.f;
    if (BMODE == 0) return bbase[(long long)gk * p.ldb];
    int cin = gk / KK, t = gk - cin*KK;
    return bbase[(long long)cin*p.inner + t];
}

// tf32 mma.sync GEMM, BM=128.
// BN=64: BK=32 (R11 config). BN=128: BK=16, NF=8 (crossbar-balanced).
// A: row-major padded smem; B: fragment-major gather layout. Both conflict-free.
template<int BN, int BMODE, int KK, int KALIGN, int BIASM, int ACT, int SMODE, int SPLITK>
__global__ void __launch_bounds__(256, 2)
gemm_k(GemmP p) {
    constexpr int BM = 128;
    constexpr int BK = (BN == 64) ? 32 : 16;
    constexpr int LDA_S = BK + 4;
    constexpr int WR = 4, WC = 2;
    constexpr int WN = BN/WC, NF = WN/8;
    constexpr int AG = BK/8;              // A fill float4 groups (4 or 2)
    constexpr int ROWSTEP = 1024/BK;      // 32 or 64
    constexpr int ASZ = BM*LDA_S, BSZ = BK*BN;
    extern __shared__ float dyn[];
    float* As = dyn;
    float* Bs = dyn + 2*ASZ;

    const int tid = threadIdx.x, lane = tid & 31, warp = tid >> 5;
    const int wr = warp % WR, wc = warp / WR;
    const int m0 = blockIdx.y * BM, n0 = blockIdx.x * BN;

    int kbeg = 0, kend = p.K;
    if (SPLITK > 1) {
        int kc = ((p.K + SPLITK*BK - 1) / (SPLITK*BK)) * BK;
        kbeg = blockIdx.z * kc;
        kend = min(kbeg + kc, p.K);
    }

    // ---- A row-major fill: thread -> row ar_+ROWSTEP*g, cols ak4..ak4+3 ----
    const int ar_ = tid / (BK/4);
    const int ak4 = (tid & (BK/4 - 1)) * 4;
    const float* arow[AG];
    int astore[AG];
    #pragma unroll
    for (int g = 0; g < AG; g++) {
        arow[g]   = p.A + (long long)(m0 + ar_ + ROWSTEP*g) * p.lda;
        astore[g] = (ar_ + ROWSTEP*g)*LDA_S + ak4;
    }
    // ---- B gather fill: warp -> (kc, cbase[, nhalf]); BRP=2 ----
    int kcw, cbw, nh;
    if (BK == 32) { kcw = warp >> 1; cbw = warp & 1; nh = 0; }
    else          { kcw = warp >> 2; cbw = (warp >> 1) & 1; nh = warp & 1; }
    const int bkl0 = kcw*8 + cbw*2;
    const float* bb_r[2];
    int bstore[2];
    bool nv_r[2];
    #pragma unroll
    for (int rp = 0; rp < 2; rp++) {
        int ln = (BK == 32) ? (lane + 32*rp) : (nh*64 + rp*32 + lane);
        int gn = n0 + ln;
        nv_r[rp] = gn < p.N;
        int g = nv_r[rp] ? gn : 0;
        int b = 0, q = g;
        if (!(BMODE == 0 && p.sBb == 0)) { b = g / p.npos; q = g - b*p.npos; }
        bb_r[rp] = p.Bp + b*p.sBb + q;
        int fb = kcw*(BN/8) + (ln >> 3);
        int X = (ln & 7)*4 + cbw*2;
        X ^= ((X >> 4) & 1) << 1;
        bstore[rp] = fb*64 + X*2;
    }
    const int physl = lane ^ (((lane >> 4) & 1) << 1);
    const int arow_c = wr*32 + (lane >> 2);
    const int acol_c = lane & 3;

    float acc[2][NF][4];
    #pragma unroll
    for (int mi = 0; mi < 2; mi++)
        #pragma unroll
        for (int ni = 0; ni < NF; ni++)
            #pragma unroll
            for (int e = 0; e < 4; e++) acc[mi][ni][e] = 0.f;

    float ra[AG][4], rb[2][4];
    // ---- prologue ----
    #pragma unroll
    for (int g = 0; g < AG; g++) {
        if (KALIGN) {
            float4 v = *(const float4*)&arow[g][kbeg + ak4];
            ra[g][0] = v.x; ra[g][1] = v.y; ra[g][2] = v.z; ra[g][3] = v.w;
        } else {
            #pragma unroll
            for (int j = 0; j < 4; j++) {
                int gk = kbeg + ak4 + j;
                ra[g][j] = (gk < p.K) ? arow[g][gk] : 0.f;
            }
        }
    }
    #pragma unroll
    for (int rp = 0; rp < 2; rp++) {
        rb[rp][0] = nv_r[rp] ? ldB<BMODE,KK>(p, bb_r[rp], kbeg + bkl0)     : 0.f;
        rb[rp][1] = nv_r[rp] ? ldB<BMODE,KK>(p, bb_r[rp], kbeg + bkl0 + 4) : 0.f;
        rb[rp][2] = nv_r[rp] ? ldB<BMODE,KK>(p, bb_r[rp], kbeg + bkl0 + 1) : 0.f;
        rb[rp][3] = nv_r[rp] ? ldB<BMODE,KK>(p, bb_r[rp], kbeg + bkl0 + 5) : 0.f;
    }
    #pragma unroll
    for (int g = 0; g < AG; g++) {
        float4 v;
        v.x = __uint_as_float(f2tf32(ra[g][0]));
        v.y = __uint_as_float(f2tf32(ra[g][1]));
        v.z = __uint_as_float(f2tf32(ra[g][2]));
        v.w = __uint_as_float(f2tf32(ra[g][3]));
        *(float4*)&As[astore[g]] = v;
    }
    #pragma unroll
    for (int rp = 0; rp < 2; rp++) {
        float4 v;
        v.x = __uint_as_float(f2tf32(rb[rp][0]));
        v.y = __uint_as_float(f2tf32(rb[rp][1]));
        v.z = __uint_as_float(f2tf32(rb[rp][2]));
        v.w = __uint_as_float(f2tf32(rb[rp][3]));
        *(float4*)&Bs[bstore[rp]] = v;
    }
    __syncthreads();

    int buf = 0;
    for (int k0 = kbeg; k0 < kend; k0 += BK) {
        int kn = k0 + BK;
        bool more = kn < kend;
        if (more) {
            #pragma unroll
            for (int g = 0; g < AG; g++) {
                if (KALIGN) {
                    float4 v = *(const float4*)&arow[g][kn + ak4];
                    ra[g][0] = v.x; ra[g][1] = v.y; ra[g][2] = v.z; ra[g][3] = v.w;
                } else {
                    #pragma unroll
                    for (int j = 0; j < 4; j++) {
                        int gk = kn + ak4 + j;
                        ra[g][j] = (gk < p.K) ? arow[g][gk] : 0.f;
                    }
                }
            }
            #pragma unroll
            for (int rp = 0; rp < 2; rp++) {
                rb[rp][0] = nv_r[rp] ? ldB<BMODE,KK>(p, bb_r[rp], kn + bkl0)     : 0.f;
                rb[rp][1] = nv_r[rp] ? ldB<BMODE,KK>(p, bb_r[rp], kn + bkl0 + 4) : 0.f;
                rb[rp][2] = nv_r[rp] ? ldB<BMODE,KK>(p, bb_r[rp], kn + bkl0 + 1) : 0.f;
                rb[rp][3] = nv_r[rp] ? ldB<BMODE,KK>(p, bb_r[rp], kn + bkl0 + 5) : 0.f;
            }
        }
        const float* Ac = As + buf*ASZ;
        const float* Bc = Bs + buf*BSZ;
        #pragma unroll
        for (int kc = 0; kc < BK/8; kc++) {
            uint32_t af[2][4];
            #pragma unroll
            for (int mi = 0; mi < 2; mi++) {
                int rb_ = (arow_c + mi*16)*LDA_S + kc*8 + acol_c;
                af[mi][0] = __float_as_uint(Ac[rb_]);
                af[mi][1] = __float_as_uint(Ac[rb_ + 8*LDA_S]);
                af[mi][2] = __float_as_uint(Ac[rb_ + 4]);
                af[mi][3] = __float_as_uint(Ac[rb_ + 8*LDA_S + 4]);
            }
            #pragma unroll
            for (int ni = 0; ni < NF; ni++) {
                const float2 bv = *(const float2*)&Bc[(kc*(BN/8) + wc*NF + ni)*64 + physl*2];
                uint32_t bf[2];
                bf[0] = __float_as_uint(bv.x);
                bf[1] = __float_as_uint(bv.y);
                mma_tf32(acc[0][ni], af[0], bf);
                mma_tf32(acc[1][ni], af[1], bf);
            }
        }
        if (more) {
            float* An = As + (buf^1)*ASZ;
            float* Bn = Bs + (buf^1)*BSZ;
            #pragma unroll
            for (int g = 0; g < AG; g++) {
                float4 v;
                v.x = __uint_as_float(f2tf32(ra[g][0]));
                v.y = __uint_as_float(f2tf32(ra[g][1]));
                v.z = __uint_as_float(f2tf32(ra[g][2]));
                v.w = __uint_as_float(f2tf32(ra[g][3]));
                *(float4*)&An[astore[g]] = v;
            }
            #pragma unroll
            for (int rp = 0; rp < 2; rp++) {
                float4 v;
                v.x = __uint_as_float(f2tf32(rb[rp][0]));
                v.y = __uint_as_float(f2tf32(rb[rp][1]));
                v.z = __uint_as_float(f2tf32(rb[rp][2]));
                v.w = __uint_as_float(f2tf32(rb[rp][3]));
                *(float4*)&Bn[bstore[rp]] = v;
            }
        }
        __syncthreads();
        buf ^= 1;
    }

    // ---- epilogue ----
    if (SPLITK > 1) {
        float* pd = p.part + (size_t)blockIdx.z * ((size_t)p.M * p.N);
        #pragma unroll
        for (int mi = 0; mi < 2; mi++)
            #pragma unroll
            for (int half = 0; half < 2; half++) {
                int row = m0 + wr*32 + mi*16 + (lane >> 2) + half*8;
                #pragma unroll
                for (int ni = 0; ni < NF; ni++)
                    #pragma unroll
                    for (int e = 0; e < 2; e++) {
                        int gn = n0 + wc*WN + ni*8 + (lane & 3)*2 + e;
                        if (gn < p.N)
                            pd[(size_t)row*p.N + gn] = acc[mi][ni][half*2 + e];
                    }
            }
        return;
    }
    #pragma unroll
    for (int mi = 0; mi < 2; mi++) {
        #pragma unroll
        for (int half = 0; half < 2; half++) {
            int row = m0 + wr*32 + mi*16 + (lane >> 2) + half*8;
            float brow = 0.f;
            if (BIASM == 1) brow = p.bias[row];
            else if (BIASM == 3) brow = p.bias[row / p.kt];
            int cout = 0, jj = 0;
            if (SMODE == 1) { cout = row / p.kt; jj = row - cout*p.kt; }
            #pragma unroll
            for (int ni = 0; ni < NF; ni++) {
                #pragma unroll
                for (int e = 0; e < 2; e++) {
                    int gn = n0 + wc*WN + ni*8 + (lane & 3)*2 + e;
                    if (gn >= p.N) continue;
                    int b, q;
                    if (SMODE == 0 && p.sDb == 0) { b = 0; q = gn; }
                    else { b = gn / p.npos; q = gn - b*p.npos; }
                    float v = acc[mi][ni][half*2 + e] + brow;
                    if (BIASM == 2) v += p.bias[q];
                    if (ACT == 1) v = tanhf(v);
                    else if (ACT == 2) v = fmaxf(v, 0.f);
                    long long addr;
                    if (SMODE == 0) addr = b*p.sDb + (long long)row*p.ldd + q;
                    else addr = b*p.sDb + (long long)cout*p.mklen + (long long)q*p.kt + jj;
                    p.D[addr] = v;
                }
            }
        }
    }
}

// ---------------- split-K reduce + bias + tanh + batched store ----------------
__global__ void reduce_ep_k(const float* __restrict__ part, float* __restrict__ D,
                            const float* __restrict__ bias,
                            int S, int M, int N, long long sDb, int ldd, int npos) {
    int idx = blockIdx.x*blockDim.x + threadIdx.x;
    if (idx >= M*N) return;
    int row = idx / N, gn = idx - row*N;
    size_t st = (size_t)M*N;
    float v = 0.f;
    for (int z = 0; z < S; z++) v += part[(size_t)z*st + idx];
    v = tanhf(v + bias[row]);
    int b = gn / npos, q = gn - b*npos;
    D[b*sDb + (long long)row*ldd + q] = v;
}

// ---------------- block reduce + layer norms ----------
__device__ __forceinline__ float blk_sum(float v) {
    __shared__ float sb[8];
    #pragma unroll
    for (int o = 16; o; o >>= 1) v += __shfl_xor_sync(0xffffffffu, v, o);
    if ((threadIdx.x & 31) == 0) sb[threadIdx.x >> 5] = v;
    __syncthreads();
    float t = 0.f;
    #pragma unroll
    for (int i = 0; i < 8; i++) t += sb[i];
    __syncthreads();
    return t;
}

__global__ void ln1_kernel(const float* __restrict__ xr, const float* __restrict__ x1,
                           const float* __restrict__ g, const float* __restrict__ bt,
                           float* __restrict__ out, int m) {
    int row = blockIdx.x;
    int b = row / m, t = row - b*m;
    int tid = threadIdx.x;
    size_t base = (size_t)b*NC*m + t;
    float v0 = xr[base + (size_t)tid*m]       + x1[base + (size_t)tid*m];
    float v1 = xr[base + (size_t)(tid+256)*m] + x1[base + (size_t)(tid+256)*m];
    float mu = blk_sum(v0 + v1) * (1.f/NC);
    float d0 = v0 - mu, d1 = v1 - mu;
    float var = blk_sum(d0*d0 + d1*d1) * (1.f/NC);
    float inv = rsqrtf(var + 1e-5f);
    out[base + (size_t)tid*m]       = d0*inv*g[tid]     + bt[tid];
    out[base + (size_t)(tid+256)*m] = d1*inv*g[tid+256] + bt[tid+256];
}

__global__ void branch_out_kernel(const float* __restrict__ y2, const float* __restrict__ resn,
                                  const float* __restrict__ g, const float* __restrict__ bt,
                                  float* __restrict__ br, int mk, int nbr) {
    int row = blockIdx.x;
    int b = row >> 10, l = row & 1023;
    int li = (l * mk) >> 10;
    int tid = threadIdx.x;
    size_t yb = (size_t)b*NC*mk + li;
    size_t rb = (size_t)b*NC*NL + l;
    float v0 = y2[yb + (size_t)tid*mk]       + resn[rb + (size_t)tid*NL];
    float v1 = y2[yb + (size_t)(tid+256)*mk] + resn[rb + (size_t)(tid+256)*NL];
    float mu = blk_sum(v0 + v1) * (1.f/NC);
    float d0 = v0 - mu, d1 = v1 - mu;
    float var = blk_sum(d0*d0 + d1*d1) * (1.f/NC);
    float inv = rsqrtf(var + 1e-5f);
    float* o = br + (size_t)row*(2*NC) + nbr*NC;
    o[tid]     = d0*inv*g[tid]     + bt[tid];
    o[tid+256] = d1*inv*g[tid+256] + bt[tid+256];
}

__global__ void final_ln_kernel(const float* __restrict__ mg, const float* __restrict__ h2,
                                const float* __restrict__ g, const float* __restrict__ bt,
                                float* __restrict__ out) {
    int row = blockIdx.x;
    int tid = threadIdx.x;
    size_t base = (size_t)row*NC;
    float v0 = mg[base + tid]       + h2[base + tid];
    float v1 = mg[base + tid + 256] + h2[base + tid + 256];
    float mu = blk_sum(v0 + v1) * (1.f/NC);
    float d0 = v0 - mu, d1 = v1 - mu;
    float var = blk_sum(d0*d0 + d1*d1) * (1.f/NC);
    float inv = rsqrtf(var + 1e-5f);
    out[base + tid]       = d0*inv*g[tid]     + bt[tid];
    out[base + tid + 256] = d1*inv*g[tid+256] + bt[tid+256];
}

template<int BN, int SPLITK>
static inline dim3 gg(int M, int N) { return dim3((N + BN - 1)/BN, M/128, SPLITK); }

template<int BN, int BMODE, int KK, int KALIGN, int BIASM, int ACT, int SMODE, int SPLITK = 1>
static void launch_gemm(const GemmP& p) {
    constexpr int BK = (BN == 64) ? 32 : 16;
    constexpr int SMEM = 2*(128*(BK + 4) + BK*BN)*4;
    cudaFuncSetAttribute((const void*)gemm_k<BN,BMODE,KK,KALIGN,BIASM,ACT,SMODE,SPLITK>,
                         cudaFuncAttributeMaxDynamicSharedMemorySize, SMEM);
    gemm_k<BN,BMODE,KK,KALIGN,BIASM,ACT,SMODE,SPLITK><<<gg<BN,SPLITK>(p.M, p.N), 256, SMEM>>>(p);
}

extern "C" void kernel_launch(void* const* d_in, const int* in_sizes, int n_in,
                              void* d_out, int out_size) {
    (void)in_sizes; (void)n_in; (void)out_size;
    const float* src   = (const float*)d_in[0];
    const float* cw[2] = {(const float*)d_in[1],  (const float*)d_in[7]};
    const float* cb[2] = {(const float*)d_in[2],  (const float*)d_in[8]};
    const float* iw[2] = {(const float*)d_in[3],  (const float*)d_in[9]};
    const float* ib[2] = {(const float*)d_in[4],  (const float*)d_in[10]};
    const float* tw[2] = {(const float*)d_in[5],  (const float*)d_in[11]};
    const float* tb[2] = {(const float*)d_in[6],  (const float*)d_in[12]};
    const float* mw  = (const float*)d_in[13];
    const float* mb  = (const float*)d_in[14];
    const float* ng  = (const float*)d_in[15];
    const float* nb  = (const float*)d_in[16];
    const float* fw1 = (const float*)d_in[17];
    const float* fb1 = (const float*)d_in[18];
    const float* fw2 = (const float*)d_in[19];
    const float* fb2 = (const float*)d_in[20];
    const float* fng = (const float*)d_in[21];
    const float* fnb = (const float*)d_in[22];
    float* out = (float*)d_out;

    float *p_res,*p_cv,*p_x1,*p_xf,*p_xi,*p_xr,*p_yln,*p_y2,*p_br,*p_mg,*p_h1,*p_h2;
    float *p_W2a,*p_W2b,*p_Wm,*p_CM0,*p_CM20,*p_CM1,*p_CM21,*p_part,*p_im;
    cudaGetSymbolAddress((void**)&p_res, g_res);
    cudaGetSymbolAddress((void**)&p_cv,  g_cv);
    cudaGetSymbolAddress((void**)&p_x1,  g_x1);
    cudaGetSymbolAddress((void**)&p_xf,  g_xf);
    cudaGetSymbolAddress((void**)&p_xi,  g_xi);
    cudaGetSymbolAddress((void**)&p_xr,  g_xr);
    cudaGetSymbolAddress((void**)&p_yln, g_yln);
    cudaGetSymbolAddress((void**)&p_y2,  g_y2);
    cudaGetSymbolAddress((void**)&p_br,  g_br);
    cudaGetSymbolAddress((void**)&p_mg,  g_mg);
    cudaGetSymbolAddress((void**)&p_h1,  g_h1);
    cudaGetSymbolAddress((void**)&p_h2,  g_h2);
    cudaGetSymbolAddress((void**)&p_W2a, g_W2a);
    cudaGetSymbolAddress((void**)&p_W2b, g_W2b);
    cudaGetSymbolAddress((void**)&p_Wm,  g_Wm);
    cudaGetSymbolAddress((void**)&p_CM0, g_CM0);
    cudaGetSymbolAddress((void**)&p_CM20,g_CM20);
    cudaGetSymbolAddress((void**)&p_CM1, g_CM1);
    cudaGetSymbolAddress((void**)&p_CM21,g_CM21);
    cudaGetSymbolAddress((void**)&p_part,g_part);
    cudaGetSymbolAddress((void**)&p_im,  g_im);

    const int Kk[2] = {12, 24}, NE[2] = {43, 22},
              MM[2] = {85, 43}, N2_[2] = {169, 85}, MKl[2] = {1020, 1032};
    float* CMv[2]  = {p_CM0, p_CM1};
    float* CM2v[2] = {p_CM20, p_CM21};
    float* W2v[2]  = {p_W2a, p_W2b};
    float* cpart[2] = {p_part, p_part + (size_t)6*1024*1024};

    decomp_kernel<<<dim3(NL/32, NC/32, NB), dim3(32, 32)>>>(src, p_res);
    prep_all<<<2048, 256>>>(mw, p_Wm, tw[0], p_W2a, tw[1], p_W2b,
                            p_CM0, p_CM20, p_CM1, p_CM21);

    // conv via materialized im2col + dense split-K GEMM (BN=128, BK=16)
    for (int n = 0; n < 2; n++) {
        int k = Kk[n], ne2 = 2*NE[n];
        int Nn = NB*ne2;
        if (n == 0) im2col_conv_k<12,86><<<NC*12, 256>>>(p_res, p_im, 6);
        else        im2col_conv_k<24,44><<<NC*24, 256>>>(p_res + (size_t)NB*NC*NL, p_im, 12);
        GemmP p{};
        p.A = cw[n]; p.lda = NC*k;
        p.Bp = p_im; p.ldb = Nn; p.sBb = 0;
        p.part = cpart[n];
        p.bias = cb[n];
        p.M = NC; p.N = Nn; p.K = NC*k; p.npos = ne2;
        if (n == 0) launch_gemm<128,0,1,1,1,1,0,4>(p);
        else        launch_gemm<128,0,1,1,1,1,0,8>(p);
        reduce_ep_k<<<(NC*Nn + 255)/256, 256>>>(cpart[n], p_cv + (size_t)n*NB*NC*86, cb[n],
                                                (n == 0) ? 4 : 8, NC, Nn,
                                                (long long)NC*ne2, ne2, ne2);
    }

    for (int n = 0; n < 2; n++) {
        int k = Kk[n], m = MM[n], N2 = N2_[n], mk = MKl[n];
        int ne2 = 2*NE[n];

        x1_kernel<<<1024, 256>>>(p_cv + (size_t)n*NB*NC*86, p_x1, m, ne2);
        { // real-DFT (ragged K -> BN=64 guarded path)
            GemmP p{};
            p.A = p_x1; p.lda = m;
            p.Bp = CMv[n]; p.ldb = N2; p.sBb = 0;
            p.D = p_xf; p.sDb = 0; p.ldd = N2;
            p.M = NB*NC; p.N = N2; p.K = m; p.npos = N2;
            launch_gemm<64,0,1,0,0,0,0>(p);
        }
        { // isometric conv (valid), tanh — split-K, BN=128
            GemmP p{};
            p.A = iw[n]; p.lda = NC*m;
            p.Bp = p_xf; p.sBb = (long long)NC*N2; p.inner = N2;
            p.part = p_part;
            p.bias = ib[n];
            p.M = NC; p.N = NB*m; p.K = NC*m; p.npos = m;
            if (n == 0) launch_gemm<128,2,85,1,1,1,0,8>(p);
            else        launch_gemm<128,2,43,1,1,1,0,8>(p);
            reduce_ep_k<<<(NC*NB*m + 255)/256, 256>>>(p_part, p_xi, ib[n],
                                                      8, NC, NB*m,
                                                      (long long)NC*m, m, m);
        }
        { // real-IDFT (ragged K)
            GemmP p{};
            p.A = p_xi; p.lda = m;
            p.Bp = CM2v[n]; p.ldb = m; p.sBb = 0;
            p.D = p_xr; p.sDb = 0; p.ldd = m;
            p.M = NB*NC; p.N = m; p.K = m; p.npos = m;
            launch_gemm<64,0,1,0,0,0,0>(p);
        }
        ln1_kernel<<<NB*m, 256>>>(p_xr, p_x1, ng, nb, p_yln, m);
        { // conv-transpose, tanh, scatter store (BN=128)
            GemmP p{};
            p.A = W2v[n]; p.lda = NC;
            p.Bp = p_yln; p.ldb = m; p.sBb = (long long)NC*m;
            p.D = p_y2; p.sDb = (long long)NC*mk; p.kt = k; p.mklen = mk;
            p.bias = tb[n];
            p.M = NC*k; p.N = NB*m; p.K = NC; p.npos = m;
            launch_gemm<128,0,1,1,3,1,1>(p);
        }
        branch_out_kernel<<<NB*NL, 256>>>(p_y2, p_res + (size_t)n*NB*NC*NL, ng, nb, p_br, mk, n);
    }
    { // merge
        GemmP p{};
        p.A = p_br; p.lda = 2*NC;
        p.Bp = p_Wm; p.ldb = NC; p.sBb = 0;
        p.D = p_mg; p.sDb = 0; p.ldd = NC;
        p.bias = mb;
        p.M = NB*NL; p.N = NC; p.K = 2*NC; p.npos = NC;
        launch_gemm<128,0,1,1,2,0,0>(p);
    }
    { // FFN layer 1 (relu)
        GemmP p{};
        p.A = p_mg; p.lda = NC;
        p.Bp = fw1; p.ldb = 4*NC; p.sBb = 0;
        p.D = p_h1; p.sDb = 0; p.ldd = 4*NC;
        p.bias = fb1;
        p.M = NB*NL; p.N = 4*NC; p.K = NC; p.npos = 4*NC;
        launch_gemm<128,0,1,1,2,2,0>(p);
    }
    { // FFN layer 2
        GemmP p{};
        p.A = p_h1; p.lda = 4*NC;
        p.Bp = fw2; p.ldb = NC; p.sBb = 0;
        p.D = p_h2; p.sDb = 0; p.ldd = NC;
        p.bias = fb2;
        p.M = NB*NL; p.N = NC; p.K = 4*NC; p.npos = NC;
        launch_gemm<128,0,1,1,2,0,0>(p);
    }
    final_ln_kernel<<<NB*NL, 256>>>(p_mg, p_h2, fng, fnb, out);
}

// round 14
// speedup vs baseline: 2.2347x; 1.0542x over previous
#include <cuda_runtime.h>
#include <math.h>
#include <stdint.h>

#define NB 32
#define NL 1024
#define NC 512
#define LH 512   // L/2

// ---------------- scratch (device globals; no allocations) ----------------
__device__ float g_res[(size_t)2*NB*NC*NL];
__device__ float g_cv [(size_t)2*NB*NC*86];
__device__ float g_x1 [(size_t)NB*NC*85];
__device__ float g_xf [(size_t)NB*NC*169];
__device__ float g_xi [(size_t)NB*NC*85];
__device__ float g_xr [(size_t)NB*NC*85];
__device__ float g_yln[(size_t)NB*NC*85];
__device__ float g_y2 [(size_t)NB*NC*1032];
__device__ float g_br [(size_t)NB*NL*2*NC];
__device__ float g_mg [(size_t)NB*NL*NC];
__device__ float g_h1 [(size_t)NB*NL*4*NC];
__device__ float g_h2 [(size_t)NB*NL*NC];
__device__ float g_W2a[(size_t)NC*12*NC];
__device__ float g_W2b[(size_t)NC*24*NC];
__device__ float g_Wm [(size_t)2*NC*NC];
__device__ float g_CM0 [85*169];
__device__ float g_CM20[85*85];
__device__ float g_CM1 [43*85];
__device__ float g_CM21[43*43];
__device__ float g_part[(size_t)16*1024*1024];  // split-K partials workspace
__device__ float g_im [(size_t)18*1024*1024];   // materialized conv im2col

// ---------------- series decomp ----------------
__global__ void decomp_kernel(const float* __restrict__ src, float* __restrict__ res) {
    __shared__ float s[64][33];
    int b = blockIdx.z;
    int c0 = blockIdx.y * 32;
    int l0 = blockIdx.x * 32;
    int tx = threadIdx.x, ty = threadIdx.y;
    for (int r = ty; r < 64; r += 32) {
        int l = l0 - 16 + r;
        l = l < 0 ? 0 : (l > NL - 1 ? NL - 1 : l);
        s[r][tx] = src[((size_t)b*NL + l)*NC + c0 + tx];
    }
    __syncthreads();
    int base = tx + 16;
    float s17 = 0.f;
    #pragma unroll
    for (int j = -8; j <= 8; j++) s17 += s[base + j][ty];
    float s33 = s17;
    #pragma unroll
    for (int j = 9; j <= 16; j++) s33 += s[base - j][ty] + s[base + j][ty];
    float v = s[base][ty];
    size_t o = ((size_t)(b*NC + c0 + ty))*NL + l0 + tx;
    res[o] = v - s17 / 17.0f;
    res[(size_t)NB*NC*NL + o] = v - s33 / 33.0f;
}

// ---------------- fused prep ----------------
__global__ void prep_all(const float* __restrict__ mwt, float* __restrict__ Wm,
                         const float* __restrict__ tw0, float* __restrict__ W2a,
                         const float* __restrict__ tw1, float* __restrict__ W2b,
                         float* __restrict__ CM0, float* __restrict__ CM20,
                         float* __restrict__ CM1, float* __restrict__ CM21) {
    const double TWO_PI = 6.283185307179586476925286766559;
    const int tM = NC*NC*2;
    const int tA = NC*NC*12, tB = NC*NC*24;
    const int c0 = 85*169, c1 = 85*85, c2 = 43*85, c3 = 43*43;
    int total = tM + tA + tB + c0 + c1 + c2 + c3;
    for (int idx = blockIdx.x*blockDim.x + threadIdx.x; idx < total; idx += gridDim.x*blockDim.x) {
        int i = idx;
        if (i < tM) {
            int o = i / (NC*2);
            int rem = i - o*NC*2;
            int c = rem >> 1, n = rem & 1;
            Wm[((size_t)n*NC + c)*NC + o] = mwt[i];
            continue;
        }
        i -= tM;
        if (i < tA) {
            int cin = i / (NC*12);
            int r   = i - cin*(NC*12);
            W2a[(size_t)r*NC + cin] = tw0[i];
            continue;
        }
        i -= tA;
        if (i < tB) {
            int cin = i / (NC*24);
            int r   = i - cin*(NC*24);
            W2b[(size_t)r*NC + cin] = tw1[i];
            continue;
        }
        i -= tB;
        if (i < c0) {
            int t = i / 169, f = i - t*169;
            CM0[i] = (float)cos(TWO_PI * (double)((long long)f*(t + 84)) / 169.0);
            continue;
        }
        i -= c0;
        if (i < c1) {
            int f = i / 85, t = i - f*85;
            CM20[i] = (float)(cos(TWO_PI * (double)((long long)f*t) / 85.0) / 85.0);
            continue;
        }
        i -= c1;
        if (i < c2) {
            int t = i / 85, f = i - t*85;
            CM1[i] = (float)cos(TWO_PI * (double)((long long)f*(t + 42)) / 85.0);
            continue;
        }
        i -= c2;
        {
            int f = i / 43, t = i - f*43;
            CM21[i] = (float)(cos(TWO_PI * (double)((long long)f*t) / 43.0) / 43.0);
        }
    }
}

// ---------------- conv im2col materialization ----------------
template<int KK, int NE2>
__global__ void im2col_conv_k(const float* __restrict__ res, float* __restrict__ out, int pad) {
    int gk = blockIdx.x;
    int cin = gk / KK, t = gk - cin*KK;
    const int N = NB*NE2;
    const float* rbase = res + (size_t)cin*NL;
    float* obase = out + (size_t)gk*N;
    int tb = t - pad;
    for (int gn = threadIdx.x; gn < N; gn += blockDim.x) {
        int b = gn / NE2, q = gn - b*NE2;
        int s = (q >> 1)*KK + tb;
        float v = (s >= 0 && s < LH) ? rbase[(size_t)b*NC*NL + 2*s + (q & 1)] : 0.f;
        obase[gn] = v;
    }
}

// ---------------- x1: exp-gated interleave ----------------
__global__ void x1_kernel(const float* __restrict__ cv, float* __restrict__ x1, int m, int ne2) {
    size_t total = (size_t)NB*NC*m;
    for (size_t idx = (size_t)blockIdx.x*blockDim.x + threadIdx.x; idx < total;
         idx += (size_t)gridDim.x*blockDim.x) {
        int t = (int)(idx % m);
        size_t bc = idx / m;
        const float* c2 = cv + bc*ne2;
        x1[idx] = c2[t ^ 1] * expf(c2[t]);
    }
}

// ---------------- GEMM params ----------------
struct GemmP {
    const float* A; int lda;
    const float* Bp; int ldb; long long sBb;
    float* D; long long sDb; int ldd;
    const float* bias;
    int M, N, K;
    int npos;
    int pad, lhalf, inner;
    int kt, mklen;
    float* part;
};

__device__ __forceinline__ uint32_t f2tf32(float v) {
    uint32_t u;
    asm("cvt.rna.tf32.f32 %0, %1;" : "=r"(u) : "f"(v));
    return u;
}
__device__ __forceinline__ void mma_tf32(float c[4], const uint32_t a[4], const uint32_t b[2]) {
    asm("mma.sync.aligned.m16n8k8.row.col.f32.tf32.tf32.f32 "
        "{%0,%1,%2,%3},{%4,%5,%6,%7},{%8,%9},{%0,%1,%2,%3};"
        : "+f"(c[0]), "+f"(c[1]), "+f"(c[2]), "+f"(c[3])
        : "r"(a[0]), "r"(a[1]), "r"(a[2]), "r"(a[3]), "r"(b[0]), "r"(b[1]));
}

template<int BMODE, int KK>
__device__ __forceinline__ float ldB(const GemmP& p, const float* bbase, int gk) {
    if (gk >= p.K) return 0.f;
    if (BMODE == 0) return bbase[(long long)gk * p.ldb];
    int cin = gk / KK, t = gk - cin*KK;
    return bbase[(long long)cin*p.inner + t];
}

// tf32 mma.sync GEMM, BM=128.
// BN=64: BK=32. BN=128: BK=16, NF=8 (crossbar-balanced).
// A: row-major padded smem; B: fragment-major gather layout. Both conflict-free.
template<int BN, int BMODE, int KK, int KALIGN, int BIASM, int ACT, int SMODE, int SPLITK>
__global__ void __launch_bounds__(256, 2)
gemm_k(GemmP p) {
    constexpr int BM = 128;
    constexpr int BK = (BN == 64) ? 32 : 16;
    constexpr int LDA_S = BK + 4;
    constexpr int WR = 4, WC = 2;
    constexpr int WN = BN/WC, NF = WN/8;
    constexpr int AG = BK/8;
    constexpr int ROWSTEP = 1024/BK;
    constexpr int ASZ = BM*LDA_S, BSZ = BK*BN;
    extern __shared__ float dyn[];
    float* As = dyn;
    float* Bs = dyn + 2*ASZ;

    const int tid = threadIdx.x, lane = tid & 31, warp = tid >> 5;
    const int wr = warp % WR, wc = warp / WR;
    const int m0 = blockIdx.y * BM, n0 = blockIdx.x * BN;

    int kbeg = 0, kend = p.K;
    if (SPLITK > 1) {
        int kc = ((p.K + SPLITK*BK - 1) / (SPLITK*BK)) * BK;
        kbeg = blockIdx.z * kc;
        kend = min(kbeg + kc, p.K);
    }

    // ---- A row-major fill ----
    const int ar_ = tid / (BK/4);
    const int ak4 = (tid & (BK/4 - 1)) * 4;
    const float* arow[AG];
    int astore[AG];
    #pragma unroll
    for (int g = 0; g < AG; g++) {
        arow[g]   = p.A + (long long)(m0 + ar_ + ROWSTEP*g) * p.lda;
        astore[g] = (ar_ + ROWSTEP*g)*LDA_S + ak4;
    }
    // ---- B gather fill ----
    int kcw, cbw, nh;
    if (BK == 32) { kcw = warp >> 1; cbw = warp & 1; nh = 0; }
    else          { kcw = warp >> 2; cbw = (warp >> 1) & 1; nh = warp & 1; }
    const int bkl0 = kcw*8 + cbw*2;
    const float* bb_r[2];
    int bstore[2];
    bool nv_r[2];
    #pragma unroll
    for (int rp = 0; rp < 2; rp++) {
        int ln = (BK == 32) ? (lane + 32*rp) : (nh*64 + rp*32 + lane);
        int gn = n0 + ln;
        nv_r[rp] = gn < p.N;
        int g = nv_r[rp] ? gn : 0;
        int b = 0, q = g;
        if (!(BMODE == 0 && p.sBb == 0)) { b = g / p.npos; q = g - b*p.npos; }
        bb_r[rp] = p.Bp + b*p.sBb + q;
        int fb = kcw*(BN/8) + (ln >> 3);
        int X = (ln & 7)*4 + cbw*2;
        X ^= ((X >> 4) & 1) << 1;
        bstore[rp] = fb*64 + X*2;
    }
    const int physl = lane ^ (((lane >> 4) & 1) << 1);
    const int arow_c = wr*32 + (lane >> 2);
    const int acol_c = lane & 3;

    float acc[2][NF][4];
    #pragma unroll
    for (int mi = 0; mi < 2; mi++)
        #pragma unroll
        for (int ni = 0; ni < NF; ni++)
            #pragma unroll
            for (int e = 0; e < 4; e++) acc[mi][ni][e] = 0.f;

    float ra[AG][4], rb[2][4];
    // ---- prologue ----
    #pragma unroll
    for (int g = 0; g < AG; g++) {
        if (KALIGN) {
            float4 v = *(const float4*)&arow[g][kbeg + ak4];
            ra[g][0] = v.x; ra[g][1] = v.y; ra[g][2] = v.z; ra[g][3] = v.w;
        } else {
            #pragma unroll
            for (int j = 0; j < 4; j++) {
                int gk = kbeg + ak4 + j;
                ra[g][j] = (gk < p.K) ? arow[g][gk] : 0.f;
            }
        }
    }
    #pragma unroll
    for (int rp = 0; rp < 2; rp++) {
        rb[rp][0] = nv_r[rp] ? ldB<BMODE,KK>(p, bb_r[rp], kbeg + bkl0)     : 0.f;
        rb[rp][1] = nv_r[rp] ? ldB<BMODE,KK>(p, bb_r[rp], kbeg + bkl0 + 4) : 0.f;
        rb[rp][2] = nv_r[rp] ? ldB<BMODE,KK>(p, bb_r[rp], kbeg + bkl0 + 1) : 0.f;
        rb[rp][3] = nv_r[rp] ? ldB<BMODE,KK>(p, bb_r[rp], kbeg + bkl0 + 5) : 0.f;
    }
    #pragma unroll
    for (int g = 0; g < AG; g++) {
        float4 v;
        v.x = __uint_as_float(f2tf32(ra[g][0]));
        v.y = __uint_as_float(f2tf32(ra[g][1]));
        v.z = __uint_as_float(f2tf32(ra[g][2]));
        v.w = __uint_as_float(f2tf32(ra[g][3]));
        *(float4*)&As[astore[g]] = v;
    }
    #pragma unroll
    for (int rp = 0; rp < 2; rp++) {
        float4 v;
        v.x = __uint_as_float(f2tf32(rb[rp][0]));
        v.y = __uint_as_float(f2tf32(rb[rp][1]));
        v.z = __uint_as_float(f2tf32(rb[rp][2]));
        v.w = __uint_as_float(f2tf32(rb[rp][3]));
        *(float4*)&Bs[bstore[rp]] = v;
    }
    __syncthreads();

    int buf = 0;
    for (int k0 = kbeg; k0 < kend; k0 += BK) {
        int kn = k0 + BK;
        bool more = kn < kend;
        if (more) {
            #pragma unroll
            for (int g = 0; g < AG; g++) {
                if (KALIGN) {
                    float4 v = *(const float4*)&arow[g][kn + ak4];
                    ra[g][0] = v.x; ra[g][1] = v.y; ra[g][2] = v.z; ra[g][3] = v.w;
                } else {
                    #pragma unroll
                    for (int j = 0; j < 4; j++) {
                        int gk = kn + ak4 + j;
                        ra[g][j] = (gk < p.K) ? arow[g][gk] : 0.f;
                    }
                }
            }
            #pragma unroll
            for (int rp = 0; rp < 2; rp++) {
                rb[rp][0] = nv_r[rp] ? ldB<BMODE,KK>(p, bb_r[rp], kn + bkl0)     : 0.f;
                rb[rp][1] = nv_r[rp] ? ldB<BMODE,KK>(p, bb_r[rp], kn + bkl0 + 4) : 0.f;
                rb[rp][2] = nv_r[rp] ? ldB<BMODE,KK>(p, bb_r[rp], kn + bkl0 + 1) : 0.f;
                rb[rp][3] = nv_r[rp] ? ldB<BMODE,KK>(p, bb_r[rp], kn + bkl0 + 5) : 0.f;
            }
        }
        const float* Ac = As + buf*ASZ;
        const float* Bc = Bs + buf*BSZ;
        #pragma unroll
        for (int kc = 0; kc < BK/8; kc++) {
            uint32_t af[2][4];
            #pragma unroll
            for (int mi = 0; mi < 2; mi++) {
                int rb_ = (arow_c + mi*16)*LDA_S + kc*8 + acol_c;
                af[mi][0] = __float_as_uint(Ac[rb_]);
                af[mi][1] = __float_as_uint(Ac[rb_ + 8*LDA_S]);
                af[mi][2] = __float_as_uint(Ac[rb_ + 4]);
                af[mi][3] = __float_as_uint(Ac[rb_ + 8*LDA_S + 4]);
            }
            #pragma unroll
            for (int ni = 0; ni < NF; ni++) {
                const float2 bv = *(const float2*)&Bc[(kc*(BN/8) + wc*NF + ni)*64 + physl*2];
                uint32_t bf[2];
                bf[0] = __float_as_uint(bv.x);
                bf[1] = __float_as_uint(bv.y);
                mma_tf32(acc[0][ni], af[0], bf);
                mma_tf32(acc[1][ni], af[1], bf);
            }
        }
        if (more) {
            float* An = As + (buf^1)*ASZ;
            float* Bn = Bs + (buf^1)*BSZ;
            #pragma unroll
            for (int g = 0; g < AG; g++) {
                float4 v;
                v.x = __uint_as_float(f2tf32(ra[g][0]));
                v.y = __uint_as_float(f2tf32(ra[g][1]));
                v.z = __uint_as_float(f2tf32(ra[g][2]));
                v.w = __uint_as_float(f2tf32(ra[g][3]));
                *(float4*)&An[astore[g]] = v;
            }
            #pragma unroll
            for (int rp = 0; rp < 2; rp++) {
                float4 v;
                v.x = __uint_as_float(f2tf32(rb[rp][0]));
                v.y = __uint_as_float(f2tf32(rb[rp][1]));
                v.z = __uint_as_float(f2tf32(rb[rp][2]));
                v.w = __uint_as_float(f2tf32(rb[rp][3]));
                *(float4*)&Bn[bstore[rp]] = v;
            }
        }
        __syncthreads();
        buf ^= 1;
    }

    // ---- epilogue ----
    if (SPLITK > 1) {
        float* pd = p.part + (size_t)blockIdx.z * ((size_t)p.M * p.N);
        #pragma unroll
        for (int mi = 0; mi < 2; mi++)
            #pragma unroll
            for (int half = 0; half < 2; half++) {
                int row = m0 + wr*32 + mi*16 + (lane >> 2) + half*8;
                #pragma unroll
                for (int ni = 0; ni < NF; ni++)
                    #pragma unroll
                    for (int e = 0; e < 2; e++) {
                        int gn = n0 + wc*WN + ni*8 + (lane & 3)*2 + e;
                        if (gn < p.N)
                            pd[(size_t)row*p.N + gn] = acc[mi][ni][half*2 + e];
                    }
            }
        return;
    }
    #pragma unroll
    for (int mi = 0; mi < 2; mi++) {
        #pragma unroll
        for (int half = 0; half < 2; half++) {
            int row = m0 + wr*32 + mi*16 + (lane >> 2) + half*8;
            float brow = 0.f;
            if (BIASM == 1) brow = p.bias[row];
            else if (BIASM == 3) brow = p.bias[row / p.kt];
            int cout = 0, jj = 0;
            if (SMODE == 1) { cout = row / p.kt; jj = row - cout*p.kt; }
            #pragma unroll
            for (int ni = 0; ni < NF; ni++) {
                #pragma unroll
                for (int e = 0; e < 2; e++) {
                    int gn = n0 + wc*WN + ni*8 + (lane & 3)*2 + e;
                    if (gn >= p.N) continue;
                    int b, q;
                    if (SMODE == 0 && p.sDb == 0) { b = 0; q = gn; }
                    else { b = gn / p.npos; q = gn - b*p.npos; }
                    float v = acc[mi][ni][half*2 + e] + brow;
                    if (BIASM == 2) v += p.bias[q];
                    if (ACT == 1) v = tanhf(v);
                    else if (ACT == 2) v = fmaxf(v, 0.f);
                    long long addr;
                    if (SMODE == 0) addr = b*p.sDb + (long long)row*p.ldd + q;
                    else addr = b*p.sDb + (long long)cout*p.mklen + (long long)q*p.kt + jj;
                    p.D[addr] = v;
                }
            }
        }
    }
}

// ---------------- split-K reduce + bias + tanh + batched store ----------------
__global__ void reduce_ep_k(const float* __restrict__ part, float* __restrict__ D,
                            const float* __restrict__ bias,
                            int S, int M, int N, long long sDb, int ldd, int npos) {
    int idx = blockIdx.x*blockDim.x + threadIdx.x;
    if (idx >= M*N) return;
    int row = idx / N, gn = idx - row*N;
    size_t st = (size_t)M*N;
    float v = 0.f;
    for (int z = 0; z < S; z++) v += part[(size_t)z*st + idx];
    v = tanhf(v + bias[row]);
    int b = gn / npos, q = gn - b*npos;
    D[b*sDb + (long long)row*ldd + q] = v;
}

// ---------------- block reduce + layer norms ----------
__device__ __forceinline__ float blk_sum(float v) {
    __shared__ float sb[8];
    #pragma unroll
    for (int o = 16; o; o >>= 1) v += __shfl_xor_sync(0xffffffffu, v, o);
    if ((threadIdx.x & 31) == 0) sb[threadIdx.x >> 5] = v;
    __syncthreads();
    float t = 0.f;
    #pragma unroll
    for (int i = 0; i < 8; i++) t += sb[i];
    __syncthreads();
    return t;
}

__global__ void ln1_kernel(const float* __restrict__ xr, const float* __restrict__ x1,
                           const float* __restrict__ g, const float* __restrict__ bt,
                           float* __restrict__ out, int m) {
    int row = blockIdx.x;
    int b = row / m, t = row - b*m;
    int tid = threadIdx.x;
    size_t base = (size_t)b*NC*m + t;
    float v0 = xr[base + (size_t)tid*m]       + x1[base + (size_t)tid*m];
    float v1 = xr[base + (size_t)(tid+256)*m] + x1[base + (size_t)(tid+256)*m];
    float mu = blk_sum(v0 + v1) * (1.f/NC);
    float d0 = v0 - mu, d1 = v1 - mu;
    float var = blk_sum(d0*d0 + d1*d1) * (1.f/NC);
    float inv = rsqrtf(var + 1e-5f);
    out[base + (size_t)tid*m]       = d0*inv*g[tid]     + bt[tid];
    out[base + (size_t)(tid+256)*m] = d1*inv*g[tid+256] + bt[tid+256];
}

__global__ void branch_out_kernel(const float* __restrict__ y2, const float* __restrict__ resn,
                                  const float* __restrict__ g, const float* __restrict__ bt,
                                  float* __restrict__ br, int mk, int nbr) {
    int row = blockIdx.x;
    int b = row >> 10, l = row & 1023;
    int li = (l * mk) >> 10;
    int tid = threadIdx.x;
    size_t yb = (size_t)b*NC*mk + li;
    size_t rb = (size_t)b*NC*NL + l;
    float v0 = y2[yb + (size_t)tid*mk]       + resn[rb + (size_t)tid*NL];
    float v1 = y2[yb + (size_t)(tid+256)*mk] + resn[rb + (size_t)(tid+256)*NL];
    float mu = blk_sum(v0 + v1) * (1.f/NC);
    float d0 = v0 - mu, d1 = v1 - mu;
    float var = blk_sum(d0*d0 + d1*d1) * (1.f/NC);
    float inv = rsqrtf(var + 1e-5f);
    float* o = br + (size_t)row*(2*NC) + nbr*NC;
    o[tid]     = d0*inv*g[tid]     + bt[tid];
    o[tid+256] = d1*inv*g[tid+256] + bt[tid+256];
}

__global__ void final_ln_kernel(const float* __restrict__ mg, const float* __restrict__ h2,
                                const float* __restrict__ g, const float* __restrict__ bt,
                                float* __restrict__ out) {
    int row = blockIdx.x;
    int tid = threadIdx.x;
    size_t base = (size_t)row*NC;
    float v0 = mg[base + tid]       + h2[base + tid];
    float v1 = mg[base + tid + 256] + h2[base + tid + 256];
    float mu = blk_sum(v0 + v1) * (1.f/NC);
    float d0 = v0 - mu, d1 = v1 - mu;
    float var = blk_sum(d0*d0 + d1*d1) * (1.f/NC);
    float inv = rsqrtf(var + 1e-5f);
    out[base + tid]       = d0*inv*g[tid]     + bt[tid];
    out[base + tid + 256] = d1*inv*g[tid+256] + bt[tid+256];
}

template<int BN, int SPLITK>
static inline dim3 gg(int M, int N) { return dim3((N + BN - 1)/BN, M/128, SPLITK); }

template<int BN, int BMODE, int KK, int KALIGN, int BIASM, int ACT, int SMODE, int SPLITK = 1>
static void launch_gemm(const GemmP& p) {
    constexpr int BK = (BN == 64) ? 32 : 16;
    constexpr int SMEM = 2*(128*(BK + 4) + BK*BN)*4;
    cudaFuncSetAttribute((const void*)gemm_k<BN,BMODE,KK,KALIGN,BIASM,ACT,SMODE,SPLITK>,
                         cudaFuncAttributeMaxDynamicSharedMemorySize, SMEM);
    gemm_k<BN,BMODE,KK,KALIGN,BIASM,ACT,SMODE,SPLITK><<<gg<BN,SPLITK>(p.M, p.N), 256, SMEM>>>(p);
}

extern "C" void kernel_launch(void* const* d_in, const int* in_sizes, int n_in,
                              void* d_out, int out_size) {
    (void)in_sizes; (void)n_in; (void)out_size;
    const float* src   = (const float*)d_in[0];
    const float* cw[2] = {(const float*)d_in[1],  (const float*)d_in[7]};
    const float* cb[2] = {(const float*)d_in[2],  (const float*)d_in[8]};
    const float* iw[2] = {(const float*)d_in[3],  (const float*)d_in[9]};
    const float* ib[2] = {(const float*)d_in[4],  (const float*)d_in[10]};
    const float* tw[2] = {(const float*)d_in[5],  (const float*)d_in[11]};
    const float* tb[2] = {(const float*)d_in[6],  (const float*)d_in[12]};
    const float* mw  = (const float*)d_in[13];
    const float* mb  = (const float*)d_in[14];
    const float* ng  = (const float*)d_in[15];
    const float* nb  = (const float*)d_in[16];
    const float* fw1 = (const float*)d_in[17];
    const float* fb1 = (const float*)d_in[18];
    const float* fw2 = (const float*)d_in[19];
    const float* fb2 = (const float*)d_in[20];
    const float* fng = (const float*)d_in[21];
    const float* fnb = (const float*)d_in[22];
    float* out = (float*)d_out;

    float *p_res,*p_cv,*p_x1,*p_xf,*p_xi,*p_xr,*p_yln,*p_y2,*p_br,*p_mg,*p_h1,*p_h2;
    float *p_W2a,*p_W2b,*p_Wm,*p_CM0,*p_CM20,*p_CM1,*p_CM21,*p_part,*p_im;
    cudaGetSymbolAddress((void**)&p_res, g_res);
    cudaGetSymbolAddress((void**)&p_cv,  g_cv);
    cudaGetSymbolAddress((void**)&p_x1,  g_x1);
    cudaGetSymbolAddress((void**)&p_xf,  g_xf);
    cudaGetSymbolAddress((void**)&p_xi,  g_xi);
    cudaGetSymbolAddress((void**)&p_xr,  g_xr);
    cudaGetSymbolAddress((void**)&p_yln, g_yln);
    cudaGetSymbolAddress((void**)&p_y2,  g_y2);
    cudaGetSymbolAddress((void**)&p_br,  g_br);
    cudaGetSymbolAddress((void**)&p_mg,  g_mg);
    cudaGetSymbolAddress((void**)&p_h1,  g_h1);
    cudaGetSymbolAddress((void**)&p_h2,  g_h2);
    cudaGetSymbolAddress((void**)&p_W2a, g_W2a);
    cudaGetSymbolAddress((void**)&p_W2b, g_W2b);
    cudaGetSymbolAddress((void**)&p_Wm,  g_Wm);
    cudaGetSymbolAddress((void**)&p_CM0, g_CM0);
    cudaGetSymbolAddress((void**)&p_CM20,g_CM20);
    cudaGetSymbolAddress((void**)&p_CM1, g_CM1);
    cudaGetSymbolAddress((void**)&p_CM21,g_CM21);
    cudaGetSymbolAddress((void**)&p_part,g_part);
    cudaGetSymbolAddress((void**)&p_im,  g_im);

    const int Kk[2] = {12, 24}, NE[2] = {43, 22},
              MM[2] = {85, 43}, N2_[2] = {169, 85}, MKl[2] = {1020, 1032};
    float* CMv[2]  = {p_CM0, p_CM1};
    float* CM2v[2] = {p_CM20, p_CM21};
    float* W2v[2]  = {p_W2a, p_W2b};

    decomp_kernel<<<dim3(NL/32, NC/32, NB), dim3(32, 32)>>>(src, p_res);
    prep_all<<<2048, 256>>>(mw, p_Wm, tw[0], p_W2a, tw[1], p_W2b,
                            p_CM0, p_CM20, p_CM1, p_CM21);

    // conv via materialized im2col + dense split-K GEMM (wave-tuned SPLITK)
    for (int n = 0; n < 2; n++) {
        int k = Kk[n], ne2 = 2*NE[n];
        int Nn = NB*ne2;
        if (n == 0) im2col_conv_k<12,86><<<NC*12, 256>>>(p_res, p_im, 6);
        else        im2col_conv_k<24,44><<<NC*24, 256>>>(p_res + (size_t)NB*NC*NL, p_im, 12);
        GemmP p{};
        p.A = cw[n]; p.lda = NC*k;
        p.Bp = p_im; p.ldb = Nn; p.sBb = 0;
        p.part = p_part;
        p.bias = cb[n];
        p.M = NC; p.N = Nn; p.K = NC*k; p.npos = ne2;
        if (n == 0) launch_gemm<128,0,1,1,1,1,0,10>(p);   // 880 CTAs ~ 2.97 waves
        else        launch_gemm<128,0,1,1,1,1,0,20>(p);   // 880 CTAs
        reduce_ep_k<<<(NC*Nn + 255)/256, 256>>>(p_part, p_cv + (size_t)n*NB*NC*86, cb[n],
                                                (n == 0) ? 10 : 20, NC, Nn,
                                                (long long)NC*ne2, ne2, ne2);
    }

    for (int n = 0; n < 2; n++) {
        int k = Kk[n], m = MM[n], N2 = N2_[n], mk = MKl[n];
        int ne2 = 2*NE[n];

        x1_kernel<<<1024, 256>>>(p_cv + (size_t)n*NB*NC*86, p_x1, m, ne2);
        { // real-DFT (ragged K -> BN=64 guarded path)
            GemmP p{};
            p.A = p_x1; p.lda = m;
            p.Bp = CMv[n]; p.ldb = N2; p.sBb = 0;
            p.D = p_xf; p.sDb = 0; p.ldd = N2;
            p.M = NB*NC; p.N = N2; p.K = m; p.npos = N2;
            launch_gemm<64,0,1,0,0,0,0>(p);
        }
        { // isometric conv (valid), tanh — split-K (wave-tuned)
            GemmP p{};
            p.A = iw[n]; p.lda = NC*m;
            p.Bp = p_xf; p.sBb = (long long)NC*N2; p.inner = N2;
            p.part = p_part;
            p.bias = ib[n];
            p.M = NC; p.N = NB*m; p.K = NC*m; p.npos = m;
            if (n == 0) launch_gemm<128,2,85,1,1,1,0,10>(p);  // 880 CTAs
            else        launch_gemm<128,2,43,1,1,1,0,20>(p);  // 880 CTAs
            reduce_ep_k<<<(NC*NB*m + 255)/256, 256>>>(p_part, p_xi, ib[n],
                                                      (n == 0) ? 10 : 20, NC, NB*m,
                                                      (long long)NC*m, m, m);
        }
        { // real-IDFT (ragged K)
            GemmP p{};
            p.A = p_xi; p.lda = m;
            p.Bp = CM2v[n]; p.ldb = m; p.sBb = 0;
            p.D = p_xr; p.sDb = 0; p.ldd = m;
            p.M = NB*NC; p.N = m; p.K = m; p.npos = m;
            launch_gemm<64,0,1,0,0,0,0>(p);
        }
        ln1_kernel<<<NB*m, 256>>>(p_xr, p_x1, ng, nb, p_yln, m);
        { // conv-transpose, tanh, scatter store
            GemmP p{};
            p.A = W2v[n]; p.lda = NC;
            p.Bp = p_yln; p.ldb = m; p.sBb = (long long)NC*m;
            p.D = p_y2; p.sDb = (long long)NC*mk; p.kt = k; p.mklen = mk;
            p.bias = tb[n];
            p.M = NC*k; p.N = NB*m; p.K = NC; p.npos = m;
            launch_gemm<128,0,1,1,3,1,1>(p);
        }
        branch_out_kernel<<<NB*NL, 256>>>(p_y2, p_res + (size_t)n*NB*NC*NL, ng, nb, p_br, mk, n);
    }
    { // merge
        GemmP p{};
        p.A = p_br; p.lda = 2*NC;
        p.Bp = p_Wm; p.ldb = NC; p.sBb = 0;
        p.D = p_mg; p.sDb = 0; p.ldd = NC;
        p.bias = mb;
        p.M = NB*NL; p.N = NC; p.K = 2*NC; p.npos = NC;
        launch_gemm<128,0,1,1,2,0,0>(p);
    }
    { // FFN layer 1 (relu)
        GemmP p{};
        p.A = p_mg; p.lda = NC;
        p.Bp = fw1; p.ldb = 4*NC; p.sBb = 0;
        p.D = p_h1; p.sDb = 0; p.ldd = 4*NC;
        p.bias = fb1;
        p.M = NB*NL; p.N = 4*NC; p.K = NC; p.npos = 4*NC;
        launch_gemm<128,0,1,1,2,2,0>(p);
    }
    { // FFN layer 2
        GemmP p{};
        p.A = p_h1; p.lda = 4*NC;
        p.Bp = fw2; p.ldb = NC; p.sBb = 0;
        p.D = p_h2; p.sDb = 0; p.ldd = NC;
        p.bias = fb2;
        p.M = NB*NL; p.N = NC; p.K = 4*NC; p.npos = NC;
        launch_gemm<128,0,1,1,2,0,0>(p);
    }
    final_ln_kernel<<<NB*NL, 256>>>(p_mg, p_h2, fng, fnb, out);
}